// round 2
// baseline (speedup 1.0000x reference)
#include <cuda_runtime.h>
#include <math.h>

#define Bq 2048
#define Mq 64
#define Dq 64
#define BMq (Bq*Mq)
#define NPB (3*Bq*Dq)
#define ROWS 6144

// ---------------- device scratch (no allocations allowed) ----------------
__device__ float g_embs[4*3*Bq*Dq];   // 4 builds x 3 layers x B x D
__device__ float g_norm[4*3*Bq*Dq];   // l2-normalized copies
__device__ float g_rowsum[2*ROWS];
__device__ float g_colsum[2*ROWS];

__device__ __forceinline__ float wsum(float v){
#pragma unroll
    for (int o = 16; o; o >>= 1) v += __shfl_xor_sync(0xffffffffu, v, o);
    return v;
}
__device__ __forceinline__ float wmax(float v){
#pragma unroll
    for (int o = 16; o; o >>= 1) v = fmaxf(v, __shfl_xor_sync(0xffffffffu, v, o));
    return v;
}
__device__ __forceinline__ int eidx(int bl, int l, int b, int j){
    return (((bl*3 + l)*Bq) + b)*Dq + j;
}
__device__ __forceinline__ float artanh_clip(float x){
    x = fminf(fmaxf(x, -1.f + 1e-5f), 1.f - 1e-5f);
    return atanhf(x);
}

// ---------------- zero accumulators ----------------
__global__ void zero_kernel(){
    int i = blockIdx.x*1024 + threadIdx.x;
    if (i < 2*ROWS){ g_rowsum[i] = 0.f; g_colsum[i] = 0.f; }
}

// ---------------- init embeddings (layer 0 of each stack) ----------------
__global__ void init_kernel(const float* __restrict__ E, const int* __restrict__ items,
                            const int* __restrict__ ucf_h, const int* __restrict__ ukg_h,
                            const int* __restrict__ icf_h){
    int b = blockIdx.x, j = threadIdx.x;   // 64 threads
    g_embs[eidx(1,0,b,j)] = E[items[b]*Dq + j];
    float s0 = 0.f, s2 = 0.f, s3 = 0.f;
#pragma unroll 4
    for (int m = 0; m < Mq; ++m){
        s0 += E[ucf_h[b*Mq + m]*Dq + j];
        s2 += E[ukg_h[b*Mq + m]*Dq + j];
        s3 += E[icf_h[b*Mq + m]*Dq + j];
    }
    const float inv = 1.f/64.f;
    g_embs[eidx(0,0,b,j)] = s0*inv;
    g_embs[eidx(2,0,b,j)] = s2*inv;
    g_embs[eidx(3,0,b,j)] = s3*inv;
}

// ---------------- euclidean attention aggregation ----------------
// grid (B, 2 layers), block 256.  smem floats: xs 64*130, ts 64*64, w1s 128*64, zs 64*64, av 64, wv 64
#define ED_SMEM_FLOATS (64*130 + 64*64 + 128*64 + 64*64 + 64 + 64)
__global__ __launch_bounds__(256) void ed_kernel(
    const float* __restrict__ E, const float* __restrict__ R,
    const int* __restrict__ hI, const int* __restrict__ rI, const int* __restrict__ tI,
    const float* __restrict__ W1, const float* __restrict__ W2, int build)
{
    extern __shared__ float sm[];
    float* xs  = sm;                    // [64][130]  (h | path)
    float* ts  = xs + 64*130;           // [64][64]
    float* w1s = ts + 64*64;            // [128][64]
    float* zs  = w1s + 128*64;          // [64][64]
    float* av  = zs + 64*64;            // [64]
    float* wv  = av + 64;               // [64]

    const int b = blockIdx.x, layer = blockIdx.y;
    const int tid = threadIdx.x, lane = tid & 31, wid = tid >> 5;

    // gather h, path, t
    for (int e = tid; e < 64*64; e += 256){
        int m = e >> 6, k = e & 63;
        int h0 = hI[b*Mq + m];
        float hv = E[h0*Dq + k];
        int r0 = rI[b*Mq + m];
        float pv = R[r0*Dq + k];
        if (layer){
            hv += E[hI[BMq + b*Mq + m]*Dq + k];
            pv *= R[rI[BMq + b*Mq + m]*Dq + k];
        }
        xs[m*130 + k]      = hv;
        xs[m*130 + 64 + k] = pv;
        ts[m*64 + k] = E[tI[layer*BMq + b*Mq + m]*Dq + k];
    }
    for (int e = tid; e < 128*64; e += 256) w1s[e] = W1[e];
    __syncthreads();

    // z = relu(x @ W1): 4x4 register tile per thread
    const int ty = tid >> 4, tx = tid & 15;
    float acc[4][4] = {};
#pragma unroll 4
    for (int k = 0; k < 128; ++k){
        float a0 = xs[(ty*4+0)*130 + k];
        float a1 = xs[(ty*4+1)*130 + k];
        float a2 = xs[(ty*4+2)*130 + k];
        float a3 = xs[(ty*4+3)*130 + k];
        float4 bv = *(const float4*)&w1s[k*64 + tx*4];
        acc[0][0] += a0*bv.x; acc[0][1] += a0*bv.y; acc[0][2] += a0*bv.z; acc[0][3] += a0*bv.w;
        acc[1][0] += a1*bv.x; acc[1][1] += a1*bv.y; acc[1][2] += a1*bv.z; acc[1][3] += a1*bv.w;
        acc[2][0] += a2*bv.x; acc[2][1] += a2*bv.y; acc[2][2] += a2*bv.z; acc[2][3] += a2*bv.w;
        acc[3][0] += a3*bv.x; acc[3][1] += a3*bv.y; acc[3][2] += a3*bv.z; acc[3][3] += a3*bv.w;
    }
#pragma unroll
    for (int ii = 0; ii < 4; ++ii){
        float4 z4;
        z4.x = fmaxf(acc[ii][0], 0.f); z4.y = fmaxf(acc[ii][1], 0.f);
        z4.z = fmaxf(acc[ii][2], 0.f); z4.w = fmaxf(acc[ii][3], 0.f);
        *(float4*)&zs[(ty*4+ii)*64 + tx*4] = z4;
    }
    __syncthreads();

    // a[m] = sigmoid(z[m] . W2)
    const float w2a = W2[lane], w2b = W2[lane+32];
    for (int r = 0; r < 8; ++r){
        int m = wid*8 + r;
        float v = zs[m*64 + lane]*w2a + zs[m*64 + lane + 32]*w2b;
        v = wsum(v);
        if (lane == 0) av[m] = 1.f/(1.f + expf(-v));
    }
    __syncthreads();

    // softmax over m (warp 0)
    if (wid == 0){
        float a0 = av[lane], a1 = av[lane+32];
        float mx = wmax(fmaxf(a0, a1));
        float e0 = expf(a0 - mx), e1 = expf(a1 - mx);
        float s = wsum(e0 + e1);
        wv[lane] = e0/s; wv[lane+32] = e1/s;
    }
    __syncthreads();

    // out[j] = sum_m w[m]*t[m][j]
    if (tid < 64){
        float o = 0.f;
#pragma unroll 4
        for (int m = 0; m < Mq; ++m) o += wv[m]*ts[m*64 + tid];
        g_embs[eidx(build, layer+1, b, tid)] = o;
    }
}

// ---------------- hyperbolic attention aggregation ----------------
#define HY_SMEM_FLOATS (64*64 + 64*64 + 64*130 + 128*64 + 64*64 + 64 + 64 + 64 + 16 + 8*64)
__global__ __launch_bounds__(256) void hyper_kernel(
    const float* __restrict__ E, const float* __restrict__ R,
    const int* __restrict__ hI, const int* __restrict__ rI, const int* __restrict__ tI,
    const float* __restrict__ W1, const float* __restrict__ B1,
    const float* __restrict__ W2, const float* __restrict__ B2,
    const float* __restrict__ curv, int build)
{
    extern __shared__ float sm[];
    float* hhs  = sm;                   // [64][64]
    float* hts  = hhs + 64*64;          // [64][64]
    float* tang = hts + 64*64;          // [64][130]
    float* w1s  = tang + 64*130;        // [128][64]
    float* zs   = w1s + 128*64;         // [64][64]
    float* av   = zs + 64*64;
    float* wv   = av + 64;
    float* mp   = wv + 64;
    float* scal = mp + 64;              // [16]
    float* parts= scal + 16;            // [8][64]

    const int b = blockIdx.x, layer = blockIdx.y;
    const int tid = threadIdx.x, lane = tid & 31, wid = tid >> 5;
    const float absc = fabsf(curv[0]);

    // per-row hyperbolic pipeline; warp handles 8 rows, lane owns dims (lane, lane+32)
    for (int r = 0; r < 8; ++r){
        int m = wid*8 + r;
        int h0 = hI[b*Mq + m];
        float hv0 = E[h0*Dq + lane], hv1 = E[h0*Dq + lane + 32];
        int r0 = rI[b*Mq + m];
        float pv0 = R[r0*Dq + lane], pv1 = R[r0*Dq + lane + 32];
        if (layer){
            int h1 = hI[BMq + b*Mq + m];
            hv0 += E[h1*Dq + lane]; hv1 += E[h1*Dq + lane + 32];
            int r1 = rI[BMq + b*Mq + m];
            pv0 *= R[r1*Dq + lane]; pv1 *= R[r1*Dq + lane + 32];
        }
        int t0 = tI[layer*BMq + b*Mq + m];
        float tv0 = E[t0*Dq + lane], tv1 = E[t0*Dq + lane + 32];

        // l2 normalize (x / max(||x||, 1e-12))
        float nh = sqrtf(wsum(hv0*hv0 + hv1*hv1)); float ih = 1.f/fmaxf(nh, 1e-12f); hv0 *= ih; hv1 *= ih;
        float np = sqrtf(wsum(pv0*pv0 + pv1*pv1)); float ip = 1.f/fmaxf(np, 1e-12f); pv0 *= ip; pv1 *= ip;
        float nt = sqrtf(wsum(tv0*tv0 + tv1*tv1)); float it = 1.f/fmaxf(nt, 1e-12f); tv0 *= it; tv1 *= it;

        // hh = expmap0(h)*|c|
        float n1 = sqrtf(fmaxf(wsum(hv0*hv0 + hv1*hv1), 1e-15f));
        float s1 = tanhf(n1)/n1*absc;
        float hh0 = s1*hv0, hh1 = s1*hv1;
        float hh2 = wsum(hh0*hh0 + hh1*hh1);
        float lam = 2.f/fmaxf(1.f - hh2, 1e-15f);

        // ht = expmap(t, hh)
        float ntn = sqrtf(fmaxf(wsum(tv0*tv0 + tv1*tv1), 1e-15f));
        float st  = tanhf(lam*ntn*0.5f)/ntn;
        float y0 = st*tv0, y1 = st*tv1;
        float y2 = wsum(y0*y0 + y1*y1);
        float xy = wsum(hh0*y0 + hh1*y1);
        float c1 = 1.f + 2.f*xy + y2, c2 = 1.f - hh2;
        float den = fmaxf(1.f + 2.f*xy + hh2*y2, 1e-15f);
        float ht0 = (c1*hh0 + c2*y0)/den, ht1 = (c1*hh1 + c2*y1)/den;

        // hr = expmap(path, hh)
        float npn = sqrtf(fmaxf(wsum(pv0*pv0 + pv1*pv1), 1e-15f));
        float sp  = tanhf(lam*npn*0.5f)/npn;
        float q0 = sp*pv0, q1 = sp*pv1;
        float q2 = wsum(q0*q0 + q1*q1);
        float xq = wsum(hh0*q0 + hh1*q1);
        float d1 = 1.f + 2.f*xq + q2, d2 = 1.f - hh2;
        float dd = fmaxf(1.f + 2.f*xq + hh2*q2, 1e-15f);
        float hr0 = (d1*hh0 + d2*q0)/dd, hr1 = (d1*hh1 + d2*q1)/dd;

        // tang = logmap0([hh, hr])  (128-dim norm)
        float hr2 = wsum(hr0*hr0 + hr1*hr1);
        float n128 = sqrtf(fmaxf(hh2 + hr2, 1e-15f));
        float stg = artanh_clip(n128)/n128;

        hhs[m*64 + lane] = hh0; hhs[m*64 + lane + 32] = hh1;
        hts[m*64 + lane] = ht0; hts[m*64 + lane + 32] = ht1;
        tang[m*130 + lane]        = stg*hh0; tang[m*130 + lane + 32]      = stg*hh1;
        tang[m*130 + 64 + lane]   = stg*hr0; tang[m*130 + 64 + lane + 32] = stg*hr1;
    }
    for (int e = tid; e < 128*64; e += 256) w1s[e] = W1[e];
    __syncthreads();

    // z = relu(tang @ W1 + b1)
    const int ty = tid >> 4, tx = tid & 15;
    float acc[4][4] = {};
#pragma unroll 4
    for (int k = 0; k < 128; ++k){
        float a0 = tang[(ty*4+0)*130 + k];
        float a1 = tang[(ty*4+1)*130 + k];
        float a2 = tang[(ty*4+2)*130 + k];
        float a3 = tang[(ty*4+3)*130 + k];
        float4 bv = *(const float4*)&w1s[k*64 + tx*4];
        acc[0][0] += a0*bv.x; acc[0][1] += a0*bv.y; acc[0][2] += a0*bv.z; acc[0][3] += a0*bv.w;
        acc[1][0] += a1*bv.x; acc[1][1] += a1*bv.y; acc[1][2] += a1*bv.z; acc[1][3] += a1*bv.w;
        acc[2][0] += a2*bv.x; acc[2][1] += a2*bv.y; acc[2][2] += a2*bv.z; acc[2][3] += a2*bv.w;
        acc[3][0] += a3*bv.x; acc[3][1] += a3*bv.y; acc[3][2] += a3*bv.z; acc[3][3] += a3*bv.w;
    }
    float4 b1v = *(const float4*)&B1[tx*4];
#pragma unroll
    for (int ii = 0; ii < 4; ++ii){
        float4 z4;
        z4.x = fmaxf(acc[ii][0] + b1v.x, 0.f); z4.y = fmaxf(acc[ii][1] + b1v.y, 0.f);
        z4.z = fmaxf(acc[ii][2] + b1v.z, 0.f); z4.w = fmaxf(acc[ii][3] + b1v.w, 0.f);
        *(float4*)&zs[(ty*4+ii)*64 + tx*4] = z4;
    }
    __syncthreads();

    // a[m] = tanh(z[m].W2 + b2)
    const float w2a = W2[lane], w2b = W2[lane+32];
    const float b2 = B2[0];
    for (int r = 0; r < 8; ++r){
        int m = wid*8 + r;
        float v = zs[m*64 + lane]*w2a + zs[m*64 + lane + 32]*w2b;
        v = wsum(v);
        if (lane == 0) av[m] = tanhf(v + b2);
    }
    __syncthreads();

    if (wid == 0){
        float a0 = av[lane], a1 = av[lane+32];
        float mx = wmax(fmaxf(a0, a1));
        float e0 = expf(a0 - mx), e1 = expf(a1 - mx);
        float s = wsum(e0 + e1);
        wv[lane] = e0/s; wv[lane+32] = e1/s;
    }
    __syncthreads();

    // mean_pt = sum_m w[m]*hh[m]
    if (tid < 64){
        float a = 0.f;
#pragma unroll 4
        for (int m = 0; m < Mq; ++m) a += wv[m]*hhs[m*64 + tid];
        mp[tid] = a;
    }
    __syncthreads();
    if (wid == 0){
        float v = mp[lane]*mp[lane] + mp[lane+32]*mp[lane+32];
        v = wsum(v);
        if (lane == 0) scal[0] = v;
    }
    __syncthreads();

    // e = logmap(w*ht, mean_pt);  out = sum_m w*e
    const float p2 = scal[0];
    const float mp0 = mp[lane], mp1 = mp[lane+32];
    const float lamp = 2.f/fmaxf(1.f - p2, 1e-15f);
    float o0 = 0.f, o1 = 0.f;
    for (int r = 0; r < 8; ++r){
        int m = wid*8 + r;
        float wm = wv[m];
        float g0 = wm*hts[m*64 + lane], g1 = wm*hts[m*64 + lane + 32];
        float y2 = wsum(g0*g0 + g1*g1);
        float xy = wsum(-(mp0*g0 + mp1*g1));
        float c1 = 1.f + 2.f*xy + y2, c2 = 1.f - p2;
        float den = fmaxf(1.f + 2.f*xy + p2*y2, 1e-15f);
        float mm0 = (c1*(-mp0) + c2*g0)/den, mm1 = (c1*(-mp1) + c2*g1)/den;
        float n = sqrtf(fmaxf(wsum(mm0*mm0 + mm1*mm1), 1e-15f));
        float sc = (2.f/lamp)*artanh_clip(n)/n;
        o0 += wm*sc*mm0; o1 += wm*sc*mm1;
    }
    parts[wid*64 + lane] = o0; parts[wid*64 + lane + 32] = o1;
    __syncthreads();
    if (tid < 64){
        float s = 0.f;
#pragma unroll
        for (int w = 0; w < 8; ++w) s += parts[w*64 + tid];
        g_embs[eidx(build, layer+1, b, tid)] = s;
    }
}

// ---------------- l2-normalize all stacks ----------------
__global__ void normalize_kernel(){
    int row = blockIdx.x*8 + (threadIdx.x >> 5);
    int lane = threadIdx.x & 31;
    if (row >= 4*3*Bq) return;
    const float* s = g_embs + row*Dq;
    float* d = g_norm + row*Dq;
    float v0 = s[lane], v1 = s[lane+32];
    float n = sqrtf(wsum(v0*v0 + v1*v1));
    float inv = 1.f/fmaxf(n, 1e-12f);
    d[lane] = v0*inv; d[lane+32] = v1*inv;
}

// ---------------- MLCL GEMM with fused exp row/col sums ----------------
__global__ __launch_bounds__(256) void mlcl_gemm(int pair){
    const float* A  = g_norm + (pair == 0 ? 0 : 1)*NPB;
    const float* Bn = g_norm + (pair == 0 ? 2 : 3)*NPB;
    float* rs = g_rowsum + pair*ROWS;
    float* cs = g_colsum + pair*ROWS;

    __shared__ float As[64*65];
    __shared__ float Bs[64*65];
    __shared__ float colpart[64];

    const int tid = threadIdx.x;
    const int by = blockIdx.y, bx = blockIdx.x;
    for (int e = tid; e < 4096; e += 256){
        int i = e >> 6, k = e & 63;
        As[i*65 + k] = A [(by*64 + i)*64 + k];
        Bs[i*65 + k] = Bn[(bx*64 + i)*64 + k];
    }
    if (tid < 64) colpart[tid] = 0.f;
    __syncthreads();

    const int ty = tid >> 4, tx = tid & 15;
    float acc[4][4] = {};
#pragma unroll 8
    for (int k = 0; k < 64; ++k){
        float a0 = As[(ty*4+0)*65 + k];
        float a1 = As[(ty*4+1)*65 + k];
        float a2 = As[(ty*4+2)*65 + k];
        float a3 = As[(ty*4+3)*65 + k];
        float b0 = Bs[(tx*4+0)*65 + k];
        float b1 = Bs[(tx*4+1)*65 + k];
        float b2 = Bs[(tx*4+2)*65 + k];
        float b3 = Bs[(tx*4+3)*65 + k];
        acc[0][0]+=a0*b0; acc[0][1]+=a0*b1; acc[0][2]+=a0*b2; acc[0][3]+=a0*b3;
        acc[1][0]+=a1*b0; acc[1][1]+=a1*b1; acc[1][2]+=a1*b2; acc[1][3]+=a1*b3;
        acc[2][0]+=a2*b0; acc[2][1]+=a2*b1; acc[2][2]+=a2*b2; acc[2][3]+=a2*b3;
        acc[3][0]+=a3*b0; acc[3][1]+=a3*b1; acc[3][2]+=a3*b2; acc[3][3]+=a3*b3;
    }
    float cp[4] = {0.f,0.f,0.f,0.f};
    float rp[4];
#pragma unroll
    for (int ii = 0; ii < 4; ++ii){
        float r = 0.f;
#pragma unroll
        for (int jj = 0; jj < 4; ++jj){
            float e = __expf(acc[ii][jj]*5.0f);   // 1/TEMP = 5
            r += e; cp[jj] += e;
        }
        rp[ii] = r;
    }
#pragma unroll
    for (int off = 1; off < 16; off <<= 1){
#pragma unroll
        for (int ii = 0; ii < 4; ++ii) rp[ii] += __shfl_xor_sync(0xffffffffu, rp[ii], off);
    }
    if (tx == 0){
#pragma unroll
        for (int ii = 0; ii < 4; ++ii) atomicAdd(&rs[by*64 + ty*4 + ii], rp[ii]);
    }
#pragma unroll
    for (int jj = 0; jj < 4; ++jj) atomicAdd(&colpart[tx*4 + jj], cp[jj]);
    __syncthreads();
    if (tid < 64) atomicAdd(&cs[bx*64 + tid], colpart[tid]);
}

// ---------------- loss reduction ----------------
__global__ void loss_kernel(float* out, int out_size){
    const int tid = threadIdx.x;
    float acc = 0.f;
    for (int p = 0; p < 2; ++p){
        const float* A  = g_norm + (p == 0 ? 0 : 1)*NPB;
        const float* Bn = g_norm + (p == 0 ? 2 : 3)*NPB;
        const float* rs = g_rowsum + p*ROWS;
        const float* cs = g_colsum + p*ROWS;
        for (int i = tid; i < ROWS; i += 256){
            float d = 0.f;
#pragma unroll 8
            for (int k = 0; k < 64; ++k) d += A[i*64 + k]*Bn[i*64 + k];
            acc += logf(rs[i]) + logf(cs[i]) - 10.f*d;   // 2*pos/TEMP = 10*dot
        }
    }
    __shared__ float red[8];
    acc = wsum(acc);
    if ((tid & 31) == 0) red[tid >> 5] = acc;
    __syncthreads();
    if (tid == 0){
        float t = 0.f;
#pragma unroll
        for (int i = 0; i < 8; ++i) t += red[i];
        if (out_size > Bq) out[Bq] = 1e-6f*t;   // KGE_W
    }
}

// ---------------- scores ----------------
__global__ void scores_kernel(float* out){
    int b = blockIdx.x*8 + (threadIdx.x >> 5);
    int lane = threadIdx.x & 31;
    if (b >= Bq) return;
    float s = 0.f;
#pragma unroll
    for (int l = 0; l < 3; ++l){
        s += g_embs[eidx(0,l,b,lane)]   *g_embs[eidx(3,l,b,lane)]
           + g_embs[eidx(0,l,b,lane+32)]*g_embs[eidx(3,l,b,lane+32)]
           + g_embs[eidx(2,l,b,lane)]   *g_embs[eidx(1,l,b,lane)]
           + g_embs[eidx(2,l,b,lane+32)]*g_embs[eidx(1,l,b,lane+32)];
    }
    s = wsum(s);
    if (lane == 0) out[b] = 1.f/(1.f + expf(-s));
}

// ---------------- launch ----------------
extern "C" void kernel_launch(void* const* d_in, const int* in_sizes, int n_in,
                              void* d_out, int out_size){
    (void)in_sizes; (void)n_in;
    const int*   items  = (const int*)  d_in[0];
    const int*   ucf_h  = (const int*)  d_in[1];
    const int*   ucf_r  = (const int*)  d_in[2];
    const int*   ucf_t  = (const int*)  d_in[3];
    const int*   ikg_h  = (const int*)  d_in[4];
    const int*   ikg_r  = (const int*)  d_in[5];
    const int*   ikg_t  = (const int*)  d_in[6];
    const int*   ukg_h  = (const int*)  d_in[7];
    const int*   ukg_r  = (const int*)  d_in[8];
    const int*   ukg_t  = (const int*)  d_in[9];
    const int*   icf_h  = (const int*)  d_in[10];
    const int*   icf_r  = (const int*)  d_in[11];
    const int*   icf_t  = (const int*)  d_in[12];
    const float* E      = (const float*)d_in[13];
    const float* R      = (const float*)d_in[14];
    const float* att_w1 = (const float*)d_in[15];
    const float* att_w2 = (const float*)d_in[16];
    const float* a2_w1  = (const float*)d_in[17];
    const float* a2_b1  = (const float*)d_in[18];
    const float* a2_w2  = (const float*)d_in[19];
    const float* a2_b2  = (const float*)d_in[20];
    const float* curv   = (const float*)d_in[21];
    float* out = (float*)d_out;

    const int ed_smem = ED_SMEM_FLOATS*4;
    const int hy_smem = HY_SMEM_FLOATS*4;
    cudaFuncSetAttribute(ed_kernel,    cudaFuncAttributeMaxDynamicSharedMemorySize, ed_smem);
    cudaFuncSetAttribute(hyper_kernel, cudaFuncAttributeMaxDynamicSharedMemorySize, hy_smem);

    zero_kernel<<<(2*ROWS + 1023)/1024, 1024>>>();
    init_kernel<<<Bq, 64>>>(E, items, ucf_h, ukg_h, icf_h);

    dim3 gb(Bq, 2);
    ed_kernel<<<gb, 256, ed_smem>>>(E, R, ucf_h, ucf_r, ucf_t, att_w1, att_w2, 0);
    ed_kernel<<<gb, 256, ed_smem>>>(E, R, ikg_h, ikg_r, ikg_t, att_w1, att_w2, 1);
    hyper_kernel<<<gb, 256, hy_smem>>>(E, R, ukg_h, ukg_r, ukg_t, a2_w1, a2_b1, a2_w2, a2_b2, curv, 2);
    hyper_kernel<<<gb, 256, hy_smem>>>(E, R, icf_h, icf_r, icf_t, a2_w1, a2_b1, a2_w2, a2_b2, curv, 3);

    normalize_kernel<<<(4*3*Bq)/8, 256>>>();
    dim3 gg(96, 96);
    mlcl_gemm<<<gg, 256>>>(0);
    mlcl_gemm<<<gg, 256>>>(1);
    loss_kernel<<<1, 256>>>(out, out_size);
    scores_kernel<<<Bq/8, 256>>>(out);
}

// round 3
// speedup vs baseline: 2.1341x; 2.1341x over previous
#include <cuda_runtime.h>
#include <math.h>

#define Bq 2048
#define Mq 64
#define Dq 64
#define BMq (Bq*Mq)
#define NPB (3*Bq*Dq)
#define ROWS 6144

// ---------------- device scratch (no allocations allowed) ----------------
__device__ float g_embs[4*3*Bq*Dq];   // 4 builds x 3 layers x B x D
__device__ float g_norm[4*3*Bq*Dq];   // l2-normalized copies
__device__ float g_rowsum[2*ROWS];
__device__ float g_colsum[2*ROWS];
__device__ float g_loss;

__device__ __forceinline__ float wsum(float v){
#pragma unroll
    for (int o = 16; o; o >>= 1) v += __shfl_xor_sync(0xffffffffu, v, o);
    return v;
}
__device__ __forceinline__ float hsum16(float v){
#pragma unroll
    for (int o = 8; o; o >>= 1) v += __shfl_xor_sync(0xffffffffu, v, o);
    return v;
}
__device__ __forceinline__ float wmax(float v){
#pragma unroll
    for (int o = 16; o; o >>= 1) v = fmaxf(v, __shfl_xor_sync(0xffffffffu, v, o));
    return v;
}
__device__ __forceinline__ int eidx(int bl, int l, int b, int j){
    return (((bl*3 + l)*Bq) + b)*Dq + j;
}
__device__ __forceinline__ float artanh_clip(float x){
    x = fminf(fmaxf(x, -1.f + 1e-5f), 1.f - 1e-5f);
    return atanhf(x);
}

// ---------------- zero accumulators ----------------
__global__ void zero_kernel(){
    int i = blockIdx.x*1024 + threadIdx.x;
    if (i < 2*ROWS){ g_rowsum[i] = 0.f; g_colsum[i] = 0.f; }
    if (i == 0) g_loss = 0.f;
}

// ---------------- init embeddings (layer 0 of each stack) ----------------
__global__ void init_kernel(const float* __restrict__ E, const int* __restrict__ items,
                            const int* __restrict__ ucf_h, const int* __restrict__ ukg_h,
                            const int* __restrict__ icf_h){
    int b = blockIdx.x, j = threadIdx.x;   // 64 threads
    g_embs[eidx(1,0,b,j)] = E[items[b]*Dq + j];
    float s0 = 0.f, s2 = 0.f, s3 = 0.f;
#pragma unroll 4
    for (int m = 0; m < Mq; ++m){
        s0 += E[ucf_h[b*Mq + m]*Dq + j];
        s2 += E[ukg_h[b*Mq + m]*Dq + j];
        s3 += E[icf_h[b*Mq + m]*Dq + j];
    }
    const float inv = 1.f/64.f;
    g_embs[eidx(0,0,b,j)] = s0*inv;
    g_embs[eidx(2,0,b,j)] = s2*inv;
    g_embs[eidx(3,0,b,j)] = s3*inv;
}

// ---------------- euclidean attention aggregation ----------------
// smem: xs 64*130, ts 64*64, av 64, wv 64  (= 50KB -> 4 CTAs/SM)
#define ED_SMEM_FLOATS (64*130 + 64*64 + 64 + 64)
__global__ __launch_bounds__(256) void ed_kernel(
    const float* __restrict__ E, const float* __restrict__ R,
    const int* __restrict__ hI, const int* __restrict__ rI, const int* __restrict__ tI,
    const float* __restrict__ W1, const float* __restrict__ W2, int build)
{
    extern __shared__ float sm[];
    float* xs  = sm;                    // [64][130]  (h | path)
    float* ts  = xs + 64*130;           // [64][64]
    float* av  = ts + 64*64;            // [64]
    float* wv  = av + 64;               // [64]

    const int b = blockIdx.x, layer = blockIdx.y;
    const int tid = threadIdx.x, lane = tid & 31, wid = tid >> 5;

    // gather h, path, t
    for (int e = tid; e < 64*64; e += 256){
        int m = e >> 6, k = e & 63;
        float hv = E[hI[b*Mq + m]*Dq + k];
        float pv = R[rI[b*Mq + m]*Dq + k];
        if (layer){
            hv += E[hI[BMq + b*Mq + m]*Dq + k];
            pv *= R[rI[BMq + b*Mq + m]*Dq + k];
        }
        xs[m*130 + k]      = hv;
        xs[m*130 + 64 + k] = pv;
        ts[m*64 + k] = E[tI[layer*BMq + b*Mq + m]*Dq + k];
    }
    __syncthreads();

    // z = relu(x @ W1), fused with W2 dot. W1 read via L1 (float4, broadcast).
    const int ty = tid >> 4, tx = tid & 15;
    const float4* W1v = (const float4*)W1;   // index k*16 + tx -> W1[k][tx*4..+3]
    float acc[4][4] = {};
#pragma unroll 4
    for (int k = 0; k < 128; ++k){
        float a0 = xs[(ty*4+0)*130 + k];
        float a1 = xs[(ty*4+1)*130 + k];
        float a2 = xs[(ty*4+2)*130 + k];
        float a3 = xs[(ty*4+3)*130 + k];
        float4 bv = __ldg(&W1v[k*16 + tx]);
        acc[0][0] += a0*bv.x; acc[0][1] += a0*bv.y; acc[0][2] += a0*bv.z; acc[0][3] += a0*bv.w;
        acc[1][0] += a1*bv.x; acc[1][1] += a1*bv.y; acc[1][2] += a1*bv.z; acc[1][3] += a1*bv.w;
        acc[2][0] += a2*bv.x; acc[2][1] += a2*bv.y; acc[2][2] += a2*bv.z; acc[2][3] += a2*bv.w;
        acc[3][0] += a3*bv.x; acc[3][1] += a3*bv.y; acc[3][2] += a3*bv.z; acc[3][3] += a3*bv.w;
    }
    float4 w2v = __ldg((const float4*)W2 + tx);
#pragma unroll
    for (int ii = 0; ii < 4; ++ii){
        float v = fmaxf(acc[ii][0],0.f)*w2v.x + fmaxf(acc[ii][1],0.f)*w2v.y
                + fmaxf(acc[ii][2],0.f)*w2v.z + fmaxf(acc[ii][3],0.f)*w2v.w;
        v = hsum16(v);
        if (tx == 0) av[ty*4 + ii] = 1.f/(1.f + expf(-v));
    }
    __syncthreads();

    // softmax over m (warp 0)
    if (wid == 0){
        float a0 = av[lane], a1 = av[lane+32];
        float mx = wmax(fmaxf(a0, a1));
        float e0 = expf(a0 - mx), e1 = expf(a1 - mx);
        float s = wsum(e0 + e1);
        wv[lane] = e0/s; wv[lane+32] = e1/s;
    }
    __syncthreads();

    // out[j] = sum_m w[m]*t[m][j]
    if (tid < 64){
        float o = 0.f;
#pragma unroll 4
        for (int m = 0; m < Mq; ++m) o += wv[m]*ts[m*64 + tid];
        g_embs[eidx(build, layer+1, b, tid)] = o;
    }
}

// ---------------- hyperbolic attention aggregation ----------------
// smem: hhs 64*64, hts 64*64, tang 64*130, av/wv/mp 64*3, scal 16, parts 512 (= 69KB -> 3 CTAs/SM)
#define HY_SMEM_FLOATS (64*64 + 64*64 + 64*130 + 64 + 64 + 64 + 16 + 8*64)
__global__ __launch_bounds__(256) void hyper_kernel(
    const float* __restrict__ E, const float* __restrict__ R,
    const int* __restrict__ hI, const int* __restrict__ rI, const int* __restrict__ tI,
    const float* __restrict__ W1, const float* __restrict__ B1,
    const float* __restrict__ W2, const float* __restrict__ B2,
    const float* __restrict__ curv, int build)
{
    extern __shared__ float sm[];
    float* hhs  = sm;                   // [64][64]
    float* hts  = hhs + 64*64;          // [64][64]
    float* tang = hts + 64*64;          // [64][130]
    float* av   = tang + 64*130;
    float* wv   = av + 64;
    float* mp   = wv + 64;
    float* scal = mp + 64;              // [16]
    float* parts= scal + 16;            // [8][64]

    const int b = blockIdx.x, layer = blockIdx.y;
    const int tid = threadIdx.x, lane = tid & 31, wid = tid >> 5;
    const float absc = fabsf(curv[0]);

    // per-row hyperbolic pipeline; warp handles 8 rows, lane owns dims (lane, lane+32)
    for (int r = 0; r < 8; ++r){
        int m = wid*8 + r;
        int h0 = hI[b*Mq + m];
        float hv0 = E[h0*Dq + lane], hv1 = E[h0*Dq + lane + 32];
        int r0 = rI[b*Mq + m];
        float pv0 = R[r0*Dq + lane], pv1 = R[r0*Dq + lane + 32];
        if (layer){
            int h1 = hI[BMq + b*Mq + m];
            hv0 += E[h1*Dq + lane]; hv1 += E[h1*Dq + lane + 32];
            int r1 = rI[BMq + b*Mq + m];
            pv0 *= R[r1*Dq + lane]; pv1 *= R[r1*Dq + lane + 32];
        }
        int t0 = tI[layer*BMq + b*Mq + m];
        float tv0 = E[t0*Dq + lane], tv1 = E[t0*Dq + lane + 32];

        // l2 normalize (x / max(||x||, 1e-12))
        float nh = sqrtf(wsum(hv0*hv0 + hv1*hv1)); float ih = 1.f/fmaxf(nh, 1e-12f); hv0 *= ih; hv1 *= ih;
        float np = sqrtf(wsum(pv0*pv0 + pv1*pv1)); float ip = 1.f/fmaxf(np, 1e-12f); pv0 *= ip; pv1 *= ip;
        float nt = sqrtf(wsum(tv0*tv0 + tv1*tv1)); float it = 1.f/fmaxf(nt, 1e-12f); tv0 *= it; tv1 *= it;

        // hh = expmap0(h)*|c|
        float n1 = sqrtf(fmaxf(wsum(hv0*hv0 + hv1*hv1), 1e-15f));
        float s1 = tanhf(n1)/n1*absc;
        float hh0 = s1*hv0, hh1 = s1*hv1;
        float hh2 = wsum(hh0*hh0 + hh1*hh1);
        float lam = 2.f/fmaxf(1.f - hh2, 1e-15f);

        // ht = expmap(t, hh)
        float ntn = sqrtf(fmaxf(wsum(tv0*tv0 + tv1*tv1), 1e-15f));
        float st  = tanhf(lam*ntn*0.5f)/ntn;
        float y0 = st*tv0, y1 = st*tv1;
        float y2 = wsum(y0*y0 + y1*y1);
        float xy = wsum(hh0*y0 + hh1*y1);
        float c1 = 1.f + 2.f*xy + y2, c2 = 1.f - hh2;
        float den = fmaxf(1.f + 2.f*xy + hh2*y2, 1e-15f);
        float ht0 = (c1*hh0 + c2*y0)/den, ht1 = (c1*hh1 + c2*y1)/den;

        // hr = expmap(path, hh)
        float npn = sqrtf(fmaxf(wsum(pv0*pv0 + pv1*pv1), 1e-15f));
        float sp  = tanhf(lam*npn*0.5f)/npn;
        float q0 = sp*pv0, q1 = sp*pv1;
        float q2 = wsum(q0*q0 + q1*q1);
        float xq = wsum(hh0*q0 + hh1*q1);
        float d1 = 1.f + 2.f*xq + q2, d2 = 1.f - hh2;
        float dd = fmaxf(1.f + 2.f*xq + hh2*q2, 1e-15f);
        float hr0 = (d1*hh0 + d2*q0)/dd, hr1 = (d1*hh1 + d2*q1)/dd;

        // tang = logmap0([hh, hr])  (128-dim norm)
        float hr2 = wsum(hr0*hr0 + hr1*hr1);
        float n128 = sqrtf(fmaxf(hh2 + hr2, 1e-15f));
        float stg = artanh_clip(n128)/n128;

        hhs[m*64 + lane] = hh0; hhs[m*64 + lane + 32] = hh1;
        hts[m*64 + lane] = ht0; hts[m*64 + lane + 32] = ht1;
        tang[m*130 + lane]        = stg*hh0; tang[m*130 + lane + 32]      = stg*hh1;
        tang[m*130 + 64 + lane]   = stg*hr0; tang[m*130 + 64 + lane + 32] = stg*hr1;
    }
    __syncthreads();

    // z = relu(tang @ W1 + b1), fused W2 dot + tanh
    const int ty = tid >> 4, tx = tid & 15;
    const float4* W1v = (const float4*)W1;
    float acc[4][4] = {};
#pragma unroll 4
    for (int k = 0; k < 128; ++k){
        float a0 = tang[(ty*4+0)*130 + k];
        float a1 = tang[(ty*4+1)*130 + k];
        float a2 = tang[(ty*4+2)*130 + k];
        float a3 = tang[(ty*4+3)*130 + k];
        float4 bv = __ldg(&W1v[k*16 + tx]);
        acc[0][0] += a0*bv.x; acc[0][1] += a0*bv.y; acc[0][2] += a0*bv.z; acc[0][3] += a0*bv.w;
        acc[1][0] += a1*bv.x; acc[1][1] += a1*bv.y; acc[1][2] += a1*bv.z; acc[1][3] += a1*bv.w;
        acc[2][0] += a2*bv.x; acc[2][1] += a2*bv.y; acc[2][2] += a2*bv.z; acc[2][3] += a2*bv.w;
        acc[3][0] += a3*bv.x; acc[3][1] += a3*bv.y; acc[3][2] += a3*bv.z; acc[3][3] += a3*bv.w;
    }
    float4 b1v = __ldg((const float4*)B1 + tx);
    float4 w2v = __ldg((const float4*)W2 + tx);
    const float b2 = B2[0];
#pragma unroll
    for (int ii = 0; ii < 4; ++ii){
        float v = fmaxf(acc[ii][0] + b1v.x, 0.f)*w2v.x + fmaxf(acc[ii][1] + b1v.y, 0.f)*w2v.y
                + fmaxf(acc[ii][2] + b1v.z, 0.f)*w2v.z + fmaxf(acc[ii][3] + b1v.w, 0.f)*w2v.w;
        v = hsum16(v);
        if (tx == 0) av[ty*4 + ii] = tanhf(v + b2);
    }
    __syncthreads();

    if (wid == 0){
        float a0 = av[lane], a1 = av[lane+32];
        float mx = wmax(fmaxf(a0, a1));
        float e0 = expf(a0 - mx), e1 = expf(a1 - mx);
        float s = wsum(e0 + e1);
        wv[lane] = e0/s; wv[lane+32] = e1/s;
    }
    __syncthreads();

    // mean_pt = sum_m w[m]*hh[m]
    if (tid < 64){
        float a = 0.f;
#pragma unroll 4
        for (int m = 0; m < Mq; ++m) a += wv[m]*hhs[m*64 + tid];
        mp[tid] = a;
    }
    __syncthreads();
    if (wid == 0){
        float v = mp[lane]*mp[lane] + mp[lane+32]*mp[lane+32];
        v = wsum(v);
        if (lane == 0) scal[0] = v;
    }
    __syncthreads();

    // e = logmap(w*ht, mean_pt);  out = sum_m w*e
    const float p2 = scal[0];
    const float mp0 = mp[lane], mp1 = mp[lane+32];
    const float lamp = 2.f/fmaxf(1.f - p2, 1e-15f);
    float o0 = 0.f, o1 = 0.f;
    for (int r = 0; r < 8; ++r){
        int m = wid*8 + r;
        float wm = wv[m];
        float g0 = wm*hts[m*64 + lane], g1 = wm*hts[m*64 + lane + 32];
        float y2 = wsum(g0*g0 + g1*g1);
        float xy = wsum(-(mp0*g0 + mp1*g1));
        float c1 = 1.f + 2.f*xy + y2, c2 = 1.f - p2;
        float den = fmaxf(1.f + 2.f*xy + p2*y2, 1e-15f);
        float mm0 = (c1*(-mp0) + c2*g0)/den, mm1 = (c1*(-mp1) + c2*g1)/den;
        float n = sqrtf(fmaxf(wsum(mm0*mm0 + mm1*mm1), 1e-15f));
        float sc = (2.f/lamp)*artanh_clip(n)/n;
        o0 += wm*sc*mm0; o1 += wm*sc*mm1;
    }
    parts[wid*64 + lane] = o0; parts[wid*64 + lane + 32] = o1;
    __syncthreads();
    if (tid < 64){
        float s = 0.f;
#pragma unroll
        for (int w = 0; w < 8; ++w) s += parts[w*64 + tid];
        g_embs[eidx(build, layer+1, b, tid)] = s;
    }
}

// ---------------- l2-normalize all stacks ----------------
__global__ void normalize_kernel(){
    int row = blockIdx.x*8 + (threadIdx.x >> 5);
    int lane = threadIdx.x & 31;
    if (row >= 4*3*Bq) return;
    const float* s = g_embs + row*Dq;
    float* d = g_norm + row*Dq;
    float v0 = s[lane], v1 = s[lane+32];
    float n = sqrtf(wsum(v0*v0 + v1*v1));
    float inv = 1.f/fmaxf(n, 1e-12f);
    d[lane] = v0*inv; d[lane+32] = v1*inv;
}

// ---------------- MLCL GEMM with fused exp row/col sums (128x128 tiles) ----------------
#define ML_SMEM_FLOATS (128*68 + 64*132 + 128)
__global__ __launch_bounds__(256) void mlcl_gemm(int pair){
    const float* A  = g_norm + (pair == 0 ? 0 : 1)*NPB;
    const float* Bn = g_norm + (pair == 0 ? 2 : 3)*NPB;
    float* rs = g_rowsum + pair*ROWS;
    float* cs = g_colsum + pair*ROWS;

    extern __shared__ float sm[];
    float* As = sm;             // [128][68]
    float* Bs = As + 128*68;    // [64][132]  (transposed: Bs[k][col])
    float* colpart = Bs + 64*132; // [128]

    const int tid = threadIdx.x;
    const int by = blockIdx.y, bx = blockIdx.x;

    // stage A (row-major) and B (transposed)
    for (int e = tid; e < 2048; e += 256){
        int i = e >> 4, k4 = e & 15;
        float4 v = *(const float4*)&A[(by*128 + i)*64 + k4*4];
        *(float4*)&As[i*68 + k4*4] = v;
    }
    for (int e = tid; e < 2048; e += 256){
        int j = e >> 4, k4 = e & 15;
        float4 v = *(const float4*)&Bn[(bx*128 + j)*64 + k4*4];
        Bs[(k4*4+0)*132 + j] = v.x;
        Bs[(k4*4+1)*132 + j] = v.y;
        Bs[(k4*4+2)*132 + j] = v.z;
        Bs[(k4*4+3)*132 + j] = v.w;
    }
    if (tid < 128) colpart[tid] = 0.f;
    __syncthreads();

    const int ty = tid >> 4, tx = tid & 15;   // rows ty*8.., cols tx*8..
    float acc[8][8] = {};
#pragma unroll 4
    for (int k = 0; k < 64; ++k){
        float a[8];
#pragma unroll
        for (int ii = 0; ii < 8; ++ii) a[ii] = As[(ty*8+ii)*68 + k];
        float4 b0 = *(const float4*)&Bs[k*132 + tx*8];
        float4 b1 = *(const float4*)&Bs[k*132 + tx*8 + 4];
        float bb[8] = {b0.x,b0.y,b0.z,b0.w,b1.x,b1.y,b1.z,b1.w};
#pragma unroll
        for (int ii = 0; ii < 8; ++ii)
#pragma unroll
            for (int jj = 0; jj < 8; ++jj) acc[ii][jj] += a[ii]*bb[jj];
    }
    // fused exp(*5) row/col sums
    float cp[8] = {0,0,0,0,0,0,0,0};
#pragma unroll
    for (int ii = 0; ii < 8; ++ii){
        float rp = 0.f;
#pragma unroll
        for (int jj = 0; jj < 8; ++jj){
            float e = __expf(acc[ii][jj]*5.0f);   // 1/TEMP = 5
            rp += e; cp[jj] += e;
        }
        rp = hsum16(rp);
        if (tx == 0) atomicAdd(&rs[by*128 + ty*8 + ii], rp);
    }
#pragma unroll
    for (int jj = 0; jj < 8; ++jj) atomicAdd(&colpart[tx*8 + jj], cp[jj]);
    __syncthreads();
    if (tid < 128) atomicAdd(&cs[bx*128 + tid], colpart[tid]);
}

// ---------------- loss reduction (parallel) ----------------
__global__ void loss_kernel(){
    const int wid = threadIdx.x >> 5, lane = threadIdx.x & 31;
    int r = blockIdx.x*8 + wid;
    int pair = r >= ROWS;
    int i = r - pair*ROWS;
    const float* A  = g_norm + (pair ? 1 : 0)*NPB;
    const float* Bn = g_norm + (pair ? 3 : 2)*NPB;
    float d = A[i*64 + lane]*Bn[i*64 + lane] + A[i*64 + lane + 32]*Bn[i*64 + lane + 32];
    d = wsum(d);
    __shared__ float red[8];
    if (lane == 0)
        red[wid] = logf(g_rowsum[pair*ROWS + i]) + logf(g_colsum[pair*ROWS + i]) - 10.f*d;
    __syncthreads();
    if (threadIdx.x == 0){
        float s = 0.f;
#pragma unroll
        for (int w = 0; w < 8; ++w) s += red[w];
        atomicAdd(&g_loss, s);
    }
}

// ---------------- scores + loss finalize ----------------
__global__ void scores_kernel(float* out, int out_size){
    int b = blockIdx.x*8 + (threadIdx.x >> 5);
    int lane = threadIdx.x & 31;
    if (blockIdx.x == 0 && threadIdx.x == 0 && out_size > Bq) out[Bq] = 1e-6f*g_loss;
    if (b >= Bq) return;
    float s = 0.f;
#pragma unroll
    for (int l = 0; l < 3; ++l){
        s += g_embs[eidx(0,l,b,lane)]   *g_embs[eidx(3,l,b,lane)]
           + g_embs[eidx(0,l,b,lane+32)]*g_embs[eidx(3,l,b,lane+32)]
           + g_embs[eidx(2,l,b,lane)]   *g_embs[eidx(1,l,b,lane)]
           + g_embs[eidx(2,l,b,lane+32)]*g_embs[eidx(1,l,b,lane+32)];
    }
    s = wsum(s);
    if (lane == 0) out[b] = 1.f/(1.f + expf(-s));
}

// ---------------- launch ----------------
extern "C" void kernel_launch(void* const* d_in, const int* in_sizes, int n_in,
                              void* d_out, int out_size){
    (void)in_sizes; (void)n_in;
    const int*   items  = (const int*)  d_in[0];
    const int*   ucf_h  = (const int*)  d_in[1];
    const int*   ucf_r  = (const int*)  d_in[2];
    const int*   ucf_t  = (const int*)  d_in[3];
    const int*   ikg_h  = (const int*)  d_in[4];
    const int*   ikg_r  = (const int*)  d_in[5];
    const int*   ikg_t  = (const int*)  d_in[6];
    const int*   ukg_h  = (const int*)  d_in[7];
    const int*   ukg_r  = (const int*)  d_in[8];
    const int*   ukg_t  = (const int*)  d_in[9];
    const int*   icf_h  = (const int*)  d_in[10];
    const int*   icf_r  = (const int*)  d_in[11];
    const int*   icf_t  = (const int*)  d_in[12];
    const float* E      = (const float*)d_in[13];
    const float* R      = (const float*)d_in[14];
    const float* att_w1 = (const float*)d_in[15];
    const float* att_w2 = (const float*)d_in[16];
    const float* a2_w1  = (const float*)d_in[17];
    const float* a2_b1  = (const float*)d_in[18];
    const float* a2_w2  = (const float*)d_in[19];
    const float* a2_b2  = (const float*)d_in[20];
    const float* curv   = (const float*)d_in[21];
    float* out = (float*)d_out;

    const int ed_smem = ED_SMEM_FLOATS*4;
    const int hy_smem = HY_SMEM_FLOATS*4;
    const int ml_smem = ML_SMEM_FLOATS*4;
    cudaFuncSetAttribute(ed_kernel,    cudaFuncAttributeMaxDynamicSharedMemorySize, ed_smem);
    cudaFuncSetAttribute(hyper_kernel, cudaFuncAttributeMaxDynamicSharedMemorySize, hy_smem);
    cudaFuncSetAttribute(mlcl_gemm,    cudaFuncAttributeMaxDynamicSharedMemorySize, ml_smem);

    zero_kernel<<<(2*ROWS + 1023)/1024, 1024>>>();
    init_kernel<<<Bq, 64>>>(E, items, ucf_h, ukg_h, icf_h);

    dim3 gb(Bq, 2);
    ed_kernel<<<gb, 256, ed_smem>>>(E, R, ucf_h, ucf_r, ucf_t, att_w1, att_w2, 0);
    ed_kernel<<<gb, 256, ed_smem>>>(E, R, ikg_h, ikg_r, ikg_t, att_w1, att_w2, 1);
    hyper_kernel<<<gb, 256, hy_smem>>>(E, R, ukg_h, ukg_r, ukg_t, a2_w1, a2_b1, a2_w2, a2_b2, curv, 2);
    hyper_kernel<<<gb, 256, hy_smem>>>(E, R, icf_h, icf_r, icf_t, a2_w1, a2_b1, a2_w2, a2_b2, curv, 3);

    normalize_kernel<<<(4*3*Bq)/8, 256>>>();
    dim3 gg(48, 48);
    mlcl_gemm<<<gg, 256, ml_smem>>>(0);
    mlcl_gemm<<<gg, 256, ml_smem>>>(1);
    loss_kernel<<<2*ROWS/8, 256>>>();
    scores_kernel<<<Bq/8, 256>>>(out, out_size);
}

// round 5
// speedup vs baseline: 2.2414x; 1.0503x over previous
#include <cuda_runtime.h>
#include <math.h>

#define Bq 2048
#define Mq 64
#define Dq 64
#define BMq (Bq*Mq)
#define NPB (3*Bq*Dq)
#define ROWS 6144

// ---------------- device scratch ----------------
__device__ float g_embs[4*3*Bq*Dq];   // 4 builds x 3 layers x B x D
__device__ float g_norm[4*3*Bq*Dq];
__device__ float g_rowsum[2*ROWS];
__device__ float g_colsum[2*ROWS];
__device__ float g_loss;

typedef unsigned long long ull;

__device__ __forceinline__ void fma2(ull &d, ull a, ull b){
    asm("fma.rn.f32x2 %0, %1, %2, %0;" : "+l"(d) : "l"(a), "l"(b));
}
__device__ __forceinline__ ull pack2(float x, float y){
    ull r; asm("mov.b64 %0, {%1, %2};" : "=l"(r) : "r"(__float_as_uint(x)), "r"(__float_as_uint(y)));
    return r;
}
__device__ __forceinline__ ull dup2(float x){ return pack2(x, x); }
__device__ __forceinline__ void unpack2(ull v, float &x, float &y){
    unsigned a, b;
    asm("mov.b64 {%0, %1}, %2;" : "=r"(a), "=r"(b) : "l"(v));
    x = __uint_as_float(a); y = __uint_as_float(b);
}

__device__ __forceinline__ float wsum(float v){
#pragma unroll
    for (int o = 16; o; o >>= 1) v += __shfl_xor_sync(0xffffffffu, v, o);
    return v;
}
__device__ __forceinline__ void wsum2(float &a, float &b){
#pragma unroll
    for (int o = 16; o; o >>= 1){
        a += __shfl_xor_sync(0xffffffffu, a, o);
        b += __shfl_xor_sync(0xffffffffu, b, o);
    }
}
__device__ __forceinline__ void wsum3(float &a, float &b, float &c){
#pragma unroll
    for (int o = 16; o; o >>= 1){
        a += __shfl_xor_sync(0xffffffffu, a, o);
        b += __shfl_xor_sync(0xffffffffu, b, o);
        c += __shfl_xor_sync(0xffffffffu, c, o);
    }
}
__device__ __forceinline__ float hsum16(float v){
#pragma unroll
    for (int o = 8; o; o >>= 1) v += __shfl_xor_sync(0xffffffffu, v, o);
    return v;
}
__device__ __forceinline__ float wmax(float v){
#pragma unroll
    for (int o = 16; o; o >>= 1) v = fmaxf(v, __shfl_xor_sync(0xffffffffu, v, o));
    return v;
}
__device__ __forceinline__ int eidx(int bl, int l, int b, int j){
    return (((bl*3 + l)*Bq) + b)*Dq + j;
}
__device__ __forceinline__ float artanh_clip(float x){
    x = fminf(fmaxf(x, -1.f + 1e-5f), 1.f - 1e-5f);
    return atanhf(x);
}

// ---------------- zero accumulators ----------------
__global__ void zero_kernel(){
    int i = blockIdx.x*1024 + threadIdx.x;
    if (i < 2*ROWS){ g_rowsum[i] = 0.f; g_colsum[i] = 0.f; }
    if (i == 0) g_loss = 0.f;
}

// ---------------- init embeddings ----------------
__global__ void init_kernel(const float* __restrict__ E, const int* __restrict__ items,
                            const int* __restrict__ ucf_h, const int* __restrict__ ukg_h,
                            const int* __restrict__ icf_h){
    int b = blockIdx.x, j = threadIdx.x;   // 64 threads
    g_embs[eidx(1,0,b,j)] = E[items[b]*Dq + j];
    float s0 = 0.f, s2 = 0.f, s3 = 0.f;
#pragma unroll 4
    for (int m = 0; m < Mq; ++m){
        s0 += E[ucf_h[b*Mq + m]*Dq + j];
        s2 += E[ukg_h[b*Mq + m]*Dq + j];
        s3 += E[icf_h[b*Mq + m]*Dq + j];
    }
    const float inv = 1.f/64.f;
    g_embs[eidx(0,0,b,j)] = s0*inv;
    g_embs[eidx(2,0,b,j)] = s2*inv;
    g_embs[eidx(3,0,b,j)] = s3*inv;
}

// ---------------- euclidean attention aggregation ----------------
// smem: xsT [128][68] k-major, ts [64][68], av 64, wv 64  (~52.7KB -> 4 CTAs/SM)
#define ED_SMEM_FLOATS (128*68 + 64*68 + 64 + 64)
__global__ __launch_bounds__(256) void ed_kernel(
    const float* __restrict__ E, const float* __restrict__ R,
    const int* __restrict__ h0, const int* __restrict__ r0, const int* __restrict__ t0,
    const int* __restrict__ h1, const int* __restrict__ r1, const int* __restrict__ t1,
    const float* __restrict__ W1, const float* __restrict__ W2)
{
    extern __shared__ float sm[];
    float* xsT = sm;                    // [128 k][68]
    float* ts  = xsT + 128*68;          // [64 m][68]
    float* av  = ts + 64*68;
    float* wv  = av + 64;

    const int b = blockIdx.x, layer = blockIdx.y, buildz = blockIdx.z;
    const int* hI = buildz ? h1 : h0;
    const int* rI = buildz ? r1 : r0;
    const int* tI = buildz ? t1 : t0;
    const int build = buildz;           // ed builds 0 (ucf), 1 (ikg)
    const int tid = threadIdx.x, lane = tid & 31, wid = tid >> 5;

    // gather h, path, t  (m-major lanes: conflict-free transposed stores)
    for (int e = tid; e < 1024; e += 256){
        int m = e & 63, k4 = e >> 6;    // k4 in [0,16)
        float4 hv = *(const float4*)&E[hI[b*Mq + m]*Dq + k4*4];
        float4 pv = *(const float4*)&R[rI[b*Mq + m]*Dq + k4*4];
        if (layer){
            float4 h2 = *(const float4*)&E[hI[BMq + b*Mq + m]*Dq + k4*4];
            hv.x += h2.x; hv.y += h2.y; hv.z += h2.z; hv.w += h2.w;
            float4 p2 = *(const float4*)&R[rI[BMq + b*Mq + m]*Dq + k4*4];
            pv.x *= p2.x; pv.y *= p2.y; pv.z *= p2.z; pv.w *= p2.w;
        }
        float4 tv = *(const float4*)&E[tI[layer*BMq + b*Mq + m]*Dq + k4*4];
        xsT[(k4*4+0)*68 + m] = hv.x; xsT[(k4*4+1)*68 + m] = hv.y;
        xsT[(k4*4+2)*68 + m] = hv.z; xsT[(k4*4+3)*68 + m] = hv.w;
        xsT[(64+k4*4+0)*68 + m] = pv.x; xsT[(64+k4*4+1)*68 + m] = pv.y;
        xsT[(64+k4*4+2)*68 + m] = pv.z; xsT[(64+k4*4+3)*68 + m] = pv.w;
        *(float4*)&ts[m*68 + k4*4] = tv;
    }
    __syncthreads();

    // z = relu(x @ W1) fused with W2 dot; packed f32x2 FMA
    const int ty = tid >> 4, tx = tid & 15;
    const ulonglong2* W1v = (const ulonglong2*)W1;   // [k*16 + tx]
    ull acc2[4][2] = {};
#pragma unroll 4
    for (int k = 0; k < 128; ++k){
        float4 a4 = *(const float4*)&xsT[k*68 + ty*4];   // rows ty*4..+3, broadcast
        ulonglong2 bv = __ldg(&W1v[k*16 + tx]);          // cols (tx*4,+1),(+2,+3) packed
        ull a0 = dup2(a4.x), a1 = dup2(a4.y), a2 = dup2(a4.z), a3 = dup2(a4.w);
        fma2(acc2[0][0], a0, bv.x); fma2(acc2[0][1], a0, bv.y);
        fma2(acc2[1][0], a1, bv.x); fma2(acc2[1][1], a1, bv.y);
        fma2(acc2[2][0], a2, bv.x); fma2(acc2[2][1], a2, bv.y);
        fma2(acc2[3][0], a3, bv.x); fma2(acc2[3][1], a3, bv.y);
    }
    float4 w2v = __ldg((const float4*)W2 + tx);
#pragma unroll
    for (int ii = 0; ii < 4; ++ii){
        float c0, c1, c2, c3;
        unpack2(acc2[ii][0], c0, c1); unpack2(acc2[ii][1], c2, c3);
        float v = fmaxf(c0,0.f)*w2v.x + fmaxf(c1,0.f)*w2v.y
                + fmaxf(c2,0.f)*w2v.z + fmaxf(c3,0.f)*w2v.w;
        v = hsum16(v);
        if (tx == 0) av[ty*4 + ii] = 1.f/(1.f + expf(-v));
    }
    __syncthreads();

    if (wid == 0){
        float a0 = av[lane], a1 = av[lane+32];
        float mx = wmax(fmaxf(a0, a1));
        float e0 = expf(a0 - mx), e1 = expf(a1 - mx);
        float s = wsum(e0 + e1);
        wv[lane] = e0/s; wv[lane+32] = e1/s;
    }
    __syncthreads();

    if (tid < 64){
        float o = 0.f;
#pragma unroll 8
        for (int m = 0; m < Mq; ++m) o += wv[m]*ts[m*68 + tid];
        g_embs[eidx(build, layer+1, b, tid)] = o;
    }
}

// ---------------- hyperbolic attention aggregation ----------------
#define HY_SMEM_FLOATS (64*64 + 64*64 + 64*130 + 64 + 64 + 64 + 64 + 16 + 8*64)
__global__ __launch_bounds__(256) void hyper_kernel(
    const float* __restrict__ E, const float* __restrict__ R,
    const int* __restrict__ h0, const int* __restrict__ r0, const int* __restrict__ t0,
    const int* __restrict__ h1, const int* __restrict__ r1, const int* __restrict__ t1,
    const float* __restrict__ W1, const float* __restrict__ B1,
    const float* __restrict__ W2, const float* __restrict__ B2,
    const float* __restrict__ curv)
{
    extern __shared__ float sm[];
    float* hhs  = sm;                   // [64][64]
    float* hts  = hhs + 64*64;          // [64][64]
    float* tang = hts + 64*64;          // [64][130]
    float* av   = tang + 64*130;
    float* wv   = av + 64;
    float* mp   = wv + 64;
    float* ht2s = mp + 64;              // [64] per-row ||ht||^2
    float* scal = ht2s + 64;            // [16]
    float* parts= scal + 16;            // [8][64]

    const int b = blockIdx.x, layer = blockIdx.y, buildz = blockIdx.z;
    const int* hI = buildz ? h1 : h0;
    const int* rI = buildz ? r1 : r0;
    const int* tI = buildz ? t1 : t0;
    const int build = 2 + buildz;       // hyper builds 2 (ukg), 3 (icf)
    const int tid = threadIdx.x, lane = tid & 31, wid = tid >> 5;
    const float absc = fabsf(curv[0]);

    for (int r = 0; r < 8; ++r){
        int m = wid*8 + r;
        int hA = hI[b*Mq + m];
        float hv0 = E[hA*Dq + lane], hv1 = E[hA*Dq + lane + 32];
        int rA = rI[b*Mq + m];
        float pv0 = R[rA*Dq + lane], pv1 = R[rA*Dq + lane + 32];
        if (layer){
            int hB = hI[BMq + b*Mq + m];
            hv0 += E[hB*Dq + lane]; hv1 += E[hB*Dq + lane + 32];
            int rB = rI[BMq + b*Mq + m];
            pv0 *= R[rB*Dq + lane]; pv1 *= R[rB*Dq + lane + 32];
        }
        int tA = tI[layer*BMq + b*Mq + m];
        float tv0 = E[tA*Dq + lane], tv1 = E[tA*Dq + lane + 32];

        // single reduction for the three squared norms
        float nh2 = hv0*hv0 + hv1*hv1;
        float np2 = pv0*pv0 + pv1*pv1;
        float nt2 = tv0*tv0 + tv1*tv1;
        wsum3(nh2, np2, nt2);
        float ih = 1.f/fmaxf(sqrtf(nh2), 1e-12f);
        float ip = 1.f/fmaxf(sqrtf(np2), 1e-12f);
        float it = 1.f/fmaxf(sqrtf(nt2), 1e-12f);

        // hh = expmap0(l2(h))*|c| ; post-norm norms propagated analytically
        float n1 = sqrtf(fmaxf(nh2*ih*ih, 1e-15f));
        float sh = tanhf(n1)/n1*absc*ih;
        float hh0 = sh*hv0, hh1 = sh*hv1;
        float hh2 = sh*sh*nh2;
        float lam = 2.f/fmaxf(1.f - hh2, 1e-15f);

        // y = tanh(lam*|t|/2)*t/|t| on normalized t
        float ntn = sqrtf(fmaxf(nt2*it*it, 1e-15f));
        float sy = tanhf(lam*ntn*0.5f)/ntn*it;
        float y0 = sy*tv0, y1 = sy*tv1;
        float y2 = sy*sy*nt2;

        float npn = sqrtf(fmaxf(np2*ip*ip, 1e-15f));
        float sq = tanhf(lam*npn*0.5f)/npn*ip;
        float q0 = sq*pv0, q1 = sq*pv1;
        float q2 = sq*sq*np2;

        float xy = hh0*y0 + hh1*y1;
        float xq = hh0*q0 + hh1*q1;
        wsum2(xy, xq);

        float c2 = 1.f - hh2;
        float c1 = 1.f + 2.f*xy + y2;
        float den = fmaxf(1.f + 2.f*xy + hh2*y2, 1e-15f);
        float ht0 = (c1*hh0 + c2*y0)/den, ht1 = (c1*hh1 + c2*y1)/den;

        float d1 = 1.f + 2.f*xq + q2;
        float dd = fmaxf(1.f + 2.f*xq + hh2*q2, 1e-15f);
        float hr0 = (d1*hh0 + c2*q0)/dd, hr1 = (d1*hh1 + c2*q1)/dd;

        float ht2 = ht0*ht0 + ht1*ht1;
        float hr2 = hr0*hr0 + hr1*hr1;
        wsum2(ht2, hr2);

        float n128 = sqrtf(fmaxf(hh2 + hr2, 1e-15f));
        float stg = artanh_clip(n128)/n128;

        hhs[m*64 + lane] = hh0; hhs[m*64 + lane + 32] = hh1;
        hts[m*64 + lane] = ht0; hts[m*64 + lane + 32] = ht1;
        if (lane == 0) ht2s[m] = ht2;
        tang[m*130 + lane]      = stg*hh0; tang[m*130 + lane + 32] = stg*hh1;
        tang[m*130 + 64 + lane] = stg*hr0; tang[m*130 + 96 + lane] = stg*hr1;
    }
    __syncthreads();

    // z = relu(tang @ W1 + b1) fused W2 dot + tanh; packed FMA
    const int ty = tid >> 4, tx = tid & 15;
    const ulonglong2* W1v = (const ulonglong2*)W1;
    ull acc2[4][2] = {};
#pragma unroll 4
    for (int k = 0; k < 128; ++k){
        float a0f = tang[(ty*4+0)*130 + k];
        float a1f = tang[(ty*4+1)*130 + k];
        float a2f = tang[(ty*4+2)*130 + k];
        float a3f = tang[(ty*4+3)*130 + k];
        ulonglong2 bv = __ldg(&W1v[k*16 + tx]);
        ull a0 = dup2(a0f), a1 = dup2(a1f), a2 = dup2(a2f), a3 = dup2(a3f);
        fma2(acc2[0][0], a0, bv.x); fma2(acc2[0][1], a0, bv.y);
        fma2(acc2[1][0], a1, bv.x); fma2(acc2[1][1], a1, bv.y);
        fma2(acc2[2][0], a2, bv.x); fma2(acc2[2][1], a2, bv.y);
        fma2(acc2[3][0], a3, bv.x); fma2(acc2[3][1], a3, bv.y);
    }
    float4 b1v = __ldg((const float4*)B1 + tx);
    float4 w2v = __ldg((const float4*)W2 + tx);
    const float b2 = B2[0];
#pragma unroll
    for (int ii = 0; ii < 4; ++ii){
        float c0, c1, c2, c3;
        unpack2(acc2[ii][0], c0, c1); unpack2(acc2[ii][1], c2, c3);
        float v = fmaxf(c0 + b1v.x, 0.f)*w2v.x + fmaxf(c1 + b1v.y, 0.f)*w2v.y
                + fmaxf(c2 + b1v.z, 0.f)*w2v.z + fmaxf(c3 + b1v.w, 0.f)*w2v.w;
        v = hsum16(v);
        if (tx == 0) av[ty*4 + ii] = tanhf(v + b2);
    }
    __syncthreads();

    if (wid == 0){
        float a0 = av[lane], a1 = av[lane+32];
        float mx = wmax(fmaxf(a0, a1));
        float e0 = expf(a0 - mx), e1 = expf(a1 - mx);
        float s = wsum(e0 + e1);
        wv[lane] = e0/s; wv[lane+32] = e1/s;
    }
    __syncthreads();

    if (tid < 64){
        float a = 0.f;
#pragma unroll 8
        for (int m = 0; m < Mq; ++m) a += wv[m]*hhs[m*64 + tid];
        mp[tid] = a;
    }
    __syncthreads();
    if (wid == 0){
        float v = mp[lane]*mp[lane] + mp[lane+32]*mp[lane+32];
        v = wsum(v);
        if (lane == 0) scal[0] = v;
    }
    __syncthreads();

    // e = logmap(w*ht, mean_pt);  out = sum_m w*e  (one wsum per row)
    const float p2 = scal[0];
    const float mp0 = mp[lane], mp1 = mp[lane+32];
    const float lamp = 2.f/fmaxf(1.f - p2, 1e-15f);
    float o0 = 0.f, o1 = 0.f;
    for (int r = 0; r < 8; ++r){
        int m = wid*8 + r;
        float wm = wv[m];
        float g0 = wm*hts[m*64 + lane], g1 = wm*hts[m*64 + lane + 32];
        float y2 = wm*wm*ht2s[m];
        float dotv = wsum(mp0*g0 + mp1*g1);
        float xy = -dotv;
        float c1 = 1.f + 2.f*xy + y2, c2 = 1.f - p2;
        float den = fmaxf(1.f + 2.f*xy + p2*y2, 1e-15f);
        float invden = 1.f/den;
        float mm0 = (c1*(-mp0) + c2*g0)*invden, mm1 = (c1*(-mp1) + c2*g1)*invden;
        float n2 = (c1*c1*p2 + 2.f*c1*c2*xy + c2*c2*y2)*invden*invden;
        float n = sqrtf(fmaxf(n2, 1e-15f));
        float sc = (2.f/lamp)*artanh_clip(n)/n;
        o0 += wm*sc*mm0; o1 += wm*sc*mm1;
    }
    parts[wid*64 + lane] = o0; parts[wid*64 + lane + 32] = o1;
    __syncthreads();
    if (tid < 64){
        float s = 0.f;
#pragma unroll
        for (int w = 0; w < 8; ++w) s += parts[w*64 + tid];
        g_embs[eidx(build, layer+1, b, tid)] = s;
    }
}

// ---------------- l2-normalize all stacks ----------------
__global__ void normalize_kernel(){
    int row = blockIdx.x*8 + (threadIdx.x >> 5);
    int lane = threadIdx.x & 31;
    if (row >= 4*3*Bq) return;
    const float* s = g_embs + row*Dq;
    float* d = g_norm + row*Dq;
    float v0 = s[lane], v1 = s[lane+32];
    float n = sqrtf(wsum(v0*v0 + v1*v1));
    float inv = 1.f/fmaxf(n, 1e-12f);
    d[lane] = v0*inv; d[lane+32] = v1*inv;
}

// ---------------- MLCL GEMM with fused exp row/col sums (128x128 tiles, f32x2) ----------------
#define ML_SMEM_FLOATS (64*136 + 64*132 + 128)
__global__ __launch_bounds__(256) void mlcl_gemm(){
    const int pair = blockIdx.z;
    const float* A  = g_norm + (pair == 0 ? 0 : 1)*NPB;
    const float* Bn = g_norm + (pair == 0 ? 2 : 3)*NPB;
    float* rs = g_rowsum + pair*ROWS;
    float* cs = g_colsum + pair*ROWS;

    extern __shared__ float sm[];
    float* AsT = sm;               // [64 k][136]  (transposed: AsT[k][row])
    float* Bs  = AsT + 64*136;     // [64 k][132]  (transposed: Bs[k][col])
    float* colpart = Bs + 64*132;  // [128]

    const int tid = threadIdx.x;
    const int by = blockIdx.y, bx = blockIdx.x;

    for (int e = tid; e < 2048; e += 256){
        int i = e & 127, k4 = e >> 7;
        float4 v = *(const float4*)&A[(by*128 + i)*64 + k4*4];
        AsT[(k4*4+0)*136 + i] = v.x; AsT[(k4*4+1)*136 + i] = v.y;
        AsT[(k4*4+2)*136 + i] = v.z; AsT[(k4*4+3)*136 + i] = v.w;
    }
    for (int e = tid; e < 2048; e += 256){
        int j = e & 127, k4 = e >> 7;
        float4 v = *(const float4*)&Bn[(bx*128 + j)*64 + k4*4];
        Bs[(k4*4+0)*132 + j] = v.x; Bs[(k4*4+1)*132 + j] = v.y;
        Bs[(k4*4+2)*132 + j] = v.z; Bs[(k4*4+3)*132 + j] = v.w;
    }
    if (tid < 128) colpart[tid] = 0.f;
    __syncthreads();

    const int ty = tid >> 4, tx = tid & 15;   // rows ty*8.., cols tx*8..
    ull acc2[4][8] = {};                       // row-pairs (2p,2p+1) x 8 cols
#pragma unroll 4
    for (int k = 0; k < 64; ++k){
        ulonglong2 ap0 = *(const ulonglong2*)&AsT[k*136 + ty*8];      // rows 0-3 packed
        ulonglong2 ap1 = *(const ulonglong2*)&AsT[k*136 + ty*8 + 4];  // rows 4-7 packed
        float4 b0 = *(const float4*)&Bs[k*132 + tx*8];
        float4 b1 = *(const float4*)&Bs[k*132 + tx*8 + 4];
        ull bd[8] = { dup2(b0.x), dup2(b0.y), dup2(b0.z), dup2(b0.w),
                      dup2(b1.x), dup2(b1.y), dup2(b1.z), dup2(b1.w) };
#pragma unroll
        for (int jj = 0; jj < 8; ++jj){
            fma2(acc2[0][jj], ap0.x, bd[jj]);
            fma2(acc2[1][jj], ap0.y, bd[jj]);
            fma2(acc2[2][jj], ap1.x, bd[jj]);
            fma2(acc2[3][jj], ap1.y, bd[jj]);
        }
    }
    float cp[8] = {0,0,0,0,0,0,0,0};
#pragma unroll
    for (int p = 0; p < 4; ++p){
        float rpl = 0.f, rph = 0.f;
#pragma unroll
        for (int jj = 0; jj < 8; ++jj){
            float elo, ehi;
            unpack2(acc2[p][jj], elo, ehi);
            elo = __expf(elo*5.0f); ehi = __expf(ehi*5.0f);   // 1/TEMP = 5
            rpl += elo; rph += ehi; cp[jj] += elo + ehi;
        }
        rpl = hsum16(rpl); rph = hsum16(rph);
        if (tx == 0){
            atomicAdd(&rs[by*128 + ty*8 + 2*p],     rpl);
            atomicAdd(&rs[by*128 + ty*8 + 2*p + 1], rph);
        }
    }
#pragma unroll
    for (int jj = 0; jj < 8; ++jj) atomicAdd(&colpart[tx*8 + jj], cp[jj]);
    __syncthreads();
    if (tid < 128) atomicAdd(&cs[bx*128 + tid], colpart[tid]);
}

// ---------------- loss reduction ----------------
__global__ void loss_kernel(){
    const int wid = threadIdx.x >> 5, lane = threadIdx.x & 31;
    int r = blockIdx.x*8 + wid;
    int pair = r >= ROWS;
    int i = r - pair*ROWS;
    const float* A  = g_norm + (pair ? 1 : 0)*NPB;
    const float* Bn = g_norm + (pair ? 3 : 2)*NPB;
    float d = A[i*64 + lane]*Bn[i*64 + lane] + A[i*64 + lane + 32]*Bn[i*64 + lane + 32];
    d = wsum(d);
    __shared__ float red[8];
    if (lane == 0)
        red[wid] = logf(g_rowsum[pair*ROWS + i]) + logf(g_colsum[pair*ROWS + i]) - 10.f*d;
    __syncthreads();
    if (threadIdx.x == 0){
        float s = 0.f;
#pragma unroll
        for (int w = 0; w < 8; ++w) s += red[w];
        atomicAdd(&g_loss, s);
    }
}

// ---------------- scores + loss finalize ----------------
__global__ void scores_kernel(float* out, int out_size){
    int b = blockIdx.x*8 + (threadIdx.x >> 5);
    int lane = threadIdx.x & 31;
    if (blockIdx.x == 0 && threadIdx.x == 0 && out_size > Bq) out[Bq] = 1e-6f*g_loss;
    if (b >= Bq) return;
    float s = 0.f;
#pragma unroll
    for (int l = 0; l < 3; ++l){
        s += g_embs[eidx(0,l,b,lane)]   *g_embs[eidx(3,l,b,lane)]
           + g_embs[eidx(0,l,b,lane+32)]*g_embs[eidx(3,l,b,lane+32)]
           + g_embs[eidx(2,l,b,lane)]   *g_embs[eidx(1,l,b,lane)]
           + g_embs[eidx(2,l,b,lane+32)]*g_embs[eidx(1,l,b,lane+32)];
    }
    s = wsum(s);
    if (lane == 0) out[b] = 1.f/(1.f + expf(-s));
}

// ---------------- launch ----------------
extern "C" void kernel_launch(void* const* d_in, const int* in_sizes, int n_in,
                              void* d_out, int out_size){
    (void)in_sizes; (void)n_in;
    const int*   items  = (const int*)  d_in[0];
    const int*   ucf_h  = (const int*)  d_in[1];
    const int*   ucf_r  = (const int*)  d_in[2];
    const int*   ucf_t  = (const int*)  d_in[3];
    const int*   ikg_h  = (const int*)  d_in[4];
    const int*   ikg_r  = (const int*)  d_in[5];
    const int*   ikg_t  = (const int*)  d_in[6];
    const int*   ukg_h  = (const int*)  d_in[7];
    const int*   ukg_r  = (const int*)  d_in[8];
    const int*   ukg_t  = (const int*)  d_in[9];
    const int*   icf_h  = (const int*)  d_in[10];
    const int*   icf_r  = (const int*)  d_in[11];
    const int*   icf_t  = (const int*)  d_in[12];
    const float* E      = (const float*)d_in[13];
    const float* R      = (const float*)d_in[14];
    const float* att_w1 = (const float*)d_in[15];
    const float* att_w2 = (const float*)d_in[16];
    const float* a2_w1  = (const float*)d_in[17];
    const float* a2_b1  = (const float*)d_in[18];
    const float* a2_w2  = (const float*)d_in[19];
    const float* a2_b2  = (const float*)d_in[20];
    const float* curv   = (const float*)d_in[21];
    float* out = (float*)d_out;

    const int ed_smem = ED_SMEM_FLOATS*4;
    const int hy_smem = HY_SMEM_FLOATS*4;
    const int ml_smem = ML_SMEM_FLOATS*4;
    cudaFuncSetAttribute(ed_kernel,    cudaFuncAttributeMaxDynamicSharedMemorySize, ed_smem);
    cudaFuncSetAttribute(hyper_kernel, cudaFuncAttributeMaxDynamicSharedMemorySize, hy_smem);
    cudaFuncSetAttribute(mlcl_gemm,    cudaFuncAttributeMaxDynamicSharedMemorySize, ml_smem);

    zero_kernel<<<(2*ROWS + 1023)/1024, 1024>>>();
    init_kernel<<<Bq, 64>>>(E, items, ucf_h, ukg_h, icf_h);

    dim3 gb(Bq, 2, 2);
    ed_kernel<<<gb, 256, ed_smem>>>(E, R, ucf_h, ucf_r, ucf_t, ikg_h, ikg_r, ikg_t, att_w1, att_w2);
    hyper_kernel<<<gb, 256, hy_smem>>>(E, R, ukg_h, ukg_r, ukg_t, icf_h, icf_r, icf_t,
                                       a2_w1, a2_b1, a2_w2, a2_b2, curv);

    normalize_kernel<<<(4*3*Bq)/8, 256>>>();
    dim3 gg(48, 48, 2);
    mlcl_gemm<<<gg, 256, ml_smem>>>();
    loss_kernel<<<2*ROWS/8, 256>>>();
    scores_kernel<<<Bq/8, 256>>>(out, out_size);
}

// round 6
// speedup vs baseline: 2.4859x; 1.1091x over previous
#include <cuda_runtime.h>
#include <math.h>

#define Bq 2048
#define Mq 64
#define Dq 64
#define BMq (Bq*Mq)
#define NPB (3*Bq*Dq)
#define ROWS 6144

// ---------------- device scratch ----------------
__device__ float g_embs[4*3*Bq*Dq];   // 4 builds x 3 layers x B x D
__device__ float g_norm[4*3*Bq*Dq];
__device__ float g_rowsum[2*ROWS];
__device__ float g_colsum[2*ROWS];
__device__ float g_loss;

typedef unsigned long long ull;

__device__ __forceinline__ void fma2(ull &d, ull a, ull b){
    asm("fma.rn.f32x2 %0, %1, %2, %0;" : "+l"(d) : "l"(a), "l"(b));
}
__device__ __forceinline__ ull pack2(float x, float y){
    ull r; asm("mov.b64 %0, {%1, %2};" : "=l"(r) : "r"(__float_as_uint(x)), "r"(__float_as_uint(y)));
    return r;
}
__device__ __forceinline__ ull dup2(float x){ return pack2(x, x); }
__device__ __forceinline__ void unpack2(ull v, float &x, float &y){
    unsigned a, b;
    asm("mov.b64 {%0, %1}, %2;" : "=r"(a), "=r"(b) : "l"(v));
    x = __uint_as_float(a); y = __uint_as_float(b);
}

__device__ __forceinline__ float wsum(float v){
#pragma unroll
    for (int o = 16; o; o >>= 1) v += __shfl_xor_sync(0xffffffffu, v, o);
    return v;
}
__device__ __forceinline__ void wsum5(float &a, float &b, float &c, float &d, float &e){
#pragma unroll
    for (int o = 16; o; o >>= 1){
        a += __shfl_xor_sync(0xffffffffu, a, o);
        b += __shfl_xor_sync(0xffffffffu, b, o);
        c += __shfl_xor_sync(0xffffffffu, c, o);
        d += __shfl_xor_sync(0xffffffffu, d, o);
        e += __shfl_xor_sync(0xffffffffu, e, o);
    }
}
__device__ __forceinline__ float hsum16(float v){
#pragma unroll
    for (int o = 8; o; o >>= 1) v += __shfl_xor_sync(0xffffffffu, v, o);
    return v;
}
__device__ __forceinline__ float wmax(float v){
#pragma unroll
    for (int o = 16; o; o >>= 1) v = fmaxf(v, __shfl_xor_sync(0xffffffffu, v, o));
    return v;
}
__device__ __forceinline__ int eidx(int bl, int l, int b, int j){
    return (((bl*3 + l)*Bq) + b)*Dq + j;
}
// fast tanh via __expf: safe here (arguments ~[0.9, 2.5], no small-x cancellation)
__device__ __forceinline__ float ftanh(float x){
    float e = __expf(2.f*x);
    return 1.f - 2.f/(e + 1.f);
}
__device__ __forceinline__ float fartanh_clip(float x){
    x = fminf(fmaxf(x, -1.f + 1e-5f), 1.f - 1e-5f);
    return 0.5f*__logf((1.f + x)/(1.f - x));
}

// ---------------- zero accumulators ----------------
__global__ void zero_kernel(){
    int i = blockIdx.x*1024 + threadIdx.x;
    if (i < 2*ROWS){ g_rowsum[i] = 0.f; g_colsum[i] = 0.f; }
    if (i == 0) g_loss = 0.f;
}

// ---------------- init embeddings ----------------
__global__ void init_kernel(const float* __restrict__ E, const int* __restrict__ items,
                            const int* __restrict__ ucf_h, const int* __restrict__ ukg_h,
                            const int* __restrict__ icf_h){
    int b = blockIdx.x, j = threadIdx.x;   // 64 threads
    g_embs[eidx(1,0,b,j)] = E[items[b]*Dq + j];
    float s0 = 0.f, s2 = 0.f, s3 = 0.f;
#pragma unroll 4
    for (int m = 0; m < Mq; ++m){
        s0 += E[ucf_h[b*Mq + m]*Dq + j];
        s2 += E[ukg_h[b*Mq + m]*Dq + j];
        s3 += E[icf_h[b*Mq + m]*Dq + j];
    }
    const float inv = 1.f/64.f;
    g_embs[eidx(0,0,b,j)] = s0*inv;
    g_embs[eidx(2,0,b,j)] = s2*inv;
    g_embs[eidx(3,0,b,j)] = s3*inv;
}

// ---------------- euclidean attention aggregation ----------------
#define ED_SMEM_FLOATS (128*68 + 64*68 + 64 + 64)
__global__ __launch_bounds__(256) void ed_kernel(
    const float* __restrict__ E, const float* __restrict__ R,
    const int* __restrict__ h0, const int* __restrict__ r0, const int* __restrict__ t0,
    const int* __restrict__ h1, const int* __restrict__ r1, const int* __restrict__ t1,
    const float* __restrict__ W1, const float* __restrict__ W2)
{
    extern __shared__ float sm[];
    float* xsT = sm;                    // [128 k][68]
    float* ts  = xsT + 128*68;          // [64 m][68]
    float* av  = ts + 64*68;
    float* wv  = av + 64;

    const int b = blockIdx.x, layer = blockIdx.y, buildz = blockIdx.z;
    const int* hI = buildz ? h1 : h0;
    const int* rI = buildz ? r1 : r0;
    const int* tI = buildz ? t1 : t0;
    const int build = buildz;
    const int tid = threadIdx.x, lane = tid & 31, wid = tid >> 5;

    for (int e = tid; e < 1024; e += 256){
        int m = e & 63, k4 = e >> 6;
        float4 hv = *(const float4*)&E[hI[b*Mq + m]*Dq + k4*4];
        float4 pv = *(const float4*)&R[rI[b*Mq + m]*Dq + k4*4];
        if (layer){
            float4 h2 = *(const float4*)&E[hI[BMq + b*Mq + m]*Dq + k4*4];
            hv.x += h2.x; hv.y += h2.y; hv.z += h2.z; hv.w += h2.w;
            float4 p2 = *(const float4*)&R[rI[BMq + b*Mq + m]*Dq + k4*4];
            pv.x *= p2.x; pv.y *= p2.y; pv.z *= p2.z; pv.w *= p2.w;
        }
        float4 tv = *(const float4*)&E[tI[layer*BMq + b*Mq + m]*Dq + k4*4];
        xsT[(k4*4+0)*68 + m] = hv.x; xsT[(k4*4+1)*68 + m] = hv.y;
        xsT[(k4*4+2)*68 + m] = hv.z; xsT[(k4*4+3)*68 + m] = hv.w;
        xsT[(64+k4*4+0)*68 + m] = pv.x; xsT[(64+k4*4+1)*68 + m] = pv.y;
        xsT[(64+k4*4+2)*68 + m] = pv.z; xsT[(64+k4*4+3)*68 + m] = pv.w;
        *(float4*)&ts[m*68 + k4*4] = tv;
    }
    __syncthreads();

    const int ty = tid >> 4, tx = tid & 15;
    const ulonglong2* W1v = (const ulonglong2*)W1;
    ull acc2[4][2] = {};
#pragma unroll 4
    for (int k = 0; k < 128; ++k){
        float4 a4 = *(const float4*)&xsT[k*68 + ty*4];
        ulonglong2 bv = __ldg(&W1v[k*16 + tx]);
        ull a0 = dup2(a4.x), a1 = dup2(a4.y), a2 = dup2(a4.z), a3 = dup2(a4.w);
        fma2(acc2[0][0], a0, bv.x); fma2(acc2[0][1], a0, bv.y);
        fma2(acc2[1][0], a1, bv.x); fma2(acc2[1][1], a1, bv.y);
        fma2(acc2[2][0], a2, bv.x); fma2(acc2[2][1], a2, bv.y);
        fma2(acc2[3][0], a3, bv.x); fma2(acc2[3][1], a3, bv.y);
    }
    float4 w2v = __ldg((const float4*)W2 + tx);
#pragma unroll
    for (int ii = 0; ii < 4; ++ii){
        float c0, c1, c2, c3;
        unpack2(acc2[ii][0], c0, c1); unpack2(acc2[ii][1], c2, c3);
        float v = fmaxf(c0,0.f)*w2v.x + fmaxf(c1,0.f)*w2v.y
                + fmaxf(c2,0.f)*w2v.z + fmaxf(c3,0.f)*w2v.w;
        v = hsum16(v);
        if (tx == 0) av[ty*4 + ii] = 1.f/(1.f + expf(-v));
    }
    __syncthreads();

    if (wid == 0){
        float a0 = av[lane], a1 = av[lane+32];
        float mx = wmax(fmaxf(a0, a1));
        float e0 = expf(a0 - mx), e1 = expf(a1 - mx);
        float s = wsum(e0 + e1);
        wv[lane] = e0/s; wv[lane+32] = e1/s;
    }
    __syncthreads();

    if (tid < 64){
        float o = 0.f;
#pragma unroll 8
        for (int m = 0; m < Mq; ++m) o += wv[m]*ts[m*68 + tid];
        g_embs[eidx(build, layer+1, b, tid)] = o;
    }
}

// ---------------- hyperbolic attention aggregation (single-reduction form) ----------------
// smem: hts [64][65], tang [64][130], av/wv/mp/ht2s/istg/wh/alpha/beta 8x64, scal 16  (~52KB -> 4 CTAs/SM)
#define HY_SMEM_FLOATS (64*65 + 64*130 + 8*64 + 16)
__global__ __launch_bounds__(256) void hyper_kernel(
    const float* __restrict__ E, const float* __restrict__ R,
    const int* __restrict__ h0, const int* __restrict__ r0, const int* __restrict__ t0,
    const int* __restrict__ h1, const int* __restrict__ r1, const int* __restrict__ t1,
    const float* __restrict__ W1, const float* __restrict__ B1,
    const float* __restrict__ W2, const float* __restrict__ B2,
    const float* __restrict__ curv)
{
    extern __shared__ float sm[];
    float* hts  = sm;                   // [64][65]
    float* tang = hts + 64*65;          // [64][130]
    float* av   = tang + 64*130;        // [64]
    float* wv   = av + 64;              // [64]
    float* mp   = wv + 64;              // [64]
    float* ht2s = mp + 64;              // [64]
    float* istg = ht2s + 64;            // [64]  1/stg per row
    float* wh   = istg + 64;            // [64]
    float* alv  = wh + 64;              // [64]
    float* bev  = alv + 64;             // [64]
    float* scal = bev + 64;             // [16]

    const int b = blockIdx.x, layer = blockIdx.y, buildz = blockIdx.z;
    const int* hI = buildz ? h1 : h0;
    const int* rI = buildz ? r1 : r0;
    const int* tI = buildz ? t1 : t0;
    const int build = 2 + buildz;
    const int tid = threadIdx.x, lane = tid & 31, wid = tid >> 5;
    const float absc = fabsf(curv[0]);

    // ---- phase 1: one 5-wide reduction per row, everything else closed-form ----
    for (int r = 0; r < 8; ++r){
        int m = wid*8 + r;
        int hA = hI[b*Mq + m];
        float hv0 = E[hA*Dq + lane], hv1 = E[hA*Dq + lane + 32];
        int rA = rI[b*Mq + m];
        float pv0 = R[rA*Dq + lane], pv1 = R[rA*Dq + lane + 32];
        if (layer){
            int hB = hI[BMq + b*Mq + m];
            hv0 += E[hB*Dq + lane]; hv1 += E[hB*Dq + lane + 32];
            int rB = rI[BMq + b*Mq + m];
            pv0 *= R[rB*Dq + lane]; pv1 *= R[rB*Dq + lane + 32];
        }
        int tA = tI[layer*BMq + b*Mq + m];
        float tv0 = E[tA*Dq + lane], tv1 = E[tA*Dq + lane + 32];

        float nh2 = hv0*hv0 + hv1*hv1;
        float np2 = pv0*pv0 + pv1*pv1;
        float nt2 = tv0*tv0 + tv1*tv1;
        float dht = hv0*tv0 + hv1*tv1;
        float dhp = hv0*pv0 + hv1*pv1;
        wsum5(nh2, np2, nt2, dht, dhp);

        float ih = 1.f/fmaxf(sqrtf(nh2), 1e-12f);
        float ip = 1.f/fmaxf(sqrtf(np2), 1e-12f);
        float it = 1.f/fmaxf(sqrtf(nt2), 1e-12f);

        // hh = expmap0(l2(h))*|c|
        float n1 = sqrtf(fmaxf(nh2*ih*ih, 1e-15f));
        float sh = ftanh(n1)/n1*absc*ih;
        float hh2 = sh*sh*nh2;
        float lam = 2.f/fmaxf(1.f - hh2, 1e-15f);

        float ntn = sqrtf(fmaxf(nt2*it*it, 1e-15f));
        float sy = ftanh(lam*ntn*0.5f)/ntn*it;
        float y2 = sy*sy*nt2;

        float npn = sqrtf(fmaxf(np2*ip*ip, 1e-15f));
        float sq = ftanh(lam*npn*0.5f)/npn*ip;
        float q2 = sq*sq*np2;

        // dot products propagate through the scalings — no second reduction
        float xy = sh*sy*dht;
        float xq = sh*sq*dhp;

        float c2 = 1.f - hh2;
        float c1 = 1.f + 2.f*xy + y2;
        float den = fmaxf(1.f + 2.f*xy + hh2*y2, 1e-15f);
        float invden = 1.f/den;
        float ht0 = (c1*sh*hv0 + c2*sy*tv0)*invden;
        float ht1 = (c1*sh*hv1 + c2*sy*tv1)*invden;
        float ht2 = (c1*c1*hh2 + 2.f*c1*c2*xy + c2*c2*y2)*invden*invden;

        float d1 = 1.f + 2.f*xq + q2;
        float dd = fmaxf(1.f + 2.f*xq + hh2*q2, 1e-15f);
        float invdd = 1.f/dd;
        float hr0 = (d1*sh*hv0 + c2*sq*pv0)*invdd;
        float hr1 = (d1*sh*hv1 + c2*sq*pv1)*invdd;
        float hr2 = (d1*d1*hh2 + 2.f*d1*c2*xq + c2*c2*q2)*invdd*invdd;

        float n128 = sqrtf(fmaxf(hh2 + hr2, 1e-15f));
        float stg = fartanh_clip(n128)/n128;

        hts[m*65 + lane] = ht0; hts[m*65 + lane + 32] = ht1;
        if (lane == 0){ ht2s[m] = ht2; istg[m] = 1.f/stg; }
        float hh0 = sh*hv0, hh1 = sh*hv1;
        tang[m*130 + lane]      = stg*hh0; tang[m*130 + lane + 32] = stg*hh1;
        tang[m*130 + 64 + lane] = stg*hr0; tang[m*130 + 96 + lane] = stg*hr1;
    }
    __syncthreads();

    // ---- phase 2: attention MLP (packed FMA) ----
    const int ty = tid >> 4, tx = tid & 15;
    const ulonglong2* W1v = (const ulonglong2*)W1;
    ull acc2[4][2] = {};
#pragma unroll 4
    for (int k = 0; k < 128; ++k){
        float a0f = tang[(ty*4+0)*130 + k];
        float a1f = tang[(ty*4+1)*130 + k];
        float a2f = tang[(ty*4+2)*130 + k];
        float a3f = tang[(ty*4+3)*130 + k];
        ulonglong2 bv = __ldg(&W1v[k*16 + tx]);
        ull a0 = dup2(a0f), a1 = dup2(a1f), a2 = dup2(a2f), a3 = dup2(a3f);
        fma2(acc2[0][0], a0, bv.x); fma2(acc2[0][1], a0, bv.y);
        fma2(acc2[1][0], a1, bv.x); fma2(acc2[1][1], a1, bv.y);
        fma2(acc2[2][0], a2, bv.x); fma2(acc2[2][1], a2, bv.y);
        fma2(acc2[3][0], a3, bv.x); fma2(acc2[3][1], a3, bv.y);
    }
    float4 b1v = __ldg((const float4*)B1 + tx);
    float4 w2v = __ldg((const float4*)W2 + tx);
    const float b2 = B2[0];
#pragma unroll
    for (int ii = 0; ii < 4; ++ii){
        float c0, c1, c2, c3;
        unpack2(acc2[ii][0], c0, c1); unpack2(acc2[ii][1], c2, c3);
        float v = fmaxf(c0 + b1v.x, 0.f)*w2v.x + fmaxf(c1 + b1v.y, 0.f)*w2v.y
                + fmaxf(c2 + b1v.z, 0.f)*w2v.z + fmaxf(c3 + b1v.w, 0.f)*w2v.w;
        v = hsum16(v);
        if (tx == 0) av[ty*4 + ii] = ftanh(v + b2);
    }
    __syncthreads();

    if (wid == 0){
        float a0 = av[lane], a1 = av[lane+32];
        float mx = wmax(fmaxf(a0, a1));
        float e0 = expf(a0 - mx), e1 = expf(a1 - mx);
        float s = wsum(e0 + e1);
        wv[lane] = e0/s; wv[lane+32] = e1/s;
    }
    __syncthreads();

    // ---- phase 3: shuffle-free logmap aggregation ----
    if (tid < 64) wh[tid] = wv[tid]*istg[tid];   // weight for hh recovery (hh = tang/stg)
    __syncthreads();
    if (tid < 64){
        float a = 0.f;
#pragma unroll 8
        for (int m = 0; m < Mq; ++m) a += wh[m]*tang[m*130 + tid];
        mp[tid] = a;
    }
    __syncthreads();
    if (wid == 0){
        float v = mp[lane]*mp[lane] + mp[lane+32]*mp[lane+32];
        v = wsum(v);
        if (lane == 0) scal[0] = v;
    }
    __syncthreads();

    if (tid < 64){
        // per-m scalar pipeline: dots via padded smem matvec (bank-conflict-free)
        float dsum = 0.f;
#pragma unroll 8
        for (int j = 0; j < 64; ++j) dsum += hts[tid*65 + j]*mp[j];
        float p2v = scal[0];
        float wm = wv[tid];
        float xy = -wm*dsum;
        float y2 = wm*wm*ht2s[tid];
        float c2v = 1.f - p2v;
        float c1v = 1.f + 2.f*xy + y2;
        float den = fmaxf(1.f + 2.f*xy + p2v*y2, 1e-15f);
        float invden = 1.f/den;
        float n2 = (c1v*c1v*p2v + 2.f*c1v*c2v*xy + c2v*c2v*y2)*invden*invden;
        float n = sqrtf(fmaxf(n2, 1e-15f));
        float lamp = 2.f/fmaxf(1.f - p2v, 1e-15f);
        float sc = (2.f/lamp)*fartanh_clip(n)/n;
        alv[tid] = wm*sc*c1v*invden;
        bev[tid] = wm*wm*sc*c2v*invden;
    }
    __syncthreads();
    if (tid < 64){
        float o = 0.f, sa = 0.f;
#pragma unroll 8
        for (int m = 0; m < Mq; ++m){ o += bev[m]*hts[m*65 + tid]; sa += alv[m]; }
        g_embs[eidx(build, layer+1, b, tid)] = o - mp[tid]*sa;
    }
}

// ---------------- l2-normalize all stacks ----------------
__global__ void normalize_kernel(){
    int row = blockIdx.x*8 + (threadIdx.x >> 5);
    int lane = threadIdx.x & 31;
    if (row >= 4*3*Bq) return;
    const float* s = g_embs + row*Dq;
    float* d = g_norm + row*Dq;
    float v0 = s[lane], v1 = s[lane+32];
    float n = sqrtf(wsum(v0*v0 + v1*v1));
    float inv = 1.f/fmaxf(n, 1e-12f);
    d[lane] = v0*inv; d[lane+32] = v1*inv;
}

// ---------------- MLCL GEMM with fused exp row/col sums (128x128 tiles, f32x2) ----------------
#define ML_SMEM_FLOATS (64*136 + 64*132 + 128)
__global__ __launch_bounds__(256) void mlcl_gemm(){
    const int pair = blockIdx.z;
    const float* A  = g_norm + (pair == 0 ? 0 : 1)*NPB;
    const float* Bn = g_norm + (pair == 0 ? 2 : 3)*NPB;
    float* rs = g_rowsum + pair*ROWS;
    float* cs = g_colsum + pair*ROWS;

    extern __shared__ float sm[];
    float* AsT = sm;               // [64 k][136]
    float* Bs  = AsT + 64*136;     // [64 k][132]
    float* colpart = Bs + 64*132;  // [128]

    const int tid = threadIdx.x;
    const int by = blockIdx.y, bx = blockIdx.x;

    for (int e = tid; e < 2048; e += 256){
        int i = e & 127, k4 = e >> 7;
        float4 v = *(const float4*)&A[(by*128 + i)*64 + k4*4];
        AsT[(k4*4+0)*136 + i] = v.x; AsT[(k4*4+1)*136 + i] = v.y;
        AsT[(k4*4+2)*136 + i] = v.z; AsT[(k4*4+3)*136 + i] = v.w;
    }
    for (int e = tid; e < 2048; e += 256){
        int j = e & 127, k4 = e >> 7;
        float4 v = *(const float4*)&Bn[(bx*128 + j)*64 + k4*4];
        Bs[(k4*4+0)*132 + j] = v.x; Bs[(k4*4+1)*132 + j] = v.y;
        Bs[(k4*4+2)*132 + j] = v.z; Bs[(k4*4+3)*132 + j] = v.w;
    }
    if (tid < 128) colpart[tid] = 0.f;
    __syncthreads();

    const int ty = tid >> 4, tx = tid & 15;
    ull acc2[4][8] = {};
#pragma unroll 4
    for (int k = 0; k < 64; ++k){
        ulonglong2 ap0 = *(const ulonglong2*)&AsT[k*136 + ty*8];
        ulonglong2 ap1 = *(const ulonglong2*)&AsT[k*136 + ty*8 + 4];
        float4 b0 = *(const float4*)&Bs[k*132 + tx*8];
        float4 b1 = *(const float4*)&Bs[k*132 + tx*8 + 4];
        ull bd[8] = { dup2(b0.x), dup2(b0.y), dup2(b0.z), dup2(b0.w),
                      dup2(b1.x), dup2(b1.y), dup2(b1.z), dup2(b1.w) };
#pragma unroll
        for (int jj = 0; jj < 8; ++jj){
            fma2(acc2[0][jj], ap0.x, bd[jj]);
            fma2(acc2[1][jj], ap0.y, bd[jj]);
            fma2(acc2[2][jj], ap1.x, bd[jj]);
            fma2(acc2[3][jj], ap1.y, bd[jj]);
        }
    }
    float cp[8] = {0,0,0,0,0,0,0,0};
#pragma unroll
    for (int p = 0; p < 4; ++p){
        float rpl = 0.f, rph = 0.f;
#pragma unroll
        for (int jj = 0; jj < 8; ++jj){
            float elo, ehi;
            unpack2(acc2[p][jj], elo, ehi);
            elo = __expf(elo*5.0f); ehi = __expf(ehi*5.0f);
            rpl += elo; rph += ehi; cp[jj] += elo + ehi;
        }
        rpl = hsum16(rpl); rph = hsum16(rph);
        if (tx == 0){
            atomicAdd(&rs[by*128 + ty*8 + 2*p],     rpl);
            atomicAdd(&rs[by*128 + ty*8 + 2*p + 1], rph);
        }
    }
#pragma unroll
    for (int jj = 0; jj < 8; ++jj) atomicAdd(&colpart[tx*8 + jj], cp[jj]);
    __syncthreads();
    if (tid < 128) atomicAdd(&cs[bx*128 + tid], colpart[tid]);
}

// ---------------- loss reduction ----------------
__global__ void loss_kernel(){
    const int wid = threadIdx.x >> 5, lane = threadIdx.x & 31;
    int r = blockIdx.x*8 + wid;
    int pair = r >= ROWS;
    int i = r - pair*ROWS;
    const float* A  = g_norm + (pair ? 1 : 0)*NPB;
    const float* Bn = g_norm + (pair ? 3 : 2)*NPB;
    float d = A[i*64 + lane]*Bn[i*64 + lane] + A[i*64 + lane + 32]*Bn[i*64 + lane + 32];
    d = wsum(d);
    __shared__ float red[8];
    if (lane == 0)
        red[wid] = logf(g_rowsum[pair*ROWS + i]) + logf(g_colsum[pair*ROWS + i]) - 10.f*d;
    __syncthreads();
    if (threadIdx.x == 0){
        float s = 0.f;
#pragma unroll
        for (int w = 0; w < 8; ++w) s += red[w];
        atomicAdd(&g_loss, s);
    }
}

// ---------------- scores + loss finalize ----------------
__global__ void scores_kernel(float* out, int out_size){
    int b = blockIdx.x*8 + (threadIdx.x >> 5);
    int lane = threadIdx.x & 31;
    if (blockIdx.x == 0 && threadIdx.x == 0 && out_size > Bq) out[Bq] = 1e-6f*g_loss;
    if (b >= Bq) return;
    float s = 0.f;
#pragma unroll
    for (int l = 0; l < 3; ++l){
        s += g_embs[eidx(0,l,b,lane)]   *g_embs[eidx(3,l,b,lane)]
           + g_embs[eidx(0,l,b,lane+32)]*g_embs[eidx(3,l,b,lane+32)]
           + g_embs[eidx(2,l,b,lane)]   *g_embs[eidx(1,l,b,lane)]
           + g_embs[eidx(2,l,b,lane+32)]*g_embs[eidx(1,l,b,lane+32)];
    }
    s = wsum(s);
    if (lane == 0) out[b] = 1.f/(1.f + expf(-s));
}

// ---------------- launch ----------------
extern "C" void kernel_launch(void* const* d_in, const int* in_sizes, int n_in,
                              void* d_out, int out_size){
    (void)in_sizes; (void)n_in;
    const int*   items  = (const int*)  d_in[0];
    const int*   ucf_h  = (const int*)  d_in[1];
    const int*   ucf_r  = (const int*)  d_in[2];
    const int*   ucf_t  = (const int*)  d_in[3];
    const int*   ikg_h  = (const int*)  d_in[4];
    const int*   ikg_r  = (const int*)  d_in[5];
    const int*   ikg_t  = (const int*)  d_in[6];
    const int*   ukg_h  = (const int*)  d_in[7];
    const int*   ukg_r  = (const int*)  d_in[8];
    const int*   ukg_t  = (const int*)  d_in[9];
    const int*   icf_h  = (const int*)  d_in[10];
    const int*   icf_r  = (const int*)  d_in[11];
    const int*   icf_t  = (const int*)  d_in[12];
    const float* E      = (const float*)d_in[13];
    const float* R      = (const float*)d_in[14];
    const float* att_w1 = (const float*)d_in[15];
    const float* att_w2 = (const float*)d_in[16];
    const float* a2_w1  = (const float*)d_in[17];
    const float* a2_b1  = (const float*)d_in[18];
    const float* a2_w2  = (const float*)d_in[19];
    const float* a2_b2  = (const float*)d_in[20];
    const float* curv   = (const float*)d_in[21];
    float* out = (float*)d_out;

    const int ed_smem = ED_SMEM_FLOATS*4;
    const int hy_smem = HY_SMEM_FLOATS*4;
    const int ml_smem = ML_SMEM_FLOATS*4;
    cudaFuncSetAttribute(ed_kernel,    cudaFuncAttributeMaxDynamicSharedMemorySize, ed_smem);
    cudaFuncSetAttribute(hyper_kernel, cudaFuncAttributeMaxDynamicSharedMemorySize, hy_smem);
    cudaFuncSetAttribute(mlcl_gemm,    cudaFuncAttributeMaxDynamicSharedMemorySize, ml_smem);

    zero_kernel<<<(2*ROWS + 1023)/1024, 1024>>>();
    init_kernel<<<Bq, 64>>>(E, items, ucf_h, ukg_h, icf_h);

    dim3 gb(Bq, 2, 2);
    ed_kernel<<<gb, 256, ed_smem>>>(E, R, ucf_h, ucf_r, ucf_t, ikg_h, ikg_r, ikg_t, att_w1, att_w2);
    hyper_kernel<<<gb, 256, hy_smem>>>(E, R, ukg_h, ukg_r, ukg_t, icf_h, icf_r, icf_t,
                                       a2_w1, a2_b1, a2_w2, a2_b2, curv);

    normalize_kernel<<<(4*3*Bq)/8, 256>>>();
    dim3 gg(48, 48, 2);
    mlcl_gemm<<<gg, 256, ml_smem>>>();
    loss_kernel<<<2*ROWS/8, 256>>>();
    scores_kernel<<<Bq/8, 256>>>(out, out_size);
}

// round 7
// speedup vs baseline: 2.6854x; 1.0802x over previous
#include <cuda_runtime.h>
#include <math.h>

#define Bq 2048
#define Mq 64
#define Dq 64
#define BMq (Bq*Mq)
#define NPB (3*Bq*Dq)
#define ROWS 6144

// ---------------- device scratch ----------------
__device__ float g_embs[4*3*Bq*Dq];   // 4 builds x 3 layers x B x D
__device__ float g_norm[4*3*Bq*Dq];
__device__ float g_rowsum[2*ROWS];
__device__ float g_colsum[2*ROWS];
__device__ float g_loss;

typedef unsigned long long ull;

__device__ __forceinline__ void fma2(ull &d, ull a, ull b){
    asm("fma.rn.f32x2 %0, %1, %2, %0;" : "+l"(d) : "l"(a), "l"(b));
}
__device__ __forceinline__ ull pack2(float x, float y){
    ull r; asm("mov.b64 %0, {%1, %2};" : "=l"(r) : "r"(__float_as_uint(x)), "r"(__float_as_uint(y)));
    return r;
}
__device__ __forceinline__ ull dup2(float x){ return pack2(x, x); }
__device__ __forceinline__ void unpack2(ull v, float &x, float &y){
    unsigned a, b;
    asm("mov.b64 {%0, %1}, %2;" : "=r"(a), "=r"(b) : "l"(v));
    x = __uint_as_float(a); y = __uint_as_float(b);
}

__device__ __forceinline__ float wsum(float v){
#pragma unroll
    for (int o = 16; o; o >>= 1) v += __shfl_xor_sync(0xffffffffu, v, o);
    return v;
}
__device__ __forceinline__ void wsum5(float &a, float &b, float &c, float &d, float &e){
#pragma unroll
    for (int o = 16; o; o >>= 1){
        a += __shfl_xor_sync(0xffffffffu, a, o);
        b += __shfl_xor_sync(0xffffffffu, b, o);
        c += __shfl_xor_sync(0xffffffffu, c, o);
        d += __shfl_xor_sync(0xffffffffu, d, o);
        e += __shfl_xor_sync(0xffffffffu, e, o);
    }
}
__device__ __forceinline__ float hsum16(float v){
#pragma unroll
    for (int o = 8; o; o >>= 1) v += __shfl_xor_sync(0xffffffffu, v, o);
    return v;
}
__device__ __forceinline__ float wmax(float v){
#pragma unroll
    for (int o = 16; o; o >>= 1) v = fmaxf(v, __shfl_xor_sync(0xffffffffu, v, o));
    return v;
}
__device__ __forceinline__ int eidx(int bl, int l, int b, int j){
    return (((bl*3 + l)*Bq) + b)*Dq + j;
}
__device__ __forceinline__ float ftanh(float x){
    float e = __expf(2.f*x);
    return 1.f - 2.f/(e + 1.f);
}
__device__ __forceinline__ float fartanh_clip(float x){
    x = fminf(fmaxf(x, -1.f + 1e-5f), 1.f - 1e-5f);
    return 0.5f*__logf((1.f + x)/(1.f - x));
}

// ---------------- zero accumulators ----------------
__global__ void zero_kernel(){
    int i = blockIdx.x*1024 + threadIdx.x;
    if (i < 2*ROWS){ g_rowsum[i] = 0.f; g_colsum[i] = 0.f; }
    if (i == 0) g_loss = 0.f;
}

// ---------------- init embeddings (256 threads, partial slabs) ----------------
__global__ __launch_bounds__(256) void init_kernel(
    const float* __restrict__ E, const int* __restrict__ items,
    const int* __restrict__ ucf_h, const int* __restrict__ ukg_h,
    const int* __restrict__ icf_h){
    __shared__ float pp[3][4][68];
    int b = blockIdx.x, tid = threadIdx.x;
    int j = tid & 63, q = tid >> 6;
    float s0 = 0.f, s2 = 0.f, s3 = 0.f;
#pragma unroll 4
    for (int mm = 0; mm < 16; ++mm){
        int m = q*16 + mm;
        s0 += E[ucf_h[b*Mq + m]*Dq + j];
        s2 += E[ukg_h[b*Mq + m]*Dq + j];
        s3 += E[icf_h[b*Mq + m]*Dq + j];
    }
    pp[0][q][j] = s0; pp[1][q][j] = s2; pp[2][q][j] = s3;
    __syncthreads();
    if (tid < 64){
        const float inv = 1.f/64.f;
        g_embs[eidx(1,0,b,tid)] = E[items[b]*Dq + tid];
        g_embs[eidx(0,0,b,tid)] = (pp[0][0][tid]+pp[0][1][tid]+pp[0][2][tid]+pp[0][3][tid])*inv;
        g_embs[eidx(2,0,b,tid)] = (pp[1][0][tid]+pp[1][1][tid]+pp[1][2][tid]+pp[1][3][tid])*inv;
        g_embs[eidx(3,0,b,tid)] = (pp[2][0][tid]+pp[2][1][tid]+pp[2][2][tid]+pp[2][3][tid])*inv;
    }
}

// ---------------- euclidean attention aggregation ----------------
#define ED_SMEM_FLOATS (128*68 + 64*68 + 64 + 64 + 4*68)
__global__ __launch_bounds__(256) void ed_kernel(
    const float* __restrict__ E, const float* __restrict__ R,
    const int* __restrict__ h0, const int* __restrict__ r0, const int* __restrict__ t0,
    const int* __restrict__ h1, const int* __restrict__ r1, const int* __restrict__ t1,
    const float* __restrict__ W1, const float* __restrict__ W2)
{
    extern __shared__ float sm[];
    float* xsT = sm;                    // [128 k][68]
    float* ts  = xsT + 128*68;          // [64 m][68]
    float* av  = ts + 64*68;
    float* wv  = av + 64;
    float* pp  = wv + 64;               // [4][68]

    const int b = blockIdx.x, layer = blockIdx.y, buildz = blockIdx.z;
    const int* hI = buildz ? h1 : h0;
    const int* rI = buildz ? r1 : r0;
    const int* tI = buildz ? t1 : t0;
    const int build = buildz;
    const int tid = threadIdx.x, lane = tid & 31, wid = tid >> 5;

    for (int e = tid; e < 1024; e += 256){
        int m = e & 63, k4 = e >> 6;
        float4 hv = *(const float4*)&E[hI[b*Mq + m]*Dq + k4*4];
        float4 pv = *(const float4*)&R[rI[b*Mq + m]*Dq + k4*4];
        if (layer){
            float4 h2 = *(const float4*)&E[hI[BMq + b*Mq + m]*Dq + k4*4];
            hv.x += h2.x; hv.y += h2.y; hv.z += h2.z; hv.w += h2.w;
            float4 p2 = *(const float4*)&R[rI[BMq + b*Mq + m]*Dq + k4*4];
            pv.x *= p2.x; pv.y *= p2.y; pv.z *= p2.z; pv.w *= p2.w;
        }
        float4 tv = *(const float4*)&E[tI[layer*BMq + b*Mq + m]*Dq + k4*4];
        xsT[(k4*4+0)*68 + m] = hv.x; xsT[(k4*4+1)*68 + m] = hv.y;
        xsT[(k4*4+2)*68 + m] = hv.z; xsT[(k4*4+3)*68 + m] = hv.w;
        xsT[(64+k4*4+0)*68 + m] = pv.x; xsT[(64+k4*4+1)*68 + m] = pv.y;
        xsT[(64+k4*4+2)*68 + m] = pv.z; xsT[(64+k4*4+3)*68 + m] = pv.w;
        *(float4*)&ts[m*68 + k4*4] = tv;
    }
    __syncthreads();

    const int ty = tid >> 4, tx = tid & 15;
    const ulonglong2* W1v = (const ulonglong2*)W1;
    ull acc2[4][2] = {};
#pragma unroll 4
    for (int k = 0; k < 128; ++k){
        float4 a4 = *(const float4*)&xsT[k*68 + ty*4];
        ulonglong2 bv = __ldg(&W1v[k*16 + tx]);
        ull a0 = dup2(a4.x), a1 = dup2(a4.y), a2 = dup2(a4.z), a3 = dup2(a4.w);
        fma2(acc2[0][0], a0, bv.x); fma2(acc2[0][1], a0, bv.y);
        fma2(acc2[1][0], a1, bv.x); fma2(acc2[1][1], a1, bv.y);
        fma2(acc2[2][0], a2, bv.x); fma2(acc2[2][1], a2, bv.y);
        fma2(acc2[3][0], a3, bv.x); fma2(acc2[3][1], a3, bv.y);
    }
    float4 w2v = __ldg((const float4*)W2 + tx);
#pragma unroll
    for (int ii = 0; ii < 4; ++ii){
        float c0, c1, c2, c3;
        unpack2(acc2[ii][0], c0, c1); unpack2(acc2[ii][1], c2, c3);
        float v = fmaxf(c0,0.f)*w2v.x + fmaxf(c1,0.f)*w2v.y
                + fmaxf(c2,0.f)*w2v.z + fmaxf(c3,0.f)*w2v.w;
        v = hsum16(v);
        if (tx == 0) av[ty*4 + ii] = 1.f/(1.f + __expf(-v));
    }
    __syncthreads();

    if (wid == 0){
        float a0 = av[lane], a1 = av[lane+32];
        float mx = wmax(fmaxf(a0, a1));
        float e0 = __expf(a0 - mx), e1 = __expf(a1 - mx);
        float s = wsum(e0 + e1);
        wv[lane] = e0/s; wv[lane+32] = e1/s;
    }
    __syncthreads();

    // out[j] = sum_m w[m]*t[m][j] — all 256 threads
    {
        int j = tid & 63, q = tid >> 6;
        float o = 0.f;
#pragma unroll 4
        for (int mm = 0; mm < 16; ++mm){
            int m = q*16 + mm;
            o += wv[m]*ts[m*68 + j];
        }
        pp[q*68 + j] = o;
    }
    __syncthreads();
    if (tid < 64)
        g_embs[eidx(build, layer+1, b, tid)] =
            pp[tid] + pp[68+tid] + pp[136+tid] + pp[204+tid];
}

// ---------------- hyperbolic attention aggregation ----------------
// ||l2(x)|| == 1 identically => hh2, lam, tanh(lam/2) are kernel-wide constants.
#define HY_SMEM_FLOATS (64*65 + 64*130 + 8*64 + 16 + 4*68)
__global__ __launch_bounds__(256) void hyper_kernel(
    const float* __restrict__ E, const float* __restrict__ R,
    const int* __restrict__ h0, const int* __restrict__ r0, const int* __restrict__ t0,
    const int* __restrict__ h1, const int* __restrict__ r1, const int* __restrict__ t1,
    const float* __restrict__ W1, const float* __restrict__ B1,
    const float* __restrict__ W2, const float* __restrict__ B2,
    const float* __restrict__ curv)
{
    extern __shared__ float sm[];
    float* hts  = sm;                   // [64][65]
    float* tang = hts + 64*65;          // [64][130]
    float* av   = tang + 64*130;        // [64]
    float* wv   = av + 64;              // [64]
    float* mp   = wv + 64;              // [64]
    float* ht2s = mp + 64;              // [64]
    float* istg = ht2s + 64;            // [64]
    float* wh   = istg + 64;            // [64]
    float* alv  = wh + 64;              // [64]
    float* bev  = alv + 64;             // [64]
    float* scal = bev + 64;             // [16]
    float* pp   = scal + 16;            // [4][68]

    const int b = blockIdx.x, layer = blockIdx.y, buildz = blockIdx.z;
    const int* hI = buildz ? h1 : h0;
    const int* rI = buildz ? r1 : r0;
    const int* tI = buildz ? t1 : t0;
    const int build = 2 + buildz;
    const int tid = threadIdx.x, lane = tid & 31, wid = tid >> 5;

    // ---- kernel-wide constants (from ||l2(x)|| == 1) ----
    const float absc = fabsf(curv[0]);
    const float th1  = 0.761594155955765f;       // tanh(1)
    const float sh0  = th1*absc;                  // hh = sh0*ih * h_raw
    const float hh2  = sh0*sh0;                   // ||hh||^2 (const)
    const float lam  = 2.f/fmaxf(1.f - hh2, 1e-15f);
    const float tyc  = ftanh(lam*0.5f);           // scale for y and q (|t̂|=|p̂|=1)
    const float y2c  = tyc*tyc;                   // ||y||^2 = ||q||^2 (const)
    const float c2c  = 1.f - hh2;

    // ---- phase 1: one 5-wide reduction per row; zero per-row tanh ----
#pragma unroll 2
    for (int r = 0; r < 8; ++r){
        int m = wid*8 + r;
        int hA = hI[b*Mq + m];
        float hv0 = E[hA*Dq + lane], hv1 = E[hA*Dq + lane + 32];
        int rA = rI[b*Mq + m];
        float pv0 = R[rA*Dq + lane], pv1 = R[rA*Dq + lane + 32];
        if (layer){
            int hB = hI[BMq + b*Mq + m];
            hv0 += E[hB*Dq + lane]; hv1 += E[hB*Dq + lane + 32];
            int rB = rI[BMq + b*Mq + m];
            pv0 *= R[rB*Dq + lane]; pv1 *= R[rB*Dq + lane + 32];
        }
        int tA = tI[layer*BMq + b*Mq + m];
        float tv0 = E[tA*Dq + lane], tv1 = E[tA*Dq + lane + 32];

        float nh2 = hv0*hv0 + hv1*hv1;
        float np2 = pv0*pv0 + pv1*pv1;
        float nt2 = tv0*tv0 + tv1*tv1;
        float dht = hv0*tv0 + hv1*tv1;
        float dhp = hv0*pv0 + hv1*pv1;
        wsum5(nh2, np2, nt2, dht, dhp);

        float ih = 1.f/fmaxf(sqrtf(nh2), 1e-12f);
        float ip = 1.f/fmaxf(sqrtf(np2), 1e-12f);
        float it = 1.f/fmaxf(sqrtf(nt2), 1e-12f);

        float sh = sh0*ih;        // applied to raw h
        float sy = tyc*it;        // applied to raw t
        float sq = tyc*ip;        // applied to raw p

        float xy = sh*sy*dht;
        float xq = sh*sq*dhp;

        float c1 = 1.f + 2.f*xy + y2c;
        float den = fmaxf(1.f + 2.f*xy + hh2*y2c, 1e-15f);
        float invden = 1.f/den;
        float ht0 = (c1*sh*hv0 + c2c*sy*tv0)*invden;
        float ht1 = (c1*sh*hv1 + c2c*sy*tv1)*invden;
        float ht2 = (c1*c1*hh2 + 2.f*c1*c2c*xy + c2c*c2c*y2c)*invden*invden;

        float d1 = 1.f + 2.f*xq + y2c;
        float dd = fmaxf(1.f + 2.f*xq + hh2*y2c, 1e-15f);
        float invdd = 1.f/dd;
        float hr0 = (d1*sh*hv0 + c2c*sq*pv0)*invdd;
        float hr1 = (d1*sh*hv1 + c2c*sq*pv1)*invdd;
        float hr2 = (d1*d1*hh2 + 2.f*d1*c2c*xq + c2c*c2c*y2c)*invdd*invdd;

        float n128 = sqrtf(fmaxf(hh2 + hr2, 1e-15f));
        float stg = fartanh_clip(n128)/n128;

        hts[m*65 + lane] = ht0; hts[m*65 + lane + 32] = ht1;
        if (lane == 0){ ht2s[m] = ht2; istg[m] = 1.f/stg; }
        tang[m*130 + lane]      = stg*sh*hv0; tang[m*130 + lane + 32] = stg*sh*hv1;
        tang[m*130 + 64 + lane] = stg*hr0;    tang[m*130 + 96 + lane] = stg*hr1;
    }
    __syncthreads();

    // ---- phase 2: attention MLP (packed FMA) ----
    const int ty = tid >> 4, tx = tid & 15;
    const ulonglong2* W1v = (const ulonglong2*)W1;
    ull acc2[4][2] = {};
#pragma unroll 4
    for (int k = 0; k < 128; ++k){
        float a0f = tang[(ty*4+0)*130 + k];
        float a1f = tang[(ty*4+1)*130 + k];
        float a2f = tang[(ty*4+2)*130 + k];
        float a3f = tang[(ty*4+3)*130 + k];
        ulonglong2 bv = __ldg(&W1v[k*16 + tx]);
        ull a0 = dup2(a0f), a1 = dup2(a1f), a2 = dup2(a2f), a3 = dup2(a3f);
        fma2(acc2[0][0], a0, bv.x); fma2(acc2[0][1], a0, bv.y);
        fma2(acc2[1][0], a1, bv.x); fma2(acc2[1][1], a1, bv.y);
        fma2(acc2[2][0], a2, bv.x); fma2(acc2[2][1], a2, bv.y);
        fma2(acc2[3][0], a3, bv.x); fma2(acc2[3][1], a3, bv.y);
    }
    float4 b1v = __ldg((const float4*)B1 + tx);
    float4 w2v = __ldg((const float4*)W2 + tx);
    const float b2 = B2[0];
#pragma unroll
    for (int ii = 0; ii < 4; ++ii){
        float c0, c1, c2, c3;
        unpack2(acc2[ii][0], c0, c1); unpack2(acc2[ii][1], c2, c3);
        float v = fmaxf(c0 + b1v.x, 0.f)*w2v.x + fmaxf(c1 + b1v.y, 0.f)*w2v.y
                + fmaxf(c2 + b1v.z, 0.f)*w2v.z + fmaxf(c3 + b1v.w, 0.f)*w2v.w;
        v = hsum16(v);
        if (tx == 0) av[ty*4 + ii] = ftanh(v + b2);
    }
    __syncthreads();

    if (wid == 0){
        float a0 = av[lane], a1 = av[lane+32];
        float mx = wmax(fmaxf(a0, a1));
        float e0 = __expf(a0 - mx), e1 = __expf(a1 - mx);
        float s = wsum(e0 + e1);
        wv[lane] = e0/s; wv[lane+32] = e1/s;
    }
    __syncthreads();

    // ---- phase 3: fully parallel logmap aggregation ----
    if (tid < 64) wh[tid] = wv[tid]*istg[tid];
    __syncthreads();
    {   // mp[j] = sum_m wh[m]*hh[m][j]  (hh = tang/stg)
        int j = tid & 63, q = tid >> 6;
        float a = 0.f;
#pragma unroll 4
        for (int mm = 0; mm < 16; ++mm){
            int m = q*16 + mm;
            a += wh[m]*tang[m*130 + j];
        }
        pp[q*68 + j] = a;
    }
    __syncthreads();
    if (tid < 64) mp[tid] = pp[tid] + pp[68+tid] + pp[136+tid] + pp[204+tid];
    __syncthreads();
    if (wid == 0){
        float v = mp[lane]*mp[lane] + mp[lane+32]*mp[lane+32];
        v = wsum(v);
        if (lane == 0) scal[0] = v;
    }
    __syncthreads();
    {   // dsum[m] = <ht[m], mp>
        int m = tid & 63, q = tid >> 6;
        float a = 0.f;
#pragma unroll 4
        for (int jj = 0; jj < 16; ++jj){
            int j = q*16 + jj;
            a += hts[m*65 + j]*mp[j];
        }
        pp[q*68 + m] = a;
    }
    __syncthreads();
    if (tid < 64){
        float dsum = pp[tid] + pp[68+tid] + pp[136+tid] + pp[204+tid];
        float p2v = scal[0];
        float wm = wv[tid];
        float xy = -wm*dsum;
        float y2 = wm*wm*ht2s[tid];
        float c2v = 1.f - p2v;
        float c1v = 1.f + 2.f*xy + y2;
        float den = fmaxf(1.f + 2.f*xy + p2v*y2, 1e-15f);
        float invden = 1.f/den;
        float n2 = (c1v*c1v*p2v + 2.f*c1v*c2v*xy + c2v*c2v*y2)*invden*invden;
        float n = sqrtf(fmaxf(n2, 1e-15f));
        float lamp = 2.f/fmaxf(1.f - p2v, 1e-15f);
        float sc = (2.f/lamp)*fartanh_clip(n)/n;
        alv[tid] = wm*sc*c1v*invden;
        bev[tid] = wm*wm*sc*c2v*invden;
    }
    __syncthreads();
    if (wid == 0){
        float sa = alv[lane] + alv[lane+32];
        sa = wsum(sa);
        if (lane == 0) scal[1] = sa;
    }
    __syncthreads();
    {   // out[j] = sum_m bev[m]*ht[m][j] - mp[j]*sum(alv)
        int j = tid & 63, q = tid >> 6;
        float o = 0.f;
#pragma unroll 4
        for (int mm = 0; mm < 16; ++mm){
            int m = q*16 + mm;
            o += bev[m]*hts[m*65 + j];
        }
        pp[q*68 + j] = o;
    }
    __syncthreads();
    if (tid < 64)
        g_embs[eidx(build, layer+1, b, tid)] =
            (pp[tid] + pp[68+tid] + pp[136+tid] + pp[204+tid]) - mp[tid]*scal[1];
}

// ---------------- l2-normalize all stacks ----------------
__global__ void normalize_kernel(){
    int row = blockIdx.x*8 + (threadIdx.x >> 5);
    int lane = threadIdx.x & 31;
    if (row >= 4*3*Bq) return;
    const float* s = g_embs + row*Dq;
    float* d = g_norm + row*Dq;
    float v0 = s[lane], v1 = s[lane+32];
    float n = sqrtf(wsum(v0*v0 + v1*v1));
    float inv = 1.f/fmaxf(n, 1e-12f);
    d[lane] = v0*inv; d[lane+32] = v1*inv;
}

// ---------------- MLCL GEMM with fused exp row/col sums ----------------
#define ML_SMEM_FLOATS (64*136 + 64*132 + 128)
__global__ __launch_bounds__(256) void mlcl_gemm(){
    const int pair = blockIdx.z;
    const float* A  = g_norm + (pair == 0 ? 0 : 1)*NPB;
    const float* Bn = g_norm + (pair == 0 ? 2 : 3)*NPB;
    float* rs = g_rowsum + pair*ROWS;
    float* cs = g_colsum + pair*ROWS;

    extern __shared__ float sm[];
    float* AsT = sm;               // [64 k][136]
    float* Bs  = AsT + 64*136;     // [64 k][132]
    float* colpart = Bs + 64*132;  // [128]

    const int tid = threadIdx.x;
    const int by = blockIdx.y, bx = blockIdx.x;

    for (int e = tid; e < 2048; e += 256){
        int i = e & 127, k4 = e >> 7;
        float4 v = *(const float4*)&A[(by*128 + i)*64 + k4*4];
        AsT[(k4*4+0)*136 + i] = v.x; AsT[(k4*4+1)*136 + i] = v.y;
        AsT[(k4*4+2)*136 + i] = v.z; AsT[(k4*4+3)*136 + i] = v.w;
    }
    for (int e = tid; e < 2048; e += 256){
        int j = e & 127, k4 = e >> 7;
        float4 v = *(const float4*)&Bn[(bx*128 + j)*64 + k4*4];
        Bs[(k4*4+0)*132 + j] = v.x; Bs[(k4*4+1)*132 + j] = v.y;
        Bs[(k4*4+2)*132 + j] = v.z; Bs[(k4*4+3)*132 + j] = v.w;
    }
    if (tid < 128) colpart[tid] = 0.f;
    __syncthreads();

    const int ty = tid >> 4, tx = tid & 15;
    ull acc2[4][8] = {};
#pragma unroll 4
    for (int k = 0; k < 64; ++k){
        ulonglong2 ap0 = *(const ulonglong2*)&AsT[k*136 + ty*8];
        ulonglong2 ap1 = *(const ulonglong2*)&AsT[k*136 + ty*8 + 4];
        float4 b0 = *(const float4*)&Bs[k*132 + tx*8];
        float4 b1 = *(const float4*)&Bs[k*132 + tx*8 + 4];
        ull bd[8] = { dup2(b0.x), dup2(b0.y), dup2(b0.z), dup2(b0.w),
                      dup2(b1.x), dup2(b1.y), dup2(b1.z), dup2(b1.w) };
#pragma unroll
        for (int jj = 0; jj < 8; ++jj){
            fma2(acc2[0][jj], ap0.x, bd[jj]);
            fma2(acc2[1][jj], ap0.y, bd[jj]);
            fma2(acc2[2][jj], ap1.x, bd[jj]);
            fma2(acc2[3][jj], ap1.y, bd[jj]);
        }
    }
    float cp[8] = {0,0,0,0,0,0,0,0};
#pragma unroll
    for (int p = 0; p < 4; ++p){
        float rpl = 0.f, rph = 0.f;
#pragma unroll
        for (int jj = 0; jj < 8; ++jj){
            float elo, ehi;
            unpack2(acc2[p][jj], elo, ehi);
            elo = __expf(elo*5.0f); ehi = __expf(ehi*5.0f);
            rpl += elo; rph += ehi; cp[jj] += elo + ehi;
        }
        rpl = hsum16(rpl); rph = hsum16(rph);
        if (tx == 0){
            atomicAdd(&rs[by*128 + ty*8 + 2*p],     rpl);
            atomicAdd(&rs[by*128 + ty*8 + 2*p + 1], rph);
        }
    }
#pragma unroll
    for (int jj = 0; jj < 8; ++jj) atomicAdd(&colpart[tx*8 + jj], cp[jj]);
    __syncthreads();
    if (tid < 128) atomicAdd(&cs[bx*128 + tid], colpart[tid]);
}

// ---------------- loss reduction ----------------
__global__ void loss_kernel(){
    const int wid = threadIdx.x >> 5, lane = threadIdx.x & 31;
    int r = blockIdx.x*8 + wid;
    int pair = r >= ROWS;
    int i = r - pair*ROWS;
    const float* A  = g_norm + (pair ? 1 : 0)*NPB;
    const float* Bn = g_norm + (pair ? 3 : 2)*NPB;
    float d = A[i*64 + lane]*Bn[i*64 + lane] + A[i*64 + lane + 32]*Bn[i*64 + lane + 32];
    d = wsum(d);
    __shared__ float red[8];
    if (lane == 0)
        red[wid] = logf(g_rowsum[pair*ROWS + i]) + logf(g_colsum[pair*ROWS + i]) - 10.f*d;
    __syncthreads();
    if (threadIdx.x == 0){
        float s = 0.f;
#pragma unroll
        for (int w = 0; w < 8; ++w) s += red[w];
        atomicAdd(&g_loss, s);
    }
}

// ---------------- scores + loss finalize ----------------
__global__ void scores_kernel(float* out, int out_size){
    int b = blockIdx.x*8 + (threadIdx.x >> 5);
    int lane = threadIdx.x & 31;
    if (blockIdx.x == 0 && threadIdx.x == 0 && out_size > Bq) out[Bq] = 1e-6f*g_loss;
    if (b >= Bq) return;
    float s = 0.f;
#pragma unroll
    for (int l = 0; l < 3; ++l){
        s += g_embs[eidx(0,l,b,lane)]   *g_embs[eidx(3,l,b,lane)]
           + g_embs[eidx(0,l,b,lane+32)]*g_embs[eidx(3,l,b,lane+32)]
           + g_embs[eidx(2,l,b,lane)]   *g_embs[eidx(1,l,b,lane)]
           + g_embs[eidx(2,l,b,lane+32)]*g_embs[eidx(1,l,b,lane+32)];
    }
    s = wsum(s);
    if (lane == 0) out[b] = 1.f/(1.f + expf(-s));
}

// ---------------- launch ----------------
extern "C" void kernel_launch(void* const* d_in, const int* in_sizes, int n_in,
                              void* d_out, int out_size){
    (void)in_sizes; (void)n_in;
    const int*   items  = (const int*)  d_in[0];
    const int*   ucf_h  = (const int*)  d_in[1];
    const int*   ucf_r  = (const int*)  d_in[2];
    const int*   ucf_t  = (const int*)  d_in[3];
    const int*   ikg_h  = (const int*)  d_in[4];
    const int*   ikg_r  = (const int*)  d_in[5];
    const int*   ikg_t  = (const int*)  d_in[6];
    const int*   ukg_h  = (const int*)  d_in[7];
    const int*   ukg_r  = (const int*)  d_in[8];
    const int*   ukg_t  = (const int*)  d_in[9];
    const int*   icf_h  = (const int*)  d_in[10];
    const int*   icf_r  = (const int*)  d_in[11];
    const int*   icf_t  = (const int*)  d_in[12];
    const float* E      = (const float*)d_in[13];
    const float* R      = (const float*)d_in[14];
    const float* att_w1 = (const float*)d_in[15];
    const float* att_w2 = (const float*)d_in[16];
    const float* a2_w1  = (const float*)d_in[17];
    const float* a2_b1  = (const float*)d_in[18];
    const float* a2_w2  = (const float*)d_in[19];
    const float* a2_b2  = (const float*)d_in[20];
    const float* curv   = (const float*)d_in[21];
    float* out = (float*)d_out;

    const int ed_smem = ED_SMEM_FLOATS*4;
    const int hy_smem = HY_SMEM_FLOATS*4;
    const int ml_smem = ML_SMEM_FLOATS*4;
    cudaFuncSetAttribute(ed_kernel,    cudaFuncAttributeMaxDynamicSharedMemorySize, ed_smem);
    cudaFuncSetAttribute(hyper_kernel, cudaFuncAttributeMaxDynamicSharedMemorySize, hy_smem);
    cudaFuncSetAttribute(mlcl_gemm,    cudaFuncAttributeMaxDynamicSharedMemorySize, ml_smem);

    zero_kernel<<<(2*ROWS + 1023)/1024, 1024>>>();
    init_kernel<<<Bq, 256>>>(E, items, ucf_h, ukg_h, icf_h);

    dim3 gb(Bq, 2, 2);
    ed_kernel<<<gb, 256, ed_smem>>>(E, R, ucf_h, ucf_r, ucf_t, ikg_h, ikg_r, ikg_t, att_w1, att_w2);
    hyper_kernel<<<gb, 256, hy_smem>>>(E, R, ukg_h, ukg_r, ukg_t, icf_h, icf_r, icf_t,
                                       a2_w1, a2_b1, a2_w2, a2_b2, curv);

    normalize_kernel<<<(4*3*Bq)/8, 256>>>();
    dim3 gg(48, 48, 2);
    mlcl_gemm<<<gg, 256, ml_smem>>>();
    loss_kernel<<<2*ROWS/8, 256>>>();
    scores_kernel<<<Bq/8, 256>>>(out, out_size);
}

// round 8
// speedup vs baseline: 4.3317x; 1.6131x over previous
#include <cuda_runtime.h>
#include <math.h>

#define Bq 2048
#define Mq 64
#define Dq 64
#define BMq (Bq*Mq)
#define NPB (3*Bq*Dq)
#define ROWS 6144

// ---------------- device scratch ----------------
__device__ float g_embs[4*3*Bq*Dq];   // 4 builds x 3 layers x B x D
__device__ float g_norm[4*3*Bq*Dq];
__device__ float g_rowsum[2*ROWS];
__device__ float g_colsum[2*ROWS];
__device__ float g_loss;

__device__ __forceinline__ unsigned cvt_tf32(float x){
    unsigned r; asm("cvt.rna.tf32.f32 %0, %1;" : "=r"(r) : "f"(x)); return r;
}
__device__ __forceinline__ float cvt_tf32f(float x){ return __uint_as_float(cvt_tf32(x)); }

// m16n8k8 tf32 mma: D += A*B. a[4], b0,b1 tf32 bits; c[4] fp32.
__device__ __forceinline__ void mma_tf32(float* c, const unsigned* a, unsigned b0, unsigned b1){
    asm volatile(
        "mma.sync.aligned.m16n8k8.row.col.f32.tf32.tf32.f32 "
        "{%0,%1,%2,%3}, {%4,%5,%6,%7}, {%8,%9}, {%0,%1,%2,%3};"
        : "+f"(c[0]), "+f"(c[1]), "+f"(c[2]), "+f"(c[3])
        : "r"(a[0]), "r"(a[1]), "r"(a[2]), "r"(a[3]), "r"(b0), "r"(b1));
}

__device__ __forceinline__ float wsum(float v){
#pragma unroll
    for (int o = 16; o; o >>= 1) v += __shfl_xor_sync(0xffffffffu, v, o);
    return v;
}
__device__ __forceinline__ void wsum5(float &a, float &b, float &c, float &d, float &e){
#pragma unroll
    for (int o = 16; o; o >>= 1){
        a += __shfl_xor_sync(0xffffffffu, a, o);
        b += __shfl_xor_sync(0xffffffffu, b, o);
        c += __shfl_xor_sync(0xffffffffu, c, o);
        d += __shfl_xor_sync(0xffffffffu, d, o);
        e += __shfl_xor_sync(0xffffffffu, e, o);
    }
}
__device__ __forceinline__ float wmax(float v){
#pragma unroll
    for (int o = 16; o; o >>= 1) v = fmaxf(v, __shfl_xor_sync(0xffffffffu, v, o));
    return v;
}
__device__ __forceinline__ int eidx(int bl, int l, int b, int j){
    return (((bl*3 + l)*Bq) + b)*Dq + j;
}
__device__ __forceinline__ float ftanh(float x){
    float e = __expf(2.f*x);
    return 1.f - 2.f/(e + 1.f);
}
__device__ __forceinline__ float fartanh_clip(float x){
    x = fminf(fmaxf(x, -1.f + 1e-5f), 1.f - 1e-5f);
    return 0.5f*__logf((1.f + x)/(1.f - x));
}

// ---------------- zero accumulators ----------------
__global__ void zero_kernel(){
    int i = blockIdx.x*1024 + threadIdx.x;
    if (i < 2*ROWS){ g_rowsum[i] = 0.f; g_colsum[i] = 0.f; }
    if (i == 0) g_loss = 0.f;
}

// ---------------- init embeddings ----------------
__global__ __launch_bounds__(256) void init_kernel(
    const float* __restrict__ E, const int* __restrict__ items,
    const int* __restrict__ ucf_h, const int* __restrict__ ukg_h,
    const int* __restrict__ icf_h){
    __shared__ float pp[3][4][68];
    int b = blockIdx.x, tid = threadIdx.x;
    int j = tid & 63, q = tid >> 6;
    float s0 = 0.f, s2 = 0.f, s3 = 0.f;
#pragma unroll 4
    for (int mm = 0; mm < 16; ++mm){
        int m = q*16 + mm;
        s0 += E[ucf_h[b*Mq + m]*Dq + j];
        s2 += E[ukg_h[b*Mq + m]*Dq + j];
        s3 += E[icf_h[b*Mq + m]*Dq + j];
    }
    pp[0][q][j] = s0; pp[1][q][j] = s2; pp[2][q][j] = s3;
    __syncthreads();
    if (tid < 64){
        const float inv = 1.f/64.f;
        g_embs[eidx(1,0,b,tid)] = E[items[b]*Dq + tid];
        g_embs[eidx(0,0,b,tid)] = (pp[0][0][tid]+pp[0][1][tid]+pp[0][2][tid]+pp[0][3][tid])*inv;
        g_embs[eidx(2,0,b,tid)] = (pp[1][0][tid]+pp[1][1][tid]+pp[1][2][tid]+pp[1][3][tid])*inv;
        g_embs[eidx(3,0,b,tid)] = (pp[2][0][tid]+pp[2][1][tid]+pp[2][2][tid]+pp[2][3][tid])*inv;
    }
}

// ---------------- euclidean attention aggregation (tensor-core MLP) ----------------
// smem: xs [64 m][132 k] (tf32), ts [64][68], av 64, wv 64, pp 4*68  (~52.8KB -> 4 CTAs/SM)
#define ED_SMEM_FLOATS (64*132 + 64*68 + 64 + 64 + 4*68)
__global__ __launch_bounds__(256) void ed_kernel(
    const float* __restrict__ E, const float* __restrict__ R,
    const int* __restrict__ h0, const int* __restrict__ r0, const int* __restrict__ t0,
    const int* __restrict__ h1, const int* __restrict__ r1, const int* __restrict__ t1,
    const float* __restrict__ W1, const float* __restrict__ W2)
{
    extern __shared__ float sm[];
    float* xs = sm;                     // [64][132]  tf32 bits
    float* ts = xs + 64*132;            // [64][68]
    float* av = ts + 64*68;
    float* wv = av + 64;
    float* pp = wv + 64;                // [4][68]

    const int b = blockIdx.x, layer = blockIdx.y, buildz = blockIdx.z;
    const int* hI = buildz ? h1 : h0;
    const int* rI = buildz ? r1 : r0;
    const int* tI = buildz ? t1 : t0;
    const int build = buildz;
    const int tid = threadIdx.x, lane = tid & 31, wid = tid >> 5;
    const int gid = lane >> 2, tig = lane & 3;

    if (tid < 64) av[tid] = 0.f;

    // gather h|path (tf32-rounded) and t
    for (int e = tid; e < 1024; e += 256){
        int m = e & 63, k4 = e >> 6;
        float4 hv = *(const float4*)&E[hI[b*Mq + m]*Dq + k4*4];
        float4 pv = *(const float4*)&R[rI[b*Mq + m]*Dq + k4*4];
        if (layer){
            float4 h2 = *(const float4*)&E[hI[BMq + b*Mq + m]*Dq + k4*4];
            hv.x += h2.x; hv.y += h2.y; hv.z += h2.z; hv.w += h2.w;
            float4 p2 = *(const float4*)&R[rI[BMq + b*Mq + m]*Dq + k4*4];
            pv.x *= p2.x; pv.y *= p2.y; pv.z *= p2.z; pv.w *= p2.w;
        }
        float4 tv = *(const float4*)&E[tI[layer*BMq + b*Mq + m]*Dq + k4*4];
        float4 hc = make_float4(cvt_tf32f(hv.x), cvt_tf32f(hv.y), cvt_tf32f(hv.z), cvt_tf32f(hv.w));
        float4 pc = make_float4(cvt_tf32f(pv.x), cvt_tf32f(pv.y), cvt_tf32f(pv.z), cvt_tf32f(pv.w));
        *(float4*)&xs[m*132 + k4*4]      = hc;
        *(float4*)&xs[m*132 + 64 + k4*4] = pc;
        *(float4*)&ts[m*68 + k4*4] = tv;
    }
    __syncthreads();

    // z = relu(x @ W1) . W2 via m16n8k8 tf32 mma; 8 warps: 2(M) x 4(N)
    {
        const int m0 = (wid & 1)*32, n0 = (wid >> 1)*16;
        float acc[2][2][4] = {};
#pragma unroll
        for (int kk = 0; kk < 16; ++kk){
            unsigned a[2][4];
#pragma unroll
            for (int mi = 0; mi < 2; ++mi){
                int base = (m0 + mi*16 + gid)*132 + kk*8 + tig;
                a[mi][0] = __float_as_uint(xs[base]);
                a[mi][1] = __float_as_uint(xs[base + 8*132]);
                a[mi][2] = __float_as_uint(xs[base + 4]);
                a[mi][3] = __float_as_uint(xs[base + 8*132 + 4]);
            }
            int kb = kk*8 + tig;
#pragma unroll
            for (int ni = 0; ni < 2; ++ni){
                int c = n0 + ni*8 + gid;
                unsigned b0 = cvt_tf32(__ldg(&W1[kb*64 + c]));
                unsigned b1 = cvt_tf32(__ldg(&W1[(kb+4)*64 + c]));
                mma_tf32(acc[0][ni], a[0], b0, b1);
                mma_tf32(acc[1][ni], a[1], b0, b1);
            }
        }
        // fused relu + W2 dot; reduce over tig then atomic into av
#pragma unroll
        for (int mi = 0; mi < 2; ++mi){
            float slo = 0.f, shi = 0.f;
#pragma unroll
            for (int ni = 0; ni < 2; ++ni){
                int c = n0 + ni*8 + tig*2;
                float w2a = __ldg(&W2[c]), w2b = __ldg(&W2[c+1]);
                slo += fmaxf(acc[mi][ni][0],0.f)*w2a + fmaxf(acc[mi][ni][1],0.f)*w2b;
                shi += fmaxf(acc[mi][ni][2],0.f)*w2a + fmaxf(acc[mi][ni][3],0.f)*w2b;
            }
            slo += __shfl_xor_sync(0xffffffffu, slo, 1);
            slo += __shfl_xor_sync(0xffffffffu, slo, 2);
            shi += __shfl_xor_sync(0xffffffffu, shi, 1);
            shi += __shfl_xor_sync(0xffffffffu, shi, 2);
            if (tig == 0){
                atomicAdd(&av[m0 + mi*16 + gid],     slo);
                atomicAdd(&av[m0 + mi*16 + gid + 8], shi);
            }
        }
    }
    __syncthreads();

    if (wid == 0){
        float a0 = 1.f/(1.f + __expf(-av[lane]));
        float a1 = 1.f/(1.f + __expf(-av[lane+32]));
        float mx = wmax(fmaxf(a0, a1));
        float e0 = __expf(a0 - mx), e1 = __expf(a1 - mx);
        float s = wsum(e0 + e1);
        wv[lane] = e0/s; wv[lane+32] = e1/s;
    }
    __syncthreads();

    {
        int j = tid & 63, q = tid >> 6;
        float o = 0.f;
#pragma unroll 4
        for (int mm = 0; mm < 16; ++mm){
            int m = q*16 + mm;
            o += wv[m]*ts[m*68 + j];
        }
        pp[q*68 + j] = o;
    }
    __syncthreads();
    if (tid < 64)
        g_embs[eidx(build, layer+1, b, tid)] =
            pp[tid] + pp[68+tid] + pp[136+tid] + pp[204+tid];
}

// ---------------- hyperbolic attention aggregation (tensor-core MLP) ----------------
#define HY_SMEM_FLOATS (64*65 + 64*132 + 8*64 + 16 + 4*68)
__global__ __launch_bounds__(256) void hyper_kernel(
    const float* __restrict__ E, const float* __restrict__ R,
    const int* __restrict__ h0, const int* __restrict__ r0, const int* __restrict__ t0,
    const int* __restrict__ h1, const int* __restrict__ r1, const int* __restrict__ t1,
    const float* __restrict__ W1, const float* __restrict__ B1,
    const float* __restrict__ W2, const float* __restrict__ B2,
    const float* __restrict__ curv)
{
    extern __shared__ float sm[];
    float* hts  = sm;                   // [64][65]
    float* tang = hts + 64*65;          // [64][132]  (fp32)
    float* av   = tang + 64*132;        // [64]
    float* wv   = av + 64;
    float* mp   = wv + 64;
    float* ht2s = mp + 64;
    float* istg = ht2s + 64;
    float* wh   = istg + 64;
    float* alv  = wh + 64;
    float* bev  = alv + 64;
    float* scal = bev + 64;             // [16]
    float* pp   = scal + 16;            // [4][68]

    const int b = blockIdx.x, layer = blockIdx.y, buildz = blockIdx.z;
    const int* hI = buildz ? h1 : h0;
    const int* rI = buildz ? r1 : r0;
    const int* tI = buildz ? t1 : t0;
    const int build = 2 + buildz;
    const int tid = threadIdx.x, lane = tid & 31, wid = tid >> 5;
    const int gid = lane >> 2, tig = lane & 3;

    // kernel-wide constants (||l2(x)|| == 1)
    const float absc = fabsf(curv[0]);
    const float th1  = 0.761594155955765f;
    const float sh0  = th1*absc;
    const float hh2  = sh0*sh0;
    const float lam  = 2.f/fmaxf(1.f - hh2, 1e-15f);
    const float tyc  = ftanh(lam*0.5f);
    const float y2c  = tyc*tyc;
    const float c2c  = 1.f - hh2;

    if (tid < 64) av[tid] = 0.f;

    // ---- phase 1 ----
#pragma unroll 2
    for (int r = 0; r < 8; ++r){
        int m = wid*8 + r;
        int hA = hI[b*Mq + m];
        float hv0 = E[hA*Dq + lane], hv1 = E[hA*Dq + lane + 32];
        int rA = rI[b*Mq + m];
        float pv0 = R[rA*Dq + lane], pv1 = R[rA*Dq + lane + 32];
        if (layer){
            int hB = hI[BMq + b*Mq + m];
            hv0 += E[hB*Dq + lane]; hv1 += E[hB*Dq + lane + 32];
            int rB = rI[BMq + b*Mq + m];
            pv0 *= R[rB*Dq + lane]; pv1 *= R[rB*Dq + lane + 32];
        }
        int tA = tI[layer*BMq + b*Mq + m];
        float tv0 = E[tA*Dq + lane], tv1 = E[tA*Dq + lane + 32];

        float nh2 = hv0*hv0 + hv1*hv1;
        float np2 = pv0*pv0 + pv1*pv1;
        float nt2 = tv0*tv0 + tv1*tv1;
        float dht = hv0*tv0 + hv1*tv1;
        float dhp = hv0*pv0 + hv1*pv1;
        wsum5(nh2, np2, nt2, dht, dhp);

        float ih = 1.f/fmaxf(sqrtf(nh2), 1e-12f);
        float ip = 1.f/fmaxf(sqrtf(np2), 1e-12f);
        float it = 1.f/fmaxf(sqrtf(nt2), 1e-12f);

        float sh = sh0*ih;
        float sy = tyc*it;
        float sq = tyc*ip;

        float xy = sh*sy*dht;
        float xq = sh*sq*dhp;

        float c1 = 1.f + 2.f*xy + y2c;
        float den = fmaxf(1.f + 2.f*xy + hh2*y2c, 1e-15f);
        float invden = 1.f/den;
        float ht0 = (c1*sh*hv0 + c2c*sy*tv0)*invden;
        float ht1 = (c1*sh*hv1 + c2c*sy*tv1)*invden;
        float ht2 = (c1*c1*hh2 + 2.f*c1*c2c*xy + c2c*c2c*y2c)*invden*invden;

        float d1 = 1.f + 2.f*xq + y2c;
        float dd = fmaxf(1.f + 2.f*xq + hh2*y2c, 1e-15f);
        float invdd = 1.f/dd;
        float hr0 = (d1*sh*hv0 + c2c*sq*pv0)*invdd;
        float hr1 = (d1*sh*hv1 + c2c*sq*pv1)*invdd;
        float hr2 = (d1*d1*hh2 + 2.f*d1*c2c*xq + c2c*c2c*y2c)*invdd*invdd;

        float n128 = sqrtf(fmaxf(hh2 + hr2, 1e-15f));
        float stg = fartanh_clip(n128)/n128;

        hts[m*65 + lane] = ht0; hts[m*65 + lane + 32] = ht1;
        if (lane == 0){ ht2s[m] = ht2; istg[m] = 1.f/stg; }
        tang[m*132 + lane]      = stg*sh*hv0; tang[m*132 + lane + 32] = stg*sh*hv1;
        tang[m*132 + 64 + lane] = stg*hr0;    tang[m*132 + 96 + lane] = stg*hr1;
    }
    __syncthreads();

    // ---- phase 2: MLP via tf32 mma ----
    {
        const int m0 = (wid & 1)*32, n0 = (wid >> 1)*16;
        float acc[2][2][4] = {};
#pragma unroll
        for (int kk = 0; kk < 16; ++kk){
            unsigned a[2][4];
#pragma unroll
            for (int mi = 0; mi < 2; ++mi){
                int base = (m0 + mi*16 + gid)*132 + kk*8 + tig;
                a[mi][0] = cvt_tf32(tang[base]);
                a[mi][1] = cvt_tf32(tang[base + 8*132]);
                a[mi][2] = cvt_tf32(tang[base + 4]);
                a[mi][3] = cvt_tf32(tang[base + 8*132 + 4]);
            }
            int kb = kk*8 + tig;
#pragma unroll
            for (int ni = 0; ni < 2; ++ni){
                int c = n0 + ni*8 + gid;
                unsigned b0 = cvt_tf32(__ldg(&W1[kb*64 + c]));
                unsigned b1 = cvt_tf32(__ldg(&W1[(kb+4)*64 + c]));
                mma_tf32(acc[0][ni], a[0], b0, b1);
                mma_tf32(acc[1][ni], a[1], b0, b1);
            }
        }
#pragma unroll
        for (int mi = 0; mi < 2; ++mi){
            float slo = 0.f, shi = 0.f;
#pragma unroll
            for (int ni = 0; ni < 2; ++ni){
                int c = n0 + ni*8 + tig*2;
                float w2a = __ldg(&W2[c]), w2b = __ldg(&W2[c+1]);
                float b1a = __ldg(&B1[c]), b1b = __ldg(&B1[c+1]);
                slo += fmaxf(acc[mi][ni][0] + b1a, 0.f)*w2a + fmaxf(acc[mi][ni][1] + b1b, 0.f)*w2b;
                shi += fmaxf(acc[mi][ni][2] + b1a, 0.f)*w2a + fmaxf(acc[mi][ni][3] + b1b, 0.f)*w2b;
            }
            slo += __shfl_xor_sync(0xffffffffu, slo, 1);
            slo += __shfl_xor_sync(0xffffffffu, slo, 2);
            shi += __shfl_xor_sync(0xffffffffu, shi, 1);
            shi += __shfl_xor_sync(0xffffffffu, shi, 2);
            if (tig == 0){
                atomicAdd(&av[m0 + mi*16 + gid],     slo);
                atomicAdd(&av[m0 + mi*16 + gid + 8], shi);
            }
        }
    }
    __syncthreads();

    if (wid == 0){
        const float b2 = B2[0];
        float a0 = ftanh(av[lane] + b2);
        float a1 = ftanh(av[lane+32] + b2);
        float mx = wmax(fmaxf(a0, a1));
        float e0 = __expf(a0 - mx), e1 = __expf(a1 - mx);
        float s = wsum(e0 + e1);
        wv[lane] = e0/s; wv[lane+32] = e1/s;
    }
    __syncthreads();

    // ---- phase 3 ----
    if (tid < 64) wh[tid] = wv[tid]*istg[tid];
    __syncthreads();
    {
        int j = tid & 63, q = tid >> 6;
        float a = 0.f;
#pragma unroll 4
        for (int mm = 0; mm < 16; ++mm){
            int m = q*16 + mm;
            a += wh[m]*tang[m*132 + j];
        }
        pp[q*68 + j] = a;
    }
    __syncthreads();
    if (tid < 64) mp[tid] = pp[tid] + pp[68+tid] + pp[136+tid] + pp[204+tid];
    __syncthreads();
    if (wid == 0){
        float v = mp[lane]*mp[lane] + mp[lane+32]*mp[lane+32];
        v = wsum(v);
        if (lane == 0) scal[0] = v;
    }
    __syncthreads();
    {
        int m = tid & 63, q = tid >> 6;
        float a = 0.f;
#pragma unroll 4
        for (int jj = 0; jj < 16; ++jj){
            int j = q*16 + jj;
            a += hts[m*65 + j]*mp[j];
        }
        pp[q*68 + m] = a;
    }
    __syncthreads();
    if (tid < 64){
        float dsum = pp[tid] + pp[68+tid] + pp[136+tid] + pp[204+tid];
        float p2v = scal[0];
        float wm = wv[tid];
        float xy = -wm*dsum;
        float y2 = wm*wm*ht2s[tid];
        float c2v = 1.f - p2v;
        float c1v = 1.f + 2.f*xy + y2;
        float den = fmaxf(1.f + 2.f*xy + p2v*y2, 1e-15f);
        float invden = 1.f/den;
        float n2 = (c1v*c1v*p2v + 2.f*c1v*c2v*xy + c2v*c2v*y2)*invden*invden;
        float n = sqrtf(fmaxf(n2, 1e-15f));
        float lamp = 2.f/fmaxf(1.f - p2v, 1e-15f);
        float sc = (2.f/lamp)*fartanh_clip(n)/n;
        alv[tid] = wm*sc*c1v*invden;
        bev[tid] = wm*wm*sc*c2v*invden;
    }
    __syncthreads();
    if (wid == 0){
        float sa = alv[lane] + alv[lane+32];
        sa = wsum(sa);
        if (lane == 0) scal[1] = sa;
    }
    __syncthreads();
    {
        int j = tid & 63, q = tid >> 6;
        float o = 0.f;
#pragma unroll 4
        for (int mm = 0; mm < 16; ++mm){
            int m = q*16 + mm;
            o += bev[m]*hts[m*65 + j];
        }
        pp[q*68 + j] = o;
    }
    __syncthreads();
    if (tid < 64)
        g_embs[eidx(build, layer+1, b, tid)] =
            (pp[tid] + pp[68+tid] + pp[136+tid] + pp[204+tid]) - mp[tid]*scal[1];
}

// ---------------- l2-normalize all stacks ----------------
__global__ void normalize_kernel(){
    int row = blockIdx.x*8 + (threadIdx.x >> 5);
    int lane = threadIdx.x & 31;
    if (row >= 4*3*Bq) return;
    const float* s = g_embs + row*Dq;
    float* d = g_norm + row*Dq;
    float v0 = s[lane], v1 = s[lane+32];
    float n = sqrtf(wsum(v0*v0 + v1*v1));
    float inv = 1.f/fmaxf(n, 1e-12f);
    d[lane] = v0*inv; d[lane+32] = v1*inv;
}

// ---------------- MLCL GEMM via tf32 mma with fused exp row/col sums ----------------
#define ML_SMEM_FLOATS (128*68*2 + 256)
__global__ __launch_bounds__(256) void mlcl_gemm(){
    const int pair = blockIdx.z;
    const float* A  = g_norm + (pair == 0 ? 0 : 1)*NPB;
    const float* Bn = g_norm + (pair == 0 ? 2 : 3)*NPB;
    float* rs = g_rowsum + pair*ROWS;
    float* cs = g_colsum + pair*ROWS;

    extern __shared__ float sm[];
    float* As = sm;                 // [128][68] tf32 bits
    float* Bs = As + 128*68;        // [128][68] tf32 bits
    float* rowpart = Bs + 128*68;   // [128]
    float* colpart = rowpart + 128; // [128]

    const int tid = threadIdx.x;
    const int by = blockIdx.y, bx = blockIdx.x;
    const int lane = tid & 31, wid = tid >> 5;
    const int gid = lane >> 2, tig = lane & 3;

    for (int e = tid; e < 2048; e += 256){
        int i = e >> 4, k4 = e & 15;
        float4 v = *(const float4*)&A[(by*128 + i)*64 + k4*4];
        float4 c = make_float4(cvt_tf32f(v.x), cvt_tf32f(v.y), cvt_tf32f(v.z), cvt_tf32f(v.w));
        *(float4*)&As[i*68 + k4*4] = c;
        float4 w = *(const float4*)&Bn[(bx*128 + i)*64 + k4*4];
        float4 d = make_float4(cvt_tf32f(w.x), cvt_tf32f(w.y), cvt_tf32f(w.z), cvt_tf32f(w.w));
        *(float4*)&Bs[i*68 + k4*4] = d;
    }
    if (tid < 128){ rowpart[tid] = 0.f; colpart[tid] = 0.f; }
    __syncthreads();

    const int m0 = (wid & 3)*32, n0 = (wid >> 2)*64;
    float acc[2][8][4] = {};
#pragma unroll
    for (int kk = 0; kk < 8; ++kk){
        unsigned a[2][4];
#pragma unroll
        for (int mi = 0; mi < 2; ++mi){
            int base = (m0 + mi*16 + gid)*68 + kk*8 + tig;
            a[mi][0] = __float_as_uint(As[base]);
            a[mi][1] = __float_as_uint(As[base + 8*68]);
            a[mi][2] = __float_as_uint(As[base + 4]);
            a[mi][3] = __float_as_uint(As[base + 8*68 + 4]);
        }
#pragma unroll
        for (int ni = 0; ni < 8; ++ni){
            int bb = (n0 + ni*8 + gid)*68 + kk*8 + tig;
            unsigned b0 = __float_as_uint(Bs[bb]);
            unsigned b1 = __float_as_uint(Bs[bb + 4]);
            mma_tf32(acc[0][ni], a[0], b0, b1);
            mma_tf32(acc[1][ni], a[1], b0, b1);
        }
    }

    // fused exp(*5) row/col sums from D fragments
    float cl[8], ch[8];
#pragma unroll
    for (int ni = 0; ni < 8; ++ni){ cl[ni] = 0.f; ch[ni] = 0.f; }
#pragma unroll
    for (int mi = 0; mi < 2; ++mi){
        float rlo = 0.f, rhi = 0.f;
#pragma unroll
        for (int ni = 0; ni < 8; ++ni){
            float e0 = __expf(5.f*acc[mi][ni][0]);
            float e1 = __expf(5.f*acc[mi][ni][1]);
            float e2 = __expf(5.f*acc[mi][ni][2]);
            float e3 = __expf(5.f*acc[mi][ni][3]);
            rlo += e0 + e1; rhi += e2 + e3;
            cl[ni] += e0 + e2; ch[ni] += e1 + e3;
        }
        rlo += __shfl_xor_sync(0xffffffffu, rlo, 1);
        rlo += __shfl_xor_sync(0xffffffffu, rlo, 2);
        rhi += __shfl_xor_sync(0xffffffffu, rhi, 1);
        rhi += __shfl_xor_sync(0xffffffffu, rhi, 2);
        if (tig == 0){
            atomicAdd(&rowpart[m0 + mi*16 + gid],     rlo);
            atomicAdd(&rowpart[m0 + mi*16 + gid + 8], rhi);
        }
    }
#pragma unroll
    for (int ni = 0; ni < 8; ++ni){
        cl[ni] += __shfl_xor_sync(0xffffffffu, cl[ni], 4);
        cl[ni] += __shfl_xor_sync(0xffffffffu, cl[ni], 8);
        cl[ni] += __shfl_xor_sync(0xffffffffu, cl[ni], 16);
        ch[ni] += __shfl_xor_sync(0xffffffffu, ch[ni], 4);
        ch[ni] += __shfl_xor_sync(0xffffffffu, ch[ni], 8);
        ch[ni] += __shfl_xor_sync(0xffffffffu, ch[ni], 16);
        if (gid == 0){
            atomicAdd(&colpart[n0 + ni*8 + tig*2],     cl[ni]);
            atomicAdd(&colpart[n0 + ni*8 + tig*2 + 1], ch[ni]);
        }
    }
    __syncthreads();
    if (tid < 128){
        atomicAdd(&rs[by*128 + tid], rowpart[tid]);
        atomicAdd(&cs[bx*128 + tid], colpart[tid]);
    }
}

// ---------------- loss reduction ----------------
__global__ void loss_kernel(){
    const int wid = threadIdx.x >> 5, lane = threadIdx.x & 31;
    int r = blockIdx.x*8 + wid;
    int pair = r >= ROWS;
    int i = r - pair*ROWS;
    const float* A  = g_norm + (pair ? 1 : 0)*NPB;
    const float* Bn = g_norm + (pair ? 3 : 2)*NPB;
    float d = A[i*64 + lane]*Bn[i*64 + lane] + A[i*64 + lane + 32]*Bn[i*64 + lane + 32];
    d = wsum(d);
    __shared__ float red[8];
    if (lane == 0)
        red[wid] = logf(g_rowsum[pair*ROWS + i]) + logf(g_colsum[pair*ROWS + i]) - 10.f*d;
    __syncthreads();
    if (threadIdx.x == 0){
        float s = 0.f;
#pragma unroll
        for (int w = 0; w < 8; ++w) s += red[w];
        atomicAdd(&g_loss, s);
    }
}

// ---------------- scores + loss finalize ----------------
__global__ void scores_kernel(float* out, int out_size){
    int b = blockIdx.x*8 + (threadIdx.x >> 5);
    int lane = threadIdx.x & 31;
    if (blockIdx.x == 0 && threadIdx.x == 0 && out_size > Bq) out[Bq] = 1e-6f*g_loss;
    if (b >= Bq) return;
    float s = 0.f;
#pragma unroll
    for (int l = 0; l < 3; ++l){
        s += g_embs[eidx(0,l,b,lane)]   *g_embs[eidx(3,l,b,lane)]
           + g_embs[eidx(0,l,b,lane+32)]*g_embs[eidx(3,l,b,lane+32)]
           + g_embs[eidx(2,l,b,lane)]   *g_embs[eidx(1,l,b,lane)]
           + g_embs[eidx(2,l,b,lane+32)]*g_embs[eidx(1,l,b,lane+32)];
    }
    s = wsum(s);
    if (lane == 0) out[b] = 1.f/(1.f + expf(-s));
}

// ---------------- launch ----------------
extern "C" void kernel_launch(void* const* d_in, const int* in_sizes, int n_in,
                              void* d_out, int out_size){
    (void)in_sizes; (void)n_in;
    const int*   items  = (const int*)  d_in[0];
    const int*   ucf_h  = (const int*)  d_in[1];
    const int*   ucf_r  = (const int*)  d_in[2];
    const int*   ucf_t  = (const int*)  d_in[3];
    const int*   ikg_h  = (const int*)  d_in[4];
    const int*   ikg_r  = (const int*)  d_in[5];
    const int*   ikg_t  = (const int*)  d_in[6];
    const int*   ukg_h  = (const int*)  d_in[7];
    const int*   ukg_r  = (const int*)  d_in[8];
    const int*   ukg_t  = (const int*)  d_in[9];
    const int*   icf_h  = (const int*)  d_in[10];
    const int*   icf_r  = (const int*)  d_in[11];
    const int*   icf_t  = (const int*)  d_in[12];
    const float* E      = (const float*)d_in[13];
    const float* R      = (const float*)d_in[14];
    const float* att_w1 = (const float*)d_in[15];
    const float* att_w2 = (const float*)d_in[16];
    const float* a2_w1  = (const float*)d_in[17];
    const float* a2_b1  = (const float*)d_in[18];
    const float* a2_w2  = (const float*)d_in[19];
    const float* a2_b2  = (const float*)d_in[20];
    const float* curv   = (const float*)d_in[21];
    float* out = (float*)d_out;

    const int ed_smem = ED_SMEM_FLOATS*4;
    const int hy_smem = HY_SMEM_FLOATS*4;
    const int ml_smem = ML_SMEM_FLOATS*4;
    cudaFuncSetAttribute(ed_kernel,    cudaFuncAttributeMaxDynamicSharedMemorySize, ed_smem);
    cudaFuncSetAttribute(hyper_kernel, cudaFuncAttributeMaxDynamicSharedMemorySize, hy_smem);
    cudaFuncSetAttribute(mlcl_gemm,    cudaFuncAttributeMaxDynamicSharedMemorySize, ml_smem);

    zero_kernel<<<(2*ROWS + 1023)/1024, 1024>>>();
    init_kernel<<<Bq, 256>>>(E, items, ucf_h, ukg_h, icf_h);

    dim3 gb(Bq, 2, 2);
    ed_kernel<<<gb, 256, ed_smem>>>(E, R, ucf_h, ucf_r, ucf_t, ikg_h, ikg_r, ikg_t, att_w1, att_w2);
    hyper_kernel<<<gb, 256, hy_smem>>>(E, R, ukg_h, ukg_r, ukg_t, icf_h, icf_r, icf_t,
                                       a2_w1, a2_b1, a2_w2, a2_b2, curv);

    normalize_kernel<<<(4*3*Bq)/8, 256>>>();
    dim3 gg(48, 48, 2);
    mlcl_gemm<<<gg, 256, ml_smem>>>();
    loss_kernel<<<2*ROWS/8, 256>>>();
    scores_kernel<<<Bq/8, 256>>>(out, out_size);
}

// round 9
// speedup vs baseline: 4.4098x; 1.0180x over previous
#include <cuda_runtime.h>
#include <math.h>

#define Bq 2048
#define Mq 64
#define Dq 64
#define BMq (Bq*Mq)
#define NPB (3*Bq*Dq)
#define ROWS 6144

// ---------------- device scratch ----------------
__device__ float g_embs[4*3*Bq*Dq];   // 4 builds x 3 layers x B x D
__device__ float g_norm[4*3*Bq*Dq];
__device__ float g_rowsum[2*ROWS];
__device__ float g_colsum[2*ROWS];
__device__ float g_loss;

__device__ __forceinline__ unsigned cvt_tf32(float x){
    unsigned r; asm("cvt.rna.tf32.f32 %0, %1;" : "=r"(r) : "f"(x)); return r;
}
__device__ __forceinline__ float cvt_tf32f(float x){ return __uint_as_float(cvt_tf32(x)); }

__device__ __forceinline__ void mma_tf32(float* c, const unsigned* a, unsigned b0, unsigned b1){
    asm volatile(
        "mma.sync.aligned.m16n8k8.row.col.f32.tf32.tf32.f32 "
        "{%0,%1,%2,%3}, {%4,%5,%6,%7}, {%8,%9}, {%0,%1,%2,%3};"
        : "+f"(c[0]), "+f"(c[1]), "+f"(c[2]), "+f"(c[3])
        : "r"(a[0]), "r"(a[1]), "r"(a[2]), "r"(a[3]), "r"(b0), "r"(b1));
}

__device__ __forceinline__ float wsum(float v){
#pragma unroll
    for (int o = 16; o; o >>= 1) v += __shfl_xor_sync(0xffffffffu, v, o);
    return v;
}
__device__ __forceinline__ void wsum5(float &a, float &b, float &c, float &d, float &e){
#pragma unroll
    for (int o = 16; o; o >>= 1){
        a += __shfl_xor_sync(0xffffffffu, a, o);
        b += __shfl_xor_sync(0xffffffffu, b, o);
        c += __shfl_xor_sync(0xffffffffu, c, o);
        d += __shfl_xor_sync(0xffffffffu, d, o);
        e += __shfl_xor_sync(0xffffffffu, e, o);
    }
}
__device__ __forceinline__ float wmax(float v){
#pragma unroll
    for (int o = 16; o; o >>= 1) v = fmaxf(v, __shfl_xor_sync(0xffffffffu, v, o));
    return v;
}
__device__ __forceinline__ int eidx(int bl, int l, int b, int j){
    return (((bl*3 + l)*Bq) + b)*Dq + j;
}
__device__ __forceinline__ float ftanh(float x){
    float e = __expf(2.f*x);
    return 1.f - 2.f/(e + 1.f);
}
__device__ __forceinline__ float fartanh_clip(float x){
    x = fminf(fmaxf(x, -1.f + 1e-5f), 1.f - 1e-5f);
    return 0.5f*__logf((1.f + x)/(1.f - x));
}

// ---------------- zero accumulators ----------------
__global__ void zero_kernel(){
    int i = blockIdx.x*1024 + threadIdx.x;
    if (i < 2*ROWS){ g_rowsum[i] = 0.f; g_colsum[i] = 0.f; }
    if (i == 0) g_loss = 0.f;
}

// ---------------- init embeddings + fused normalize ----------------
__global__ __launch_bounds__(256) void init_kernel(
    const float* __restrict__ E, const int* __restrict__ items,
    const int* __restrict__ ucf_h, const int* __restrict__ ukg_h,
    const int* __restrict__ icf_h){
    __shared__ float pp[3][4][68];
    __shared__ float rows[4][68];
    __shared__ float inr[4];
    int b = blockIdx.x, tid = threadIdx.x;
    int j = tid & 63, q = tid >> 6;
    int lane = tid & 31, wid = tid >> 5;
    float s0 = 0.f, s2 = 0.f, s3 = 0.f;
#pragma unroll 4
    for (int mm = 0; mm < 16; ++mm){
        int m = q*16 + mm;
        s0 += E[ucf_h[b*Mq + m]*Dq + j];
        s2 += E[ukg_h[b*Mq + m]*Dq + j];
        s3 += E[icf_h[b*Mq + m]*Dq + j];
    }
    pp[0][q][j] = s0; pp[1][q][j] = s2; pp[2][q][j] = s3;
    __syncthreads();
    if (tid < 64){
        const float inv = 1.f/64.f;
        rows[0][tid] = (pp[0][0][tid]+pp[0][1][tid]+pp[0][2][tid]+pp[0][3][tid])*inv;
        rows[1][tid] = E[items[b]*Dq + tid];
        rows[2][tid] = (pp[1][0][tid]+pp[1][1][tid]+pp[1][2][tid]+pp[1][3][tid])*inv;
        rows[3][tid] = (pp[2][0][tid]+pp[2][1][tid]+pp[2][2][tid]+pp[2][3][tid])*inv;
    }
    __syncthreads();
    if (wid < 4){
        float v = rows[wid][lane]*rows[wid][lane] + rows[wid][lane+32]*rows[wid][lane+32];
        v = wsum(v);
        if (lane == 0) inr[wid] = 1.f/fmaxf(sqrtf(v), 1e-12f);
    }
    __syncthreads();
    if (tid < 64){
#pragma unroll
        for (int bl = 0; bl < 4; ++bl){
            float o = rows[bl][tid];
            g_embs[eidx(bl,0,b,tid)] = o;
            g_norm[eidx(bl,0,b,tid)] = o*inr[bl];
        }
    }
}

// ---------------- unified aggregation kernel (ed: z<2, hyper: z>=2) ----------------
#define AGG_SMEM_FLOATS (64*132 + 64*68 + 64 + 64 + 4*68 + 64*3 + 16)
// ed uses:    xs[64][132], ts[64][68], av, wv, pp
// hyper uses: tang[64][132], hts[64][65 -> fits in ts+extra], av, wv, mp, ht2s, istg, alv/bev in pp area, scal
// Layout below is explicit per-branch; both fit in AGG_SMEM_FLOATS.

__device__ __forceinline__ void ed_body(
    float* sm, int b, int layer, int build,
    const float* __restrict__ E, const float* __restrict__ R,
    const int* __restrict__ hI, const int* __restrict__ rI, const int* __restrict__ tI,
    const float* __restrict__ W1, const float* __restrict__ W2)
{
    float* xs = sm;                     // [64][132] tf32
    float* ts = xs + 64*132;            // [64][68]
    float* av = ts + 64*68;             // [64]
    float* wv = av + 64;                // [64]
    float* pp = wv + 64;                // [4][68]

    const int tid = threadIdx.x, lane = tid & 31, wid = tid >> 5;
    const int gid = lane >> 2, tig = lane & 3;

    if (tid < 64) av[tid] = 0.f;

    for (int e = tid; e < 1024; e += 256){
        int m = e & 63, k4 = e >> 6;
        float4 hv = *(const float4*)&E[hI[b*Mq + m]*Dq + k4*4];
        float4 pv = *(const float4*)&R[rI[b*Mq + m]*Dq + k4*4];
        if (layer){
            float4 h2 = *(const float4*)&E[hI[BMq + b*Mq + m]*Dq + k4*4];
            hv.x += h2.x; hv.y += h2.y; hv.z += h2.z; hv.w += h2.w;
            float4 p2 = *(const float4*)&R[rI[BMq + b*Mq + m]*Dq + k4*4];
            pv.x *= p2.x; pv.y *= p2.y; pv.z *= p2.z; pv.w *= p2.w;
        }
        float4 tv = *(const float4*)&E[tI[layer*BMq + b*Mq + m]*Dq + k4*4];
        float4 hc = make_float4(cvt_tf32f(hv.x), cvt_tf32f(hv.y), cvt_tf32f(hv.z), cvt_tf32f(hv.w));
        float4 pc = make_float4(cvt_tf32f(pv.x), cvt_tf32f(pv.y), cvt_tf32f(pv.z), cvt_tf32f(pv.w));
        *(float4*)&xs[m*132 + k4*4]      = hc;
        *(float4*)&xs[m*132 + 64 + k4*4] = pc;
        *(float4*)&ts[m*68 + k4*4] = tv;
    }
    __syncthreads();

    {
        const int m0 = (wid & 1)*32, n0 = (wid >> 1)*16;
        float acc[2][2][4] = {};
#pragma unroll
        for (int kk = 0; kk < 16; ++kk){
            unsigned a[2][4];
#pragma unroll
            for (int mi = 0; mi < 2; ++mi){
                int base = (m0 + mi*16 + gid)*132 + kk*8 + tig;
                a[mi][0] = __float_as_uint(xs[base]);
                a[mi][1] = __float_as_uint(xs[base + 8*132]);
                a[mi][2] = __float_as_uint(xs[base + 4]);
                a[mi][3] = __float_as_uint(xs[base + 8*132 + 4]);
            }
            int kb = kk*8 + tig;
#pragma unroll
            for (int ni = 0; ni < 2; ++ni){
                int c = n0 + ni*8 + gid;
                unsigned b0 = cvt_tf32(__ldg(&W1[kb*64 + c]));
                unsigned b1 = cvt_tf32(__ldg(&W1[(kb+4)*64 + c]));
                mma_tf32(acc[0][ni], a[0], b0, b1);
                mma_tf32(acc[1][ni], a[1], b0, b1);
            }
        }
#pragma unroll
        for (int mi = 0; mi < 2; ++mi){
            float slo = 0.f, shi = 0.f;
#pragma unroll
            for (int ni = 0; ni < 2; ++ni){
                int c = n0 + ni*8 + tig*2;
                float w2a = __ldg(&W2[c]), w2b = __ldg(&W2[c+1]);
                slo += fmaxf(acc[mi][ni][0],0.f)*w2a + fmaxf(acc[mi][ni][1],0.f)*w2b;
                shi += fmaxf(acc[mi][ni][2],0.f)*w2a + fmaxf(acc[mi][ni][3],0.f)*w2b;
            }
            slo += __shfl_xor_sync(0xffffffffu, slo, 1);
            slo += __shfl_xor_sync(0xffffffffu, slo, 2);
            shi += __shfl_xor_sync(0xffffffffu, shi, 1);
            shi += __shfl_xor_sync(0xffffffffu, shi, 2);
            if (tig == 0){
                atomicAdd(&av[m0 + mi*16 + gid],     slo);
                atomicAdd(&av[m0 + mi*16 + gid + 8], shi);
            }
        }
    }
    __syncthreads();

    if (wid == 0){
        float a0 = 1.f/(1.f + __expf(-av[lane]));
        float a1 = 1.f/(1.f + __expf(-av[lane+32]));
        float mx = wmax(fmaxf(a0, a1));
        float e0 = __expf(a0 - mx), e1 = __expf(a1 - mx);
        float s = wsum(e0 + e1);
        wv[lane] = e0/s; wv[lane+32] = e1/s;
    }
    __syncthreads();

    {
        int j = tid & 63, q = tid >> 6;
        float o = 0.f;
#pragma unroll 4
        for (int mm = 0; mm < 16; ++mm){
            int m = q*16 + mm;
            o += wv[m]*ts[m*68 + j];
        }
        pp[q*68 + j] = o;
    }
    __syncthreads();
    if (tid < 64) av[tid] = pp[tid] + pp[68+tid] + pp[136+tid] + pp[204+tid];
    __syncthreads();
    if (wid == 0){
        float v = av[lane]*av[lane] + av[lane+32]*av[lane+32];
        v = wsum(v);
        if (lane == 0) wv[0] = 1.f/fmaxf(sqrtf(v), 1e-12f);
    }
    __syncthreads();
    if (tid < 64){
        float o = av[tid];
        g_embs[eidx(build, layer+1, b, tid)] = o;
        g_norm[eidx(build, layer+1, b, tid)] = o*wv[0];
    }
}

__device__ __forceinline__ void hyper_body(
    float* sm, int b, int layer, int build,
    const float* __restrict__ E, const float* __restrict__ R,
    const int* __restrict__ hI, const int* __restrict__ rI, const int* __restrict__ tI,
    const float* __restrict__ W1, const float* __restrict__ B1,
    const float* __restrict__ W2, const float* __restrict__ B2,
    const float* __restrict__ curv)
{
    float* tang = sm;                   // [64][132]
    float* hts  = tang + 64*132;        // [64][65]  (inside the ts[64][68] region)
    float* av   = hts + 64*68;          // [64]
    float* wv   = av + 64;              // [64]
    float* pp   = wv + 64;              // [4][68]
    float* mp   = pp + 4*68;            // [64]
    float* ht2s = mp + 64;              // [64]
    float* istg = ht2s + 64;            // [64]
    float* scal = istg + 64;            // [16]
    // alv/bev reuse pp after final matvec ordering (kept distinct via phases)

    const int tid = threadIdx.x, lane = tid & 31, wid = tid >> 5;
    const int gid = lane >> 2, tig = lane & 3;

    const float absc = fabsf(curv[0]);
    const float th1  = 0.761594155955765f;
    const float sh0  = th1*absc;
    const float hh2  = sh0*sh0;
    const float lam  = 2.f/fmaxf(1.f - hh2, 1e-15f);
    const float tyc  = ftanh(lam*0.5f);
    const float y2c  = tyc*tyc;
    const float c2c  = 1.f - hh2;

    if (tid < 64) av[tid] = 0.f;

    const float2* E2 = (const float2*)E;
    const float2* R2 = (const float2*)R;

    // ---- phase 1: packed float2 loads, one 5-wide reduction per row ----
#pragma unroll 2
    for (int r = 0; r < 8; ++r){
        int m = wid*8 + r;
        float2 h2v = E2[hI[b*Mq + m]*32 + lane];
        float2 p2v = R2[rI[b*Mq + m]*32 + lane];
        if (layer){
            float2 hB = E2[hI[BMq + b*Mq + m]*32 + lane];
            h2v.x += hB.x; h2v.y += hB.y;
            float2 pB = R2[rI[BMq + b*Mq + m]*32 + lane];
            p2v.x *= pB.x; p2v.y *= pB.y;
        }
        float2 t2v = E2[tI[layer*BMq + b*Mq + m]*32 + lane];
        float hv0 = h2v.x, hv1 = h2v.y;
        float pv0 = p2v.x, pv1 = p2v.y;
        float tv0 = t2v.x, tv1 = t2v.y;

        float nh2 = hv0*hv0 + hv1*hv1;
        float np2 = pv0*pv0 + pv1*pv1;
        float nt2 = tv0*tv0 + tv1*tv1;
        float dht = hv0*tv0 + hv1*tv1;
        float dhp = hv0*pv0 + hv1*pv1;
        wsum5(nh2, np2, nt2, dht, dhp);

        float ih = 1.f/fmaxf(sqrtf(nh2), 1e-12f);
        float ip = 1.f/fmaxf(sqrtf(np2), 1e-12f);
        float it = 1.f/fmaxf(sqrtf(nt2), 1e-12f);

        float sh = sh0*ih;
        float sy = tyc*it;
        float sq = tyc*ip;

        float xy = sh*sy*dht;
        float xq = sh*sq*dhp;

        float c1 = 1.f + 2.f*xy + y2c;
        float den = fmaxf(1.f + 2.f*xy + hh2*y2c, 1e-15f);
        float invden = 1.f/den;
        float ht0 = (c1*sh*hv0 + c2c*sy*tv0)*invden;
        float ht1 = (c1*sh*hv1 + c2c*sy*tv1)*invden;
        float ht2 = (c1*c1*hh2 + 2.f*c1*c2c*xy + c2c*c2c*y2c)*invden*invden;

        float d1 = 1.f + 2.f*xq + y2c;
        float dd = fmaxf(1.f + 2.f*xq + hh2*y2c, 1e-15f);
        float invdd = 1.f/dd;
        float hr0 = (d1*sh*hv0 + c2c*sq*pv0)*invdd;
        float hr1 = (d1*sh*hv1 + c2c*sq*pv1)*invdd;
        float hr2 = (d1*d1*hh2 + 2.f*d1*c2c*xq + c2c*c2c*y2c)*invdd*invdd;

        float n128 = sqrtf(fmaxf(hh2 + hr2, 1e-15f));
        float stg = fartanh_clip(n128)/n128;

        hts[m*65 + 2*lane] = ht0; hts[m*65 + 2*lane + 1] = ht1;
        if (lane == 0){ ht2s[m] = ht2; istg[m] = 1.f/stg; }
        *(float2*)&tang[m*132 + 2*lane]      = make_float2(stg*sh*hv0, stg*sh*hv1);
        *(float2*)&tang[m*132 + 64 + 2*lane] = make_float2(stg*hr0,    stg*hr1);
    }
    __syncthreads();

    // ---- phase 2: MLP via tf32 mma ----
    {
        const int m0 = (wid & 1)*32, n0 = (wid >> 1)*16;
        float acc[2][2][4] = {};
#pragma unroll
        for (int kk = 0; kk < 16; ++kk){
            unsigned a[2][4];
#pragma unroll
            for (int mi = 0; mi < 2; ++mi){
                int base = (m0 + mi*16 + gid)*132 + kk*8 + tig;
                a[mi][0] = cvt_tf32(tang[base]);
                a[mi][1] = cvt_tf32(tang[base + 8*132]);
                a[mi][2] = cvt_tf32(tang[base + 4]);
                a[mi][3] = cvt_tf32(tang[base + 8*132 + 4]);
            }
            int kb = kk*8 + tig;
#pragma unroll
            for (int ni = 0; ni < 2; ++ni){
                int c = n0 + ni*8 + gid;
                unsigned b0 = cvt_tf32(__ldg(&W1[kb*64 + c]));
                unsigned b1 = cvt_tf32(__ldg(&W1[(kb+4)*64 + c]));
                mma_tf32(acc[0][ni], a[0], b0, b1);
                mma_tf32(acc[1][ni], a[1], b0, b1);
            }
        }
#pragma unroll
        for (int mi = 0; mi < 2; ++mi){
            float slo = 0.f, shi = 0.f;
#pragma unroll
            for (int ni = 0; ni < 2; ++ni){
                int c = n0 + ni*8 + tig*2;
                float w2a = __ldg(&W2[c]), w2b = __ldg(&W2[c+1]);
                float b1a = __ldg(&B1[c]), b1b = __ldg(&B1[c+1]);
                slo += fmaxf(acc[mi][ni][0] + b1a, 0.f)*w2a + fmaxf(acc[mi][ni][1] + b1b, 0.f)*w2b;
                shi += fmaxf(acc[mi][ni][2] + b1a, 0.f)*w2a + fmaxf(acc[mi][ni][3] + b1b, 0.f)*w2b;
            }
            slo += __shfl_xor_sync(0xffffffffu, slo, 1);
            slo += __shfl_xor_sync(0xffffffffu, slo, 2);
            shi += __shfl_xor_sync(0xffffffffu, shi, 1);
            shi += __shfl_xor_sync(0xffffffffu, shi, 2);
            if (tig == 0){
                atomicAdd(&av[m0 + mi*16 + gid],     slo);
                atomicAdd(&av[m0 + mi*16 + gid + 8], shi);
            }
        }
    }
    __syncthreads();

    if (wid == 0){
        const float b2 = B2[0];
        float a0 = ftanh(av[lane] + b2);
        float a1 = ftanh(av[lane+32] + b2);
        float mx = wmax(fmaxf(a0, a1));
        float e0 = __expf(a0 - mx), e1 = __expf(a1 - mx);
        float s = wsum(e0 + e1);
        wv[lane] = e0/s; wv[lane+32] = e1/s;
    }
    __syncthreads();

    // ---- phase 3 ----
    if (tid < 64) av[tid] = wv[tid]*istg[tid];   // wh in av
    __syncthreads();
    {
        int j = tid & 63, q = tid >> 6;
        float a = 0.f;
#pragma unroll 4
        for (int mm = 0; mm < 16; ++mm){
            int m = q*16 + mm;
            a += av[m]*tang[m*132 + j];
        }
        pp[q*68 + j] = a;
    }
    __syncthreads();
    if (tid < 64) mp[tid] = pp[tid] + pp[68+tid] + pp[136+tid] + pp[204+tid];
    __syncthreads();
    if (wid == 0){
        float v = mp[lane]*mp[lane] + mp[lane+32]*mp[lane+32];
        v = wsum(v);
        if (lane == 0) scal[0] = v;
    }
    __syncthreads();
    {
        int m = tid & 63, q = tid >> 6;
        float a = 0.f;
#pragma unroll 4
        for (int jj = 0; jj < 16; ++jj){
            int j = q*16 + jj;
            a += hts[m*65 + j]*mp[j];
        }
        pp[q*68 + m] = a;
    }
    __syncthreads();
    if (tid < 64){
        float dsum = pp[tid] + pp[68+tid] + pp[136+tid] + pp[204+tid];
        float p2v = scal[0];
        float wm = wv[tid];
        float xy = -wm*dsum;
        float y2 = wm*wm*ht2s[tid];
        float c2v = 1.f - p2v;
        float c1v = 1.f + 2.f*xy + y2;
        float den = fmaxf(1.f + 2.f*xy + p2v*y2, 1e-15f);
        float invden = 1.f/den;
        float n2 = (c1v*c1v*p2v + 2.f*c1v*c2v*xy + c2v*c2v*y2)*invden*invden;
        float n = sqrtf(fmaxf(n2, 1e-15f));
        float lamp = 2.f/fmaxf(1.f - p2v, 1e-15f);
        float sc = (2.f/lamp)*fartanh_clip(n)/n;
        av[tid]   = wm*sc*c1v*invden;   // alv
        istg[tid] = wm*wm*sc*c2v*invden; // bev (reuse istg)
    }
    __syncthreads();
    if (wid == 0){
        float sa = av[lane] + av[lane+32];
        sa = wsum(sa);
        if (lane == 0) scal[1] = sa;
    }
    __syncthreads();
    {
        int j = tid & 63, q = tid >> 6;
        float o = 0.f;
#pragma unroll 4
        for (int mm = 0; mm < 16; ++mm){
            int m = q*16 + mm;
            o += istg[m]*hts[m*65 + j];
        }
        pp[q*68 + j] = o;
    }
    __syncthreads();
    if (tid < 64)
        ht2s[tid] = (pp[tid] + pp[68+tid] + pp[136+tid] + pp[204+tid]) - mp[tid]*scal[1];
    __syncthreads();
    if (wid == 0){
        float v = ht2s[lane]*ht2s[lane] + ht2s[lane+32]*ht2s[lane+32];
        v = wsum(v);
        if (lane == 0) scal[2] = 1.f/fmaxf(sqrtf(v), 1e-12f);
    }
    __syncthreads();
    if (tid < 64){
        float o = ht2s[tid];
        g_embs[eidx(build, layer+1, b, tid)] = o;
        g_norm[eidx(build, layer+1, b, tid)] = o*scal[2];
    }
}

__global__ __launch_bounds__(256) void agg_kernel(
    const float* __restrict__ E, const float* __restrict__ R,
    const int* __restrict__ ucf_h, const int* __restrict__ ucf_r, const int* __restrict__ ucf_t,
    const int* __restrict__ ikg_h, const int* __restrict__ ikg_r, const int* __restrict__ ikg_t,
    const int* __restrict__ ukg_h, const int* __restrict__ ukg_r, const int* __restrict__ ukg_t,
    const int* __restrict__ icf_h, const int* __restrict__ icf_r, const int* __restrict__ icf_t,
    const float* __restrict__ att_w1, const float* __restrict__ att_w2,
    const float* __restrict__ a2_w1, const float* __restrict__ a2_b1,
    const float* __restrict__ a2_w2, const float* __restrict__ a2_b2,
    const float* __restrict__ curv)
{
    extern __shared__ float sm[];
    const int b = blockIdx.x, layer = blockIdx.y, z = blockIdx.z;
    if (z == 0)      ed_body(sm, b, layer, 0, E, R, ucf_h, ucf_r, ucf_t, att_w1, att_w2);
    else if (z == 1) ed_body(sm, b, layer, 1, E, R, ikg_h, ikg_r, ikg_t, att_w1, att_w2);
    else if (z == 2) hyper_body(sm, b, layer, 2, E, R, ukg_h, ukg_r, ukg_t, a2_w1, a2_b1, a2_w2, a2_b2, curv);
    else             hyper_body(sm, b, layer, 3, E, R, icf_h, icf_r, icf_t, a2_w1, a2_b1, a2_w2, a2_b2, curv);
}

// ---------------- MLCL GEMM via tf32 mma with fused exp row/col sums ----------------
#define ML_SMEM_FLOATS (128*68*2 + 256)
__global__ __launch_bounds__(256) void mlcl_gemm(){
    const int pair = blockIdx.z;
    const float* A  = g_norm + (pair == 0 ? 0 : 1)*NPB;
    const float* Bn = g_norm + (pair == 0 ? 2 : 3)*NPB;
    float* rs = g_rowsum + pair*ROWS;
    float* cs = g_colsum + pair*ROWS;

    extern __shared__ float sm[];
    float* As = sm;
    float* Bs = As + 128*68;
    float* rowpart = Bs + 128*68;
    float* colpart = rowpart + 128;

    const int tid = threadIdx.x;
    const int by = blockIdx.y, bx = blockIdx.x;
    const int lane = tid & 31, wid = tid >> 5;
    const int gid = lane >> 2, tig = lane & 3;

    for (int e = tid; e < 2048; e += 256){
        int i = e >> 4, k4 = e & 15;
        float4 v = *(const float4*)&A[(by*128 + i)*64 + k4*4];
        *(float4*)&As[i*68 + k4*4] =
            make_float4(cvt_tf32f(v.x), cvt_tf32f(v.y), cvt_tf32f(v.z), cvt_tf32f(v.w));
        float4 w = *(const float4*)&Bn[(bx*128 + i)*64 + k4*4];
        *(float4*)&Bs[i*68 + k4*4] =
            make_float4(cvt_tf32f(w.x), cvt_tf32f(w.y), cvt_tf32f(w.z), cvt_tf32f(w.w));
    }
    if (tid < 128){ rowpart[tid] = 0.f; colpart[tid] = 0.f; }
    __syncthreads();

    const int m0 = (wid & 3)*32, n0 = (wid >> 2)*64;
    float acc[2][8][4] = {};
#pragma unroll
    for (int kk = 0; kk < 8; ++kk){
        unsigned a[2][4];
#pragma unroll
        for (int mi = 0; mi < 2; ++mi){
            int base = (m0 + mi*16 + gid)*68 + kk*8 + tig;
            a[mi][0] = __float_as_uint(As[base]);
            a[mi][1] = __float_as_uint(As[base + 8*68]);
            a[mi][2] = __float_as_uint(As[base + 4]);
            a[mi][3] = __float_as_uint(As[base + 8*68 + 4]);
        }
#pragma unroll
        for (int ni = 0; ni < 8; ++ni){
            int bb = (n0 + ni*8 + gid)*68 + kk*8 + tig;
            unsigned b0 = __float_as_uint(Bs[bb]);
            unsigned b1 = __float_as_uint(Bs[bb + 4]);
            mma_tf32(acc[0][ni], a[0], b0, b1);
            mma_tf32(acc[1][ni], a[1], b0, b1);
        }
    }

    float cl[8], ch[8];
#pragma unroll
    for (int ni = 0; ni < 8; ++ni){ cl[ni] = 0.f; ch[ni] = 0.f; }
#pragma unroll
    for (int mi = 0; mi < 2; ++mi){
        float rlo = 0.f, rhi = 0.f;
#pragma unroll
        for (int ni = 0; ni < 8; ++ni){
            float e0 = __expf(5.f*acc[mi][ni][0]);
            float e1 = __expf(5.f*acc[mi][ni][1]);
            float e2 = __expf(5.f*acc[mi][ni][2]);
            float e3 = __expf(5.f*acc[mi][ni][3]);
            rlo += e0 + e1; rhi += e2 + e3;
            cl[ni] += e0 + e2; ch[ni] += e1 + e3;
        }
        rlo += __shfl_xor_sync(0xffffffffu, rlo, 1);
        rlo += __shfl_xor_sync(0xffffffffu, rlo, 2);
        rhi += __shfl_xor_sync(0xffffffffu, rhi, 1);
        rhi += __shfl_xor_sync(0xffffffffu, rhi, 2);
        if (tig == 0){
            atomicAdd(&rowpart[m0 + mi*16 + gid],     rlo);
            atomicAdd(&rowpart[m0 + mi*16 + gid + 8], rhi);
        }
    }
#pragma unroll
    for (int ni = 0; ni < 8; ++ni){
        cl[ni] += __shfl_xor_sync(0xffffffffu, cl[ni], 4);
        cl[ni] += __shfl_xor_sync(0xffffffffu, cl[ni], 8);
        cl[ni] += __shfl_xor_sync(0xffffffffu, cl[ni], 16);
        ch[ni] += __shfl_xor_sync(0xffffffffu, ch[ni], 4);
        ch[ni] += __shfl_xor_sync(0xffffffffu, ch[ni], 8);
        ch[ni] += __shfl_xor_sync(0xffffffffu, ch[ni], 16);
        if (gid == 0){
            atomicAdd(&colpart[n0 + ni*8 + tig*2],     cl[ni]);
            atomicAdd(&colpart[n0 + ni*8 + tig*2 + 1], ch[ni]);
        }
    }
    __syncthreads();
    if (tid < 128){
        atomicAdd(&rs[by*128 + tid], rowpart[tid]);
        atomicAdd(&cs[bx*128 + tid], colpart[tid]);
    }
}

// ---------------- loss reduction ----------------
__global__ void loss_kernel(){
    const int wid = threadIdx.x >> 5, lane = threadIdx.x & 31;
    int r = blockIdx.x*8 + wid;
    int pair = r >= ROWS;
    int i = r - pair*ROWS;
    const float* A  = g_norm + (pair ? 1 : 0)*NPB;
    const float* Bn = g_norm + (pair ? 3 : 2)*NPB;
    float d = A[i*64 + lane]*Bn[i*64 + lane] + A[i*64 + lane + 32]*Bn[i*64 + lane + 32];
    d = wsum(d);
    __shared__ float red[8];
    if (lane == 0)
        red[wid] = logf(g_rowsum[pair*ROWS + i]) + logf(g_colsum[pair*ROWS + i]) - 10.f*d;
    __syncthreads();
    if (threadIdx.x == 0){
        float s = 0.f;
#pragma unroll
        for (int w = 0; w < 8; ++w) s += red[w];
        atomicAdd(&g_loss, s);
    }
}

// ---------------- scores + loss finalize ----------------
__global__ void scores_kernel(float* out, int out_size){
    int b = blockIdx.x*8 + (threadIdx.x >> 5);
    int lane = threadIdx.x & 31;
    if (blockIdx.x == 0 && threadIdx.x == 0 && out_size > Bq) out[Bq] = 1e-6f*g_loss;
    if (b >= Bq) return;
    float s = 0.f;
#pragma unroll
    for (int l = 0; l < 3; ++l){
        s += g_embs[eidx(0,l,b,lane)]   *g_embs[eidx(3,l,b,lane)]
           + g_embs[eidx(0,l,b,lane+32)]*g_embs[eidx(3,l,b,lane+32)]
           + g_embs[eidx(2,l,b,lane)]   *g_embs[eidx(1,l,b,lane)]
           + g_embs[eidx(2,l,b,lane+32)]*g_embs[eidx(1,l,b,lane+32)];
    }
    s = wsum(s);
    if (lane == 0) out[b] = 1.f/(1.f + expf(-s));
}

// ---------------- launch ----------------
extern "C" void kernel_launch(void* const* d_in, const int* in_sizes, int n_in,
                              void* d_out, int out_size){
    (void)in_sizes; (void)n_in;
    const int*   items  = (const int*)  d_in[0];
    const int*   ucf_h  = (const int*)  d_in[1];
    const int*   ucf_r  = (const int*)  d_in[2];
    const int*   ucf_t  = (const int*)  d_in[3];
    const int*   ikg_h  = (const int*)  d_in[4];
    const int*   ikg_r  = (const int*)  d_in[5];
    const int*   ikg_t  = (const int*)  d_in[6];
    const int*   ukg_h  = (const int*)  d_in[7];
    const int*   ukg_r  = (const int*)  d_in[8];
    const int*   ukg_t  = (const int*)  d_in[9];
    const int*   icf_h  = (const int*)  d_in[10];
    const int*   icf_r  = (const int*)  d_in[11];
    const int*   icf_t  = (const int*)  d_in[12];
    const float* E      = (const float*)d_in[13];
    const float* R      = (const float*)d_in[14];
    const float* att_w1 = (const float*)d_in[15];
    const float* att_w2 = (const float*)d_in[16];
    const float* a2_w1  = (const float*)d_in[17];
    const float* a2_b1  = (const float*)d_in[18];
    const float* a2_w2  = (const float*)d_in[19];
    const float* a2_b2  = (const float*)d_in[20];
    const float* curv   = (const float*)d_in[21];
    float* out = (float*)d_out;

    const int ag_smem = AGG_SMEM_FLOATS*4;
    const int ml_smem = ML_SMEM_FLOATS*4;
    cudaFuncSetAttribute(agg_kernel, cudaFuncAttributeMaxDynamicSharedMemorySize, ag_smem);
    cudaFuncSetAttribute(mlcl_gemm,  cudaFuncAttributeMaxDynamicSharedMemorySize, ml_smem);

    zero_kernel<<<(2*ROWS + 1023)/1024, 1024>>>();
    init_kernel<<<Bq, 256>>>(E, items, ucf_h, ukg_h, icf_h);

    dim3 gb(Bq, 2, 4);
    agg_kernel<<<gb, 256, ag_smem>>>(E, R,
        ucf_h, ucf_r, ucf_t, ikg_h, ikg_r, ikg_t,
        ukg_h, ukg_r, ukg_t, icf_h, icf_r, icf_t,
        att_w1, att_w2, a2_w1, a2_b1, a2_w2, a2_b2, curv);

    dim3 gg(48, 48, 2);
    mlcl_gemm<<<gg, 256, ml_smem>>>();
    loss_kernel<<<2*ROWS/8, 256>>>();
    scores_kernel<<<Bq/8, 256>>>(out, out_size);
}